// round 1
// baseline (speedup 1.0000x reference)
#include <cuda_runtime.h>
#include <math.h>

// Problem constants
#define NN 100000
#define EE 1250000
#define DD 64
#define HH 256
#define CC 40
#define KPROP 4
#define ALPHA 0.05f
#define BNEPS 1e-5f

#define NB_SCAN 98   // ceil(100000/1024)

// ---------------- device scratch (no allocations allowed) ----------------
__device__ float g_hA[NN * DD];
__device__ float g_hB[NN * DD];
__device__ float g_acc[NN * DD];
__device__ float g_norm[NN];
__device__ int   g_deg[NN];
__device__ int   g_off[NN + 1];
__device__ int   g_cursor[NN];
__device__ int   g_csr[EE];
__device__ int   g_bsum[NB_SCAN];
__device__ float g_y1[NN * HH];
__device__ float g_y2[NN * HH];
__device__ float g_stats[4 * HH];   // [sum1|sq1|sum2|sq2]
__device__ float g_bnA1[HH], g_bnC1[HH], g_bnA2[HH], g_bnC2[HH];

// ---------------- prep kernels ----------------
__global__ void k_init() {
    int i = blockIdx.x * blockDim.x + threadIdx.x;
    if (i < NN) { g_deg[i] = 0; g_cursor[i] = 0; }
    if (i < 4 * HH) g_stats[i] = 0.0f;
}

__global__ void k_count(const int* __restrict__ dst) {
    int e = blockIdx.x * blockDim.x + threadIdx.x;
    if (e < EE) atomicAdd(&g_deg[dst[e]], 1);
}

__global__ void k_scan1() {
    __shared__ int s[1024];
    int t = threadIdx.x;
    int i = blockIdx.x * 1024 + t;
    int v = (i < NN) ? g_deg[i] : 0;
    s[t] = v;
    __syncthreads();
    for (int off = 1; off < 1024; off <<= 1) {
        int x = (t >= off) ? s[t - off] : 0;
        __syncthreads();
        s[t] += x;
        __syncthreads();
    }
    if (i < NN) g_off[i] = s[t] - v;       // exclusive within block
    if (t == 1023) g_bsum[blockIdx.x] = s[1023];
}

__global__ void k_scan2() {
    if (threadIdx.x == 0 && blockIdx.x == 0) {
        int run = 0;
        for (int b = 0; b < NB_SCAN; b++) { int v = g_bsum[b]; g_bsum[b] = run; run += v; }
    }
}

__global__ void k_scan3() {
    int i = blockIdx.x * 1024 + threadIdx.x;
    if (i < NN) {
        g_off[i] += g_bsum[blockIdx.x];
        int d = g_deg[i];
        g_norm[i] = rsqrtf((float)(d > 0 ? d : 1));
    }
    if (i == NN) g_off[NN] = EE;
}

__global__ void k_fill(const int* __restrict__ src, const int* __restrict__ dst) {
    int e = blockIdx.x * blockDim.x + threadIdx.x;
    if (e < EE) {
        int d = dst[e];
        int p = atomicAdd(&g_cursor[d], 1);
        g_csr[g_off[d] + p] = src[e];
    }
}

// ---------------- propagation: one warp per node, pull-gather ----------------
__global__ __launch_bounds__(256) void k_gather(const float* __restrict__ hin,
                                                float* __restrict__ hout,
                                                int setacc) {
    int warp = (blockIdx.x * blockDim.x + threadIdx.x) >> 5;
    int lane = threadIdx.x & 31;
    if (warp >= NN) return;
    int beg = g_off[warp], end = g_off[warp + 1];
    const float2* hin2 = (const float2*)hin;
    float ax = 0.0f, ay = 0.0f;
    for (int e = beg; e < end; e++) {
        int j = g_csr[e];
        float nj = g_norm[j];
        float2 v = hin2[j * 32 + lane];
        ax = fmaf(nj, v.x, ax);
        ay = fmaf(nj, v.y, ay);
    }
    float ni = g_norm[warp];
    ax *= ni; ay *= ni;
    float2 r; r.x = ax; r.y = ay;
    ((float2*)hout)[warp * 32 + lane] = r;
    float2* acc2 = (float2*)g_acc;
    if (setacc) {
        acc2[warp * 32 + lane] = r;
    } else {
        float2 t = acc2[warp * 32 + lane];
        t.x += ax; t.y += ay;
        acc2[warp * 32 + lane] = t;
    }
}

// ---------------- fused GEMM (+ BN/ReLU on A-load, + bias + BN stats epilogue) -----
// PHASE 1: A = 0.2375*acc + 0.05*feat (K=64), out=y1, stats -> stats[0..2H)
// PHASE 2: A = relu(y1*bnA1 + bnC1)   (K=256), out=y2, stats -> stats[2H..4H)
// PHASE 3: A = relu(y2*bnA2 + bnC2)   (K=256), out=logits (ldo=40), no stats
template <int PHASE>
__global__ __launch_bounds__(256) void k_gemm(
    const float* __restrict__ A, const float* __restrict__ A2,
    const float* __restrict__ W, const float* __restrict__ bias,
    const float* __restrict__ bnA, const float* __restrict__ bnC,
    float* __restrict__ out, float* __restrict__ stats,
    int Kdim, int Ncols, int ldo)
{
    __shared__ float As[32 * 68];
    __shared__ float Bs[32 * 64];
    __shared__ float red[16 * 64];

    int tid = threadIdx.x;
    int tc = tid & 15;
    int tr = tid >> 4;
    int row0 = blockIdx.x * 64;
    int n0 = blockIdx.y * 64;

    float c[4][4];
#pragma unroll
    for (int r = 0; r < 4; r++)
#pragma unroll
        for (int q = 0; q < 4; q++) c[r][q] = 0.0f;

    for (int k0 = 0; k0 < Kdim; k0 += 32) {
        // A tile: 64 rows x 32 k, stored transposed As[k][row] (pad 68)
#pragma unroll
        for (int q = 0; q < 2; q++) {
            int idx = tid + q * 256;
            int i = idx >> 3;     // row within tile
            int kq = idx & 7;     // float4 index within 32-k chunk
            int gi = row0 + i;
            float4 v = make_float4(0.f, 0.f, 0.f, 0.f);
            if (gi < NN) {
                float4 a = *((const float4*)(A + (long)gi * Kdim + k0) + kq);
                if (PHASE == 1) {
                    float4 f = *((const float4*)(A2 + (long)gi * Kdim + k0) + kq);
                    v.x = 0.2375f * a.x + ALPHA * f.x;
                    v.y = 0.2375f * a.y + ALPHA * f.y;
                    v.z = 0.2375f * a.z + ALPHA * f.z;
                    v.w = 0.2375f * a.w + ALPHA * f.w;
                } else {
                    float4 s = *((const float4*)(bnA + k0) + kq);
                    float4 h = *((const float4*)(bnC + k0) + kq);
                    v.x = fmaxf(fmaf(a.x, s.x, h.x), 0.f);
                    v.y = fmaxf(fmaf(a.y, s.y, h.y), 0.f);
                    v.z = fmaxf(fmaf(a.z, s.z, h.z), 0.f);
                    v.w = fmaxf(fmaf(a.w, s.w, h.w), 0.f);
                }
            }
            int kk = kq * 4;
            As[(kk + 0) * 68 + i] = v.x;
            As[(kk + 1) * 68 + i] = v.y;
            As[(kk + 2) * 68 + i] = v.z;
            As[(kk + 3) * 68 + i] = v.w;
        }
        // B tile: 32 k x 64 n
#pragma unroll
        for (int q = 0; q < 2; q++) {
            int idx = tid + q * 256;
            int kb = idx >> 4;
            int nq = idx & 15;
            int gn = n0 + nq * 4;
            float4 b = make_float4(0.f, 0.f, 0.f, 0.f);
            if (gn < Ncols)
                b = *(const float4*)(W + (long)(k0 + kb) * Ncols + gn);
            *(float4*)&Bs[kb * 64 + nq * 4] = b;
        }
        __syncthreads();
#pragma unroll
        for (int k = 0; k < 32; k++) {
            float4 a = *(const float4*)&As[k * 68 + (tr << 2)];
            float4 b = *(const float4*)&Bs[(k << 6) + (tc << 2)];
            c[0][0] = fmaf(a.x, b.x, c[0][0]); c[0][1] = fmaf(a.x, b.y, c[0][1]);
            c[0][2] = fmaf(a.x, b.z, c[0][2]); c[0][3] = fmaf(a.x, b.w, c[0][3]);
            c[1][0] = fmaf(a.y, b.x, c[1][0]); c[1][1] = fmaf(a.y, b.y, c[1][1]);
            c[1][2] = fmaf(a.y, b.z, c[1][2]); c[1][3] = fmaf(a.y, b.w, c[1][3]);
            c[2][0] = fmaf(a.z, b.x, c[2][0]); c[2][1] = fmaf(a.z, b.y, c[2][1]);
            c[2][2] = fmaf(a.z, b.z, c[2][2]); c[2][3] = fmaf(a.z, b.w, c[2][3]);
            c[3][0] = fmaf(a.w, b.x, c[3][0]); c[3][1] = fmaf(a.w, b.y, c[3][1]);
            c[3][2] = fmaf(a.w, b.z, c[3][2]); c[3][3] = fmaf(a.w, b.w, c[3][3]);
        }
        __syncthreads();
    }

    // epilogue: bias add, store, stats
    int colg = n0 + (tc << 2);
    float4 bv = make_float4(0.f, 0.f, 0.f, 0.f);
    if (colg < Ncols) bv = *(const float4*)(bias + colg);
#pragma unroll
    for (int r = 0; r < 4; r++) {
        c[r][0] += bv.x; c[r][1] += bv.y; c[r][2] += bv.z; c[r][3] += bv.w;
    }
#pragma unroll
    for (int r = 0; r < 4; r++) {
        int gr = row0 + (tr << 2) + r;
        if (gr < NN && colg < Ncols) {
            float4 o; o.x = c[r][0]; o.y = c[r][1]; o.z = c[r][2]; o.w = c[r][3];
            *(float4*)(out + (long)gr * ldo + colg) = o;
        }
    }

    if (PHASE != 3) {
        // column sums of (biased) outputs across the 64 rows of this block
        int base = (tc << 2);
        // pass 1: sums
        float s[4];
#pragma unroll
        for (int q = 0; q < 4; q++) {
            float acc = 0.f;
#pragma unroll
            for (int r = 0; r < 4; r++) {
                int gr = row0 + (tr << 2) + r;
                acc += (gr < NN) ? c[r][q] : 0.f;
            }
            s[q] = acc;
        }
        __syncthreads();
#pragma unroll
        for (int q = 0; q < 4; q++) red[tr * 64 + base + q] = s[q];
        __syncthreads();
        for (int st = 8; st > 0; st >>= 1) {
            if (tr < st) {
#pragma unroll
                for (int q = 0; q < 4; q++)
                    red[tr * 64 + base + q] += red[(tr + st) * 64 + base + q];
            }
            __syncthreads();
        }
        if (tr == 0) {
#pragma unroll
            for (int q = 0; q < 4; q++)
                atomicAdd(&stats[colg + q], red[base + q]);
        }
        __syncthreads();
        // pass 2: sums of squares
#pragma unroll
        for (int q = 0; q < 4; q++) {
            float acc = 0.f;
#pragma unroll
            for (int r = 0; r < 4; r++) {
                int gr = row0 + (tr << 2) + r;
                float v = (gr < NN) ? c[r][q] : 0.f;
                acc = fmaf(v, v, acc);
            }
            s[q] = acc;
        }
        __syncthreads();
#pragma unroll
        for (int q = 0; q < 4; q++) red[tr * 64 + base + q] = s[q];
        __syncthreads();
        for (int st = 8; st > 0; st >>= 1) {
            if (tr < st) {
#pragma unroll
                for (int q = 0; q < 4; q++)
                    red[tr * 64 + base + q] += red[(tr + st) * 64 + base + q];
            }
            __syncthreads();
        }
        if (tr == 0) {
#pragma unroll
            for (int q = 0; q < 4; q++)
                atomicAdd(&stats[HH + colg + q], red[base + q]);
        }
    }
}

__global__ void k_bnfin(const float* __restrict__ stats, const float* __restrict__ g,
                        const float* __restrict__ be, float* __restrict__ bnA,
                        float* __restrict__ bnC) {
    int col = threadIdx.x;
    if (col < HH) {
        float inv = 1.0f / (float)NN;
        float mean = stats[col] * inv;
        float var = stats[HH + col] * inv - mean * mean;
        float rstd = rsqrtf(var + BNEPS);
        float a = g[col] * rstd;
        bnA[col] = a;
        bnC[col] = be[col] - a * mean;
    }
}

// ---------------- launch ----------------
extern "C" void kernel_launch(void* const* d_in, const int* in_sizes, int n_in,
                              void* d_out, int out_size) {
    const float* feat = (const float*)d_in[0];
    const int*   src  = (const int*)d_in[1];
    const int*   dst  = (const int*)d_in[2];
    const float* W1   = (const float*)d_in[3];
    const float* b1   = (const float*)d_in[4];
    const float* g1   = (const float*)d_in[5];
    const float* be1  = (const float*)d_in[6];
    const float* W2   = (const float*)d_in[7];
    const float* b2   = (const float*)d_in[8];
    const float* g2   = (const float*)d_in[9];
    const float* be2  = (const float*)d_in[10];
    const float* W3   = (const float*)d_in[11];
    const float* b3   = (const float*)d_in[12];
    float* out = (float*)d_out;

    float *p_hA, *p_hB, *p_acc, *p_y1, *p_y2, *p_stats;
    float *p_bnA1, *p_bnC1, *p_bnA2, *p_bnC2;
    cudaGetSymbolAddress((void**)&p_hA, g_hA);
    cudaGetSymbolAddress((void**)&p_hB, g_hB);
    cudaGetSymbolAddress((void**)&p_acc, g_acc);
    cudaGetSymbolAddress((void**)&p_y1, g_y1);
    cudaGetSymbolAddress((void**)&p_y2, g_y2);
    cudaGetSymbolAddress((void**)&p_stats, g_stats);
    cudaGetSymbolAddress((void**)&p_bnA1, g_bnA1);
    cudaGetSymbolAddress((void**)&p_bnC1, g_bnC1);
    cudaGetSymbolAddress((void**)&p_bnA2, g_bnA2);
    cudaGetSymbolAddress((void**)&p_bnC2, g_bnC2);

    k_init<<<(NN + 255) / 256, 256>>>();
    k_count<<<(EE + 255) / 256, 256>>>(dst);
    k_scan1<<<NB_SCAN, 1024>>>();
    k_scan2<<<1, 32>>>();
    k_scan3<<<NB_SCAN, 1024>>>();
    k_fill<<<(EE + 255) / 256, 256>>>(src, dst);

    int gblocks = (NN * 32 + 255) / 256;  // one warp per node
    k_gather<<<gblocks, 256>>>(feat, p_hA, 1);
    k_gather<<<gblocks, 256>>>(p_hA, p_hB, 0);
    k_gather<<<gblocks, 256>>>(p_hB, p_hA, 0);
    k_gather<<<gblocks, 256>>>(p_hA, p_hB, 0);

    dim3 grid12((NN + 63) / 64, HH / 64);
    k_gemm<1><<<grid12, 256>>>(p_acc, feat, W1, b1, nullptr, nullptr,
                               p_y1, p_stats, DD, HH, HH);
    k_bnfin<<<1, 256>>>(p_stats, g1, be1, p_bnA1, p_bnC1);
    k_gemm<2><<<grid12, 256>>>(p_y1, nullptr, W2, b2, p_bnA1, p_bnC1,
                               p_y2, p_stats + 2 * HH, HH, HH, HH);
    k_bnfin<<<1, 256>>>(p_stats + 2 * HH, g2, be2, p_bnA2, p_bnC2);
    dim3 grid3((NN + 63) / 64, 1);
    k_gemm<3><<<grid3, 256>>>(p_y2, nullptr, W3, b3, p_bnA2, p_bnC2,
                              out, nullptr, HH, CC, CC);
}

// round 3
// speedup vs baseline: 1.3615x; 1.3615x over previous
#include <cuda_runtime.h>
#include <cuda_bf16.h>
#include <math.h>
#include <stdint.h>

// Problem constants
#define NN 100000
#define EE 1250000
#define DD 64
#define HH 256
#define CC 40
#define BNEPS 1e-5f
#define NB_SCAN 98   // ceil(100000/1024)

// ---------------- device scratch ----------------
__device__ float g_zA[NN * DD];
__device__ float g_zB[NN * DD];
__device__ float g_acc[NN * DD];
__device__ float g_norm[NN];
__device__ int   g_deg[NN];
__device__ int   g_off[NN + 1];
__device__ int   g_cursor[NN];
__device__ int   g_csr[EE];
__device__ int   g_bsum[NB_SCAN];
__device__ float g_y1[NN * HH];
__device__ float g_y2[NN * HH];
__device__ float g_stats[4 * HH];
__device__ float g_bnA1[HH], g_bnC1[HH], g_bnA2[HH], g_bnC2[HH];
// bf16 split weights, K-major transposed: Wt[n][k]
__device__ __nv_bfloat16 g_w1h[HH * DD], g_w1l[HH * DD];
__device__ __nv_bfloat16 g_w2h[HH * HH], g_w2l[HH * HH];
__device__ __nv_bfloat16 g_w3h[64 * HH], g_w3l[64 * HH];

// ---------------- helpers ----------------
__device__ __forceinline__ uint32_t smem_u32(const void* p) {
    uint32_t a;
    asm("{ .reg .u64 t; cvta.to.shared.u64 t, %1; cvt.u32.u64 %0, t; }" : "=r"(a) : "l"(p));
    return a;
}
__device__ __forceinline__ void ldm_x4(uint32_t* r, uint32_t addr) {
    asm volatile("ldmatrix.sync.aligned.m8n8.x4.shared.b16 {%0,%1,%2,%3}, [%4];"
                 : "=r"(r[0]), "=r"(r[1]), "=r"(r[2]), "=r"(r[3]) : "r"(addr));
}
__device__ __forceinline__ void ldm_x2(uint32_t* r, uint32_t addr) {
    asm volatile("ldmatrix.sync.aligned.m8n8.x2.shared.b16 {%0,%1}, [%2];"
                 : "=r"(r[0]), "=r"(r[1]) : "r"(addr));
}
__device__ __forceinline__ void mma_bf16(float* c, const uint32_t* a, const uint32_t* b) {
    asm volatile(
        "mma.sync.aligned.m16n8k16.row.col.f32.bf16.bf16.f32 "
        "{%0,%1,%2,%3}, {%4,%5,%6,%7}, {%8,%9}, {%0,%1,%2,%3};"
        : "+f"(c[0]), "+f"(c[1]), "+f"(c[2]), "+f"(c[3])
        : "r"(a[0]), "r"(a[1]), "r"(a[2]), "r"(a[3]), "r"(b[0]), "r"(b[1]));
}
__device__ __forceinline__ void split_pack(float x, float y, uint32_t& hi, uint32_t& lo) {
    __nv_bfloat16 hx = __float2bfloat16(x), hy = __float2bfloat16(y);
    float rx = x - __bfloat162float(hx), ry = y - __bfloat162float(hy);
    __nv_bfloat16 lx = __float2bfloat16(rx), ly = __float2bfloat16(ry);
    hi = (uint32_t)__bfloat16_as_ushort(hx) | ((uint32_t)__bfloat16_as_ushort(hy) << 16);
    lo = (uint32_t)__bfloat16_as_ushort(lx) | ((uint32_t)__bfloat16_as_ushort(ly) << 16);
}

// ---------------- prep kernels ----------------
__global__ void k_init() {
    int i = blockIdx.x * blockDim.x + threadIdx.x;
    if (i < NN) { g_deg[i] = 0; g_cursor[i] = 0; }
    if (i < 4 * HH) g_stats[i] = 0.0f;
}
__global__ void k_count(const int* __restrict__ dst) {
    int e = blockIdx.x * blockDim.x + threadIdx.x;
    if (e < EE) atomicAdd(&g_deg[dst[e]], 1);
}
__global__ void k_scan1() {
    __shared__ int s[1024];
    int t = threadIdx.x;
    int i = blockIdx.x * 1024 + t;
    int v = (i < NN) ? g_deg[i] : 0;
    s[t] = v;
    __syncthreads();
    for (int off = 1; off < 1024; off <<= 1) {
        int x = (t >= off) ? s[t - off] : 0;
        __syncthreads();
        s[t] += x;
        __syncthreads();
    }
    if (i < NN) g_off[i] = s[t] - v;
    if (t == 1023) g_bsum[blockIdx.x] = s[1023];
}
__global__ void k_scan2() {
    if (threadIdx.x == 0) {
        int run = 0;
        for (int b = 0; b < NB_SCAN; b++) { int v = g_bsum[b]; g_bsum[b] = run; run += v; }
    }
}
__global__ void k_scan3() {
    int i = blockIdx.x * 1024 + threadIdx.x;
    if (i < NN) {
        g_off[i] += g_bsum[blockIdx.x];
        int d = g_deg[i];
        g_norm[i] = rsqrtf((float)(d > 0 ? d : 1));
    }
    if (i == NN) g_off[NN] = EE;
}
__global__ void k_fill(const int* __restrict__ src, const int* __restrict__ dst) {
    int e = blockIdx.x * blockDim.x + threadIdx.x;
    if (e < EE) {
        int d = dst[e];
        int p = atomicAdd(&g_cursor[d], 1);
        g_csr[g_off[d] + p] = src[e];
    }
}
// W [K][Nsrc] row-major -> Wt hi/lo [Npad][K] bf16
__global__ void k_wt(const float* __restrict__ W, __nv_bfloat16* __restrict__ hi,
                     __nv_bfloat16* __restrict__ lo, int K, int Nsrc, int Npad) {
    int idx = blockIdx.x * blockDim.x + threadIdx.x;
    if (idx >= K * Npad) return;
    int n = idx / K, k = idx - n * K;
    float v = (n < Nsrc) ? W[(size_t)k * Nsrc + n] : 0.0f;
    __nv_bfloat16 h = __float2bfloat16(v);
    float r = v - __bfloat162float(h);
    hi[idx] = h;
    lo[idx] = __float2bfloat16(r);
}
__global__ void k_prescale(const float* __restrict__ feat) {
    int i = blockIdx.x * blockDim.x + threadIdx.x;
    if (i < NN * 32) {
        float n = g_norm[i >> 5];
        float2 v = ((const float2*)feat)[i];
        ((float2*)g_zA)[i] = make_float2(n * v.x, n * v.y);
    }
}

// ---------------- propagation: one warp per node, pull-gather (pre-scaled) ----
__global__ __launch_bounds__(256) void k_gather(const float* __restrict__ zin,
                                                float* __restrict__ zout, int setacc) {
    int warp = (blockIdx.x * blockDim.x + threadIdx.x) >> 5;
    int lane = threadIdx.x & 31;
    if (warp >= NN) return;
    int beg = g_off[warp], end = g_off[warp + 1];
    const float2* z2 = (const float2*)zin;
    float ax = 0.f, ay = 0.f, bx = 0.f, by = 0.f;
    int e = beg;
    for (; e + 4 <= end; e += 4) {
        int j0 = g_csr[e], j1 = g_csr[e + 1], j2 = g_csr[e + 2], j3 = g_csr[e + 3];
        float2 v0 = z2[j0 * 32 + lane];
        float2 v1 = z2[j1 * 32 + lane];
        float2 v2 = z2[j2 * 32 + lane];
        float2 v3 = z2[j3 * 32 + lane];
        ax += v0.x; ay += v0.y; bx += v1.x; by += v1.y;
        ax += v2.x; ay += v2.y; bx += v3.x; by += v3.y;
    }
    for (; e < end; e++) {
        int j = g_csr[e];
        float2 v = z2[j * 32 + lane];
        ax += v.x; ay += v.y;
    }
    ax += bx; ay += by;
    float ni = g_norm[warp];
    float hx = ni * ax, hy = ni * ay;
    int idx = warp * 32 + lane;
    float2* acc2 = (float2*)g_acc;
    if (setacc) {
        acc2[idx] = make_float2(hx, hy);
    } else {
        float2 t = acc2[idx];
        acc2[idx] = make_float2(t.x + hx, t.y + hy);
    }
    ((float2*)zout)[idx] = make_float2(ni * hx, ni * hy);
}

// ---------------- warp-tiled mma.sync split-bf16 GEMM ----------------
// out[128 x NTILE] = A'[128 x KDIM] @ Wt^T slice, fp32 accum.
// PHASE 1: A' = 0.2375*A + 0.05*A2
// PHASE 2/3: A' = relu(A*bnA + bnC); PHASE 3 adds bias on store.
// 8 warps: warp_m in {0,1} (64 rows), warp_n in 0..3 (NTILE/4 cols).
template <int KDIM, int NTILE, int PHASE, int LDO, int NSTORE>
__global__ __launch_bounds__(256) void k_mma(
    const float* __restrict__ A, const float* __restrict__ A2,
    const __nv_bfloat16* __restrict__ Bhi, const __nv_bfloat16* __restrict__ Blo,
    const float* __restrict__ bnA, const float* __restrict__ bnC,
    const float* __restrict__ bias, float* __restrict__ out)
{
    constexpr int WN = NTILE / 4;     // warp n-width
    constexpr int NT8 = WN / 8;       // n8 tiles per warp (4 or 2)
    constexpr int LDS = 40;           // smem row stride (bf16 elems): 80B, conflict-free

    __shared__ __align__(16) __nv_bfloat16 sAhi[128 * LDS];
    __shared__ __align__(16) __nv_bfloat16 sAlo[128 * LDS];
    __shared__ __align__(16) __nv_bfloat16 sBhi[NTILE * LDS];
    __shared__ __align__(16) __nv_bfloat16 sBlo[NTILE * LDS];

    int tid = threadIdx.x, lane = tid & 31, wid = tid >> 5;
    int warp_m = wid & 1, warp_n = wid >> 1;
    int row0 = blockIdx.x * 128;
    int n0 = blockIdx.y * NTILE;

    float c[4][NT8][4];
#pragma unroll
    for (int mt = 0; mt < 4; mt++)
#pragma unroll
        for (int nt = 0; nt < NT8; nt++)
#pragma unroll
            for (int q = 0; q < 4; q++) c[mt][nt][q] = 0.0f;

    uint32_t aAhi = smem_u32(sAhi), aAlo = smem_u32(sAlo);
    uint32_t aBhi = smem_u32(sBhi), aBlo = smem_u32(sBlo);

    int arow = lane & 15;              // ldmatrix A: row within 16
    int acol8 = (lane >> 4) << 3;      // 0 or 8
    int brow = lane & 7;               // ldmatrix B: n-row within 8
    int bcol8 = ((lane & 15) >> 3) << 3;

#pragma unroll 1
    for (int ch = 0; ch < KDIM / 32; ch++) {
        int k0 = ch * 32;
        // --- A chunk: 128 rows x 32 k, fp32 -> transform -> split bf16 hi/lo ---
#pragma unroll
        for (int it = 0; it < 4; it++) {
            int idx = tid + it * 256;        // 1024 float4
            int r = idx >> 3, q = idx & 7;
            int gi = row0 + r;
            float4 v = make_float4(0.f, 0.f, 0.f, 0.f);
            if (gi < NN) {
                float4 a = ((const float4*)(A + (size_t)gi * KDIM + k0))[q];
                if (PHASE == 1) {
                    float4 f = ((const float4*)(A2 + (size_t)gi * KDIM + k0))[q];
                    v.x = 0.2375f * a.x + 0.05f * f.x;
                    v.y = 0.2375f * a.y + 0.05f * f.y;
                    v.z = 0.2375f * a.z + 0.05f * f.z;
                    v.w = 0.2375f * a.w + 0.05f * f.w;
                } else {
                    int kc = k0 + q * 4;
                    float4 s = *(const float4*)(bnA + kc);
                    float4 h = *(const float4*)(bnC + kc);
                    v.x = fmaxf(fmaf(a.x, s.x, h.x), 0.f);
                    v.y = fmaxf(fmaf(a.y, s.y, h.y), 0.f);
                    v.z = fmaxf(fmaf(a.z, s.z, h.z), 0.f);
                    v.w = fmaxf(fmaf(a.w, s.w, h.w), 0.f);
                }
            }
            uint32_t h01, l01, h23, l23;
            split_pack(v.x, v.y, h01, l01);
            split_pack(v.z, v.w, h23, l23);
            *(uint2*)&sAhi[r * LDS + q * 4] = make_uint2(h01, h23);
            *(uint2*)&sAlo[r * LDS + q * 4] = make_uint2(l01, l23);
        }
        // --- B chunk: NTILE rows(n) x 32 k, pre-split bf16 ---
#pragma unroll
        for (int it = 0; it < (NTILE * 4) / 256; it++) {
            int idx = tid + it * 256;        // NTILE*4 uint4 per split
            int n = idx >> 2, q = idx & 3;
            size_t goff = (size_t)(n0 + n) * KDIM + k0 + q * 8;
            uint4 h = *(const uint4*)(Bhi + goff);
            uint4 l = *(const uint4*)(Blo + goff);
            *(uint4*)&sBhi[n * LDS + q * 8] = h;
            *(uint4*)&sBlo[n * LDS + q * 8] = l;
        }
        __syncthreads();
        // --- compute: two k16 steps ---
#pragma unroll
        for (int ks = 0; ks < 2; ks++) {
            int kc = ks * 16;
            uint32_t bh[NT8][2], bl[NT8][2];
#pragma unroll
            for (int nt = 0; nt < NT8; nt++) {
                int n = warp_n * WN + nt * 8 + brow;
                uint32_t off = (uint32_t)(n * LDS + kc + bcol8) * 2;
                ldm_x2(bh[nt], aBhi + off);
                ldm_x2(bl[nt], aBlo + off);
            }
#pragma unroll
            for (int mt = 0; mt < 4; mt++) {
                int r = warp_m * 64 + mt * 16 + arow;
                uint32_t off = (uint32_t)(r * LDS + kc + acol8) * 2;
                uint32_t ah[4], al[4];
                ldm_x4(ah, aAhi + off);
                ldm_x4(al, aAlo + off);
#pragma unroll
                for (int nt = 0; nt < NT8; nt++) {
                    mma_bf16(c[mt][nt], ah, bh[nt]);
                    mma_bf16(c[mt][nt], al, bh[nt]);
                    mma_bf16(c[mt][nt], ah, bl[nt]);
                }
            }
        }
        __syncthreads();
    }

    // --- epilogue: direct stores from fragments ---
    int colbase = n0 + warp_n * WN + ((lane & 3) << 1);
    int rbase = row0 + warp_m * 64 + (lane >> 2);
#pragma unroll
    for (int mt = 0; mt < 4; mt++) {
        int r0g = rbase + mt * 16;
#pragma unroll
        for (int nt = 0; nt < NT8; nt++) {
            int col = colbase + nt * 8;
            if (NSTORE < NTILE && col >= NSTORE) continue;
            float bx = 0.f, by = 0.f;
            if (PHASE == 3) { bx = bias[col]; by = bias[col + 1]; }
            if (r0g < NN)
                *(float2*)(out + (size_t)r0g * LDO + col) =
                    make_float2(c[mt][nt][0] + bx, c[mt][nt][1] + by);
            if (r0g + 8 < NN)
                *(float2*)(out + (size_t)(r0g + 8) * LDO + col) =
                    make_float2(c[mt][nt][2] + bx, c[mt][nt][3] + by);
        }
    }
}

// ---------------- BN stats + finalize ----------------
__global__ __launch_bounds__(256) void k_stats(const float* __restrict__ y,
                                               float* __restrict__ stats) {
    __shared__ float red[4][512];
    int cg = (threadIdx.x & 63) << 2;
    int rl = threadIdx.x >> 6;
    float4 s = make_float4(0.f, 0.f, 0.f, 0.f);
    float4 q = make_float4(0.f, 0.f, 0.f, 0.f);
    for (int r = blockIdx.x * 4 + rl; r < NN; r += gridDim.x * 4) {
        float4 v = *(const float4*)(y + (size_t)r * HH + cg);
        s.x += v.x; s.y += v.y; s.z += v.z; s.w += v.w;
        q.x = fmaf(v.x, v.x, q.x); q.y = fmaf(v.y, v.y, q.y);
        q.z = fmaf(v.z, v.z, q.z); q.w = fmaf(v.w, v.w, q.w);
    }
    *(float4*)&red[rl][cg] = s;
    *(float4*)&red[rl][256 + cg] = q;
    __syncthreads();
    if (rl == 0) {
#pragma unroll
        for (int i = 0; i < 4; i++) {
            float a = red[0][cg + i] + red[1][cg + i] + red[2][cg + i] + red[3][cg + i];
            float b = red[0][256 + cg + i] + red[1][256 + cg + i] +
                      red[2][256 + cg + i] + red[3][256 + cg + i];
            atomicAdd(&stats[cg + i], a);
            atomicAdd(&stats[HH + cg + i], b);
        }
    }
}
__global__ void k_bnfin(const float* __restrict__ stats, const float* __restrict__ g,
                        const float* __restrict__ be, float* __restrict__ bnA,
                        float* __restrict__ bnC) {
    int col = threadIdx.x;
    if (col < HH) {
        float inv = 1.0f / (float)NN;
        float mean = stats[col] * inv;
        float var = stats[HH + col] * inv - mean * mean;
        float rstd = rsqrtf(var + BNEPS);
        float a = g[col] * rstd;
        bnA[col] = a;
        bnC[col] = be[col] - a * mean;
    }
}

// ---------------- launch ----------------
extern "C" void kernel_launch(void* const* d_in, const int* in_sizes, int n_in,
                              void* d_out, int out_size) {
    const float* feat = (const float*)d_in[0];
    const int*   src  = (const int*)d_in[1];
    const int*   dst  = (const int*)d_in[2];
    const float* W1   = (const float*)d_in[3];
    const float* g1   = (const float*)d_in[5];
    const float* be1  = (const float*)d_in[6];
    const float* W2   = (const float*)d_in[7];
    const float* g2   = (const float*)d_in[9];
    const float* be2  = (const float*)d_in[10];
    const float* W3   = (const float*)d_in[11];
    const float* b3   = (const float*)d_in[12];
    float* out = (float*)d_out;

    float *p_zA, *p_zB, *p_acc, *p_y1, *p_y2, *p_stats;
    float *p_bnA1, *p_bnC1, *p_bnA2, *p_bnC2;
    __nv_bfloat16 *p_w1h, *p_w1l, *p_w2h, *p_w2l, *p_w3h, *p_w3l;
    cudaGetSymbolAddress((void**)&p_zA, g_zA);
    cudaGetSymbolAddress((void**)&p_zB, g_zB);
    cudaGetSymbolAddress((void**)&p_acc, g_acc);
    cudaGetSymbolAddress((void**)&p_y1, g_y1);
    cudaGetSymbolAddress((void**)&p_y2, g_y2);
    cudaGetSymbolAddress((void**)&p_stats, g_stats);
    cudaGetSymbolAddress((void**)&p_bnA1, g_bnA1);
    cudaGetSymbolAddress((void**)&p_bnC1, g_bnC1);
    cudaGetSymbolAddress((void**)&p_bnA2, g_bnA2);
    cudaGetSymbolAddress((void**)&p_bnC2, g_bnC2);
    cudaGetSymbolAddress((void**)&p_w1h, g_w1h);
    cudaGetSymbolAddress((void**)&p_w1l, g_w1l);
    cudaGetSymbolAddress((void**)&p_w2h, g_w2h);
    cudaGetSymbolAddress((void**)&p_w2l, g_w2l);
    cudaGetSymbolAddress((void**)&p_w3h, g_w3h);
    cudaGetSymbolAddress((void**)&p_w3l, g_w3l);

    // CSR build
    k_init<<<(NN + 255) / 256, 256>>>();
    k_count<<<(EE + 255) / 256, 256>>>(dst);
    k_scan1<<<NB_SCAN, 1024>>>();
    k_scan2<<<1, 32>>>();
    k_scan3<<<NB_SCAN, 1024>>>();
    k_fill<<<(EE + 255) / 256, 256>>>(src, dst);

    // weight split/transpose (tiny)
    k_wt<<<(HH * DD + 255) / 256, 256>>>(W1, p_w1h, p_w1l, DD, HH, HH);
    k_wt<<<(HH * HH + 255) / 256, 256>>>(W2, p_w2h, p_w2l, HH, HH, HH);
    k_wt<<<(64 * HH + 255) / 256, 256>>>(W3, p_w3h, p_w3l, HH, CC, 64);

    // propagation
    k_prescale<<<(NN * 32 + 255) / 256, 256>>>(feat);
    int gblocks = (NN * 32 + 255) / 256;
    k_gather<<<gblocks, 256>>>(p_zA, p_zB, 1);
    k_gather<<<gblocks, 256>>>(p_zB, p_zA, 0);
    k_gather<<<gblocks, 256>>>(p_zA, p_zB, 0);
    k_gather<<<gblocks, 256>>>(p_zB, p_zA, 0);

    int mgrid = (NN + 127) / 128;  // 782
    dim3 grid12(mgrid, HH / 128);  // y = 2
    k_mma<64, 128, 1, 256, 128><<<grid12, 256>>>(
        p_acc, feat, p_w1h, p_w1l, nullptr, nullptr, nullptr, p_y1);
    k_stats<<<512, 256>>>(p_y1, p_stats);
    k_bnfin<<<1, 256>>>(p_stats, g1, be1, p_bnA1, p_bnC1);
    k_mma<256, 128, 2, 256, 128><<<grid12, 256>>>(
        p_y1, nullptr, p_w2h, p_w2l, p_bnA1, p_bnC1, nullptr, p_y2);
    k_stats<<<512, 256>>>(p_y2, p_stats + 2 * HH);
    k_bnfin<<<1, 256>>>(p_stats + 2 * HH, g2, be2, p_bnA2, p_bnC2);
    dim3 grid3(mgrid, 1);
    k_mma<256, 64, 3, 40, 40><<<grid3, 256>>>(
        p_y2, nullptr, p_w3h, p_w3l, p_bnA2, p_bnC2, b3, out);
}

// round 4
// speedup vs baseline: 1.5872x; 1.1658x over previous
#include <cuda_runtime.h>
#include <cuda_bf16.h>
#include <math.h>
#include <stdint.h>

#define NN 100000
#define EE 1250000
#define DD 64
#define HH 256
#define CC 40
#define BNEPS 1e-5f
#define NB_SCAN 98

// ---------------- device scratch ----------------
__device__ float g_zA[NN * DD];
__device__ float g_zB[NN * DD];
__device__ float g_acc[NN * DD];
__device__ float g_norm[NN];
__device__ int   g_deg[NN];
__device__ int   g_off[NN + 1];
__device__ int   g_cursor[NN];
__device__ int   g_csr[EE];
__device__ int   g_bsum[NB_SCAN];
__device__ float g_y1[NN * HH];
__device__ float g_y2[NN * HH];
__device__ float g_stats[4 * HH];
__device__ float g_bnA1[HH], g_bnC1[HH], g_bnA2[HH], g_bnC2[HH];
__device__ __nv_bfloat16 g_w1h[HH * DD], g_w1l[HH * DD];
__device__ __nv_bfloat16 g_w2h[HH * HH], g_w2l[HH * HH];
__device__ __nv_bfloat16 g_w3h[64 * HH], g_w3l[64 * HH];

// ---------------- helpers ----------------
__device__ __forceinline__ uint32_t smem_u32(const void* p) {
    uint32_t a;
    asm("{ .reg .u64 t; cvta.to.shared.u64 t, %1; cvt.u32.u64 %0, t; }" : "=r"(a) : "l"(p));
    return a;
}
__device__ __forceinline__ void ldm_x4(uint32_t* r, uint32_t addr) {
    asm volatile("ldmatrix.sync.aligned.m8n8.x4.shared.b16 {%0,%1,%2,%3}, [%4];"
                 : "=r"(r[0]), "=r"(r[1]), "=r"(r[2]), "=r"(r[3]) : "r"(addr));
}
__device__ __forceinline__ void ldm_x2(uint32_t* r, uint32_t addr) {
    asm volatile("ldmatrix.sync.aligned.m8n8.x2.shared.b16 {%0,%1}, [%2];"
                 : "=r"(r[0]), "=r"(r[1]) : "r"(addr));
}
__device__ __forceinline__ void mma_bf16(float* c, const uint32_t* a, const uint32_t* b) {
    asm volatile(
        "mma.sync.aligned.m16n8k16.row.col.f32.bf16.bf16.f32 "
        "{%0,%1,%2,%3}, {%4,%5,%6,%7}, {%8,%9}, {%0,%1,%2,%3};"
        : "+f"(c[0]), "+f"(c[1]), "+f"(c[2]), "+f"(c[3])
        : "r"(a[0]), "r"(a[1]), "r"(a[2]), "r"(a[3]), "r"(b[0]), "r"(b[1]));
}
__device__ __forceinline__ void split_pack(float x, float y, uint32_t& hi, uint32_t& lo) {
    __nv_bfloat16 hx = __float2bfloat16(x), hy = __float2bfloat16(y);
    float rx = x - __bfloat162float(hx), ry = y - __bfloat162float(hy);
    __nv_bfloat16 lx = __float2bfloat16(rx), ly = __float2bfloat16(ry);
    hi = (uint32_t)__bfloat16_as_ushort(hx) | ((uint32_t)__bfloat16_as_ushort(hy) << 16);
    lo = (uint32_t)__bfloat16_as_ushort(lx) | ((uint32_t)__bfloat16_as_ushort(ly) << 16);
}

// ---------------- prep kernels ----------------
__global__ void k_init() {
    int i = blockIdx.x * blockDim.x + threadIdx.x;
    if (i < NN) { g_deg[i] = 0; g_cursor[i] = 0; }
    if (i < 4 * HH) g_stats[i] = 0.0f;
}
__global__ void k_count(const int* __restrict__ dst) {
    int e = blockIdx.x * blockDim.x + threadIdx.x;
    if (e < EE) atomicAdd(&g_deg[dst[e]], 1);
}
__global__ void k_scan1() {
    __shared__ int s[1024];
    int t = threadIdx.x;
    int i = blockIdx.x * 1024 + t;
    int v = (i < NN) ? g_deg[i] : 0;
    s[t] = v;
    __syncthreads();
    for (int off = 1; off < 1024; off <<= 1) {
        int x = (t >= off) ? s[t - off] : 0;
        __syncthreads();
        s[t] += x;
        __syncthreads();
    }
    if (i < NN) g_off[i] = s[t] - v;
    if (t == 1023) g_bsum[blockIdx.x] = s[1023];
}
__global__ void k_scan2() {   // parallel small scan, 128 threads
    __shared__ int s[128];
    int t = threadIdx.x;
    int v = (t < NB_SCAN) ? g_bsum[t] : 0;
    s[t] = v;
    __syncthreads();
    for (int off = 1; off < 128; off <<= 1) {
        int x = (t >= off) ? s[t - off] : 0;
        __syncthreads();
        s[t] += x;
        __syncthreads();
    }
    if (t < NB_SCAN) g_bsum[t] = s[t] - v;
}
__global__ void k_scan3() {
    int i = blockIdx.x * 1024 + threadIdx.x;
    if (i < NN) {
        g_off[i] += g_bsum[blockIdx.x];
        int d = g_deg[i];
        g_norm[i] = rsqrtf((float)(d > 0 ? d : 1));
    }
    if (i == NN) g_off[NN] = EE;
}
__global__ void k_fill(const int* __restrict__ src, const int* __restrict__ dst) {
    int e = blockIdx.x * blockDim.x + threadIdx.x;
    if (e < EE) {
        int d = dst[e];
        int p = atomicAdd(&g_cursor[d], 1);
        g_csr[g_off[d] + p] = src[e];
    }
}
__global__ void k_wt(const float* __restrict__ W, __nv_bfloat16* __restrict__ hi,
                     __nv_bfloat16* __restrict__ lo, int K, int Nsrc, int Npad) {
    int idx = blockIdx.x * blockDim.x + threadIdx.x;
    if (idx >= K * Npad) return;
    int n = idx / K, k = idx - n * K;
    float v = (n < Nsrc) ? W[(size_t)k * Nsrc + n] : 0.0f;
    __nv_bfloat16 h = __float2bfloat16(v);
    float r = v - __bfloat162float(h);
    hi[idx] = h;
    lo[idx] = __float2bfloat16(r);
}

// ---------------- propagation ----------------
// FIRST=1: zin is raw feat; multiply norm[j] per edge (fuses prescale).
template <int FIRST>
__global__ __launch_bounds__(256) void k_gather(const float* __restrict__ zin,
                                                float* __restrict__ zout, int setacc) {
    int warp = (blockIdx.x * blockDim.x + threadIdx.x) >> 5;
    int lane = threadIdx.x & 31;
    if (warp >= NN) return;
    int beg = g_off[warp], end = g_off[warp + 1];
    const float2* z2 = (const float2*)zin;
    float ax = 0.f, ay = 0.f, bx = 0.f, by = 0.f;
    int e = beg;
    for (; e + 4 <= end; e += 4) {
        int j0 = g_csr[e], j1 = g_csr[e + 1], j2 = g_csr[e + 2], j3 = g_csr[e + 3];
        float2 v0 = z2[j0 * 32 + lane];
        float2 v1 = z2[j1 * 32 + lane];
        float2 v2 = z2[j2 * 32 + lane];
        float2 v3 = z2[j3 * 32 + lane];
        if (FIRST) {
            float n0 = g_norm[j0], n1 = g_norm[j1], n2 = g_norm[j2], n3 = g_norm[j3];
            ax = fmaf(n0, v0.x, ax); ay = fmaf(n0, v0.y, ay);
            bx = fmaf(n1, v1.x, bx); by = fmaf(n1, v1.y, by);
            ax = fmaf(n2, v2.x, ax); ay = fmaf(n2, v2.y, ay);
            bx = fmaf(n3, v3.x, bx); by = fmaf(n3, v3.y, by);
        } else {
            ax += v0.x; ay += v0.y; bx += v1.x; by += v1.y;
            ax += v2.x; ay += v2.y; bx += v3.x; by += v3.y;
        }
    }
    for (; e < end; e++) {
        int j = g_csr[e];
        float2 v = z2[j * 32 + lane];
        if (FIRST) {
            float nj = g_norm[j];
            ax = fmaf(nj, v.x, ax); ay = fmaf(nj, v.y, ay);
        } else {
            ax += v.x; ay += v.y;
        }
    }
    ax += bx; ay += by;
    float ni = g_norm[warp];
    float hx = ni * ax, hy = ni * ay;
    int idx = warp * 32 + lane;
    float2* acc2 = (float2*)g_acc;
    if (setacc) {
        acc2[idx] = make_float2(hx, hy);
    } else {
        float2 t = acc2[idx];
        acc2[idx] = make_float2(t.x + hx, t.y + hy);
    }
    ((float2*)zout)[idx] = make_float2(ni * hx, ni * hy);
}

// ---------------- big GEMM: CTA 128x256, 512 threads, reg-staged A pipeline ---
// PHASE 1: A' = 0.2375*A + 0.05*A2 ; PHASE 2: A' = relu(A*bnA + bnC)
// out[128x256] fp32; fused BN stats (col sum / sumsq) via shfl + global atomics.
template <int KDIM, int PHASE>
__global__ __launch_bounds__(512, 1) void k_mma_big(
    const float* __restrict__ A, const float* __restrict__ A2,
    const __nv_bfloat16* __restrict__ Bhi, const __nv_bfloat16* __restrict__ Blo,
    const float* __restrict__ bnA, const float* __restrict__ bnC,
    float* __restrict__ out, float* __restrict__ stats)
{
    constexpr int LDS = 40;                 // bf16 row stride (80B)
    extern __shared__ __align__(16) char smem[];
    __nv_bfloat16* sAhi = (__nv_bfloat16*)(smem);            // 128*40
    __nv_bfloat16* sAlo = (__nv_bfloat16*)(smem + 10240);
    __nv_bfloat16* sBhi = (__nv_bfloat16*)(smem + 20480);    // 256*40
    __nv_bfloat16* sBlo = (__nv_bfloat16*)(smem + 40960);

    int tid = threadIdx.x, lane = tid & 31, wid = tid >> 5;
    int warp_m = wid & 3, warp_n = wid >> 2;     // 4 x 4 warps: 32 rows x 64 cols each
    int row0 = blockIdx.x * 128;

    float c[2][8][4];
#pragma unroll
    for (int mt = 0; mt < 2; mt++)
#pragma unroll
        for (int nt = 0; nt < 8; nt++)
#pragma unroll
            for (int q = 0; q < 4; q++) c[mt][nt][q] = 0.0f;

    uint32_t aAhi = smem_u32(sAhi), aAlo = smem_u32(sAlo);
    uint32_t aBhi = smem_u32(sBhi), aBlo = smem_u32(sBlo);

    // A stage mapping: per thread 2 float4 (it=0,1); row fixed across chunks
    int qa = tid & 7;                 // float4 index within 32-k chunk
    int ra0 = tid >> 3;               // rows 0..63 (it0), +64 (it1)
    bool val0 = (row0 + ra0) < NN;
    bool val1 = (row0 + ra0 + 64) < NN;
    const float* Arow0 = A + (size_t)(row0 + ra0) * KDIM + qa * 4;
    const float* Arow1 = Arow0 + (size_t)64 * KDIM;
    const float* A2row0 = (PHASE == 1) ? (A2 + (size_t)(row0 + ra0) * KDIM + qa * 4) : nullptr;
    const float* A2row1 = (PHASE == 1) ? (A2row0 + (size_t)64 * KDIM) : nullptr;
    // B stage mapping: per thread 2 uint4 per split
    int qb = tid & 3;
    int nb0 = tid >> 2;               // n 0..127 (it0), +128 (it1)

    const int NCH = KDIM / 32;
    float4 ra[2], ra2[2];
    // preload chunk 0
    ra[0] = val0 ? *(const float4*)(Arow0) : make_float4(0, 0, 0, 0);
    ra[1] = val1 ? *(const float4*)(Arow1) : make_float4(0, 0, 0, 0);
    if (PHASE == 1) {
        ra2[0] = val0 ? *(const float4*)(A2row0) : make_float4(0, 0, 0, 0);
        ra2[1] = val1 ? *(const float4*)(A2row1) : make_float4(0, 0, 0, 0);
    }

#pragma unroll 1
    for (int ch = 0; ch < NCH; ch++) {
        int k0 = ch * 32;
        // transform + split + store A smem
#pragma unroll
        for (int it = 0; it < 2; it++) {
            float4 v;
            if (PHASE == 1) {
                v.x = 0.2375f * ra[it].x + 0.05f * ra2[it].x;
                v.y = 0.2375f * ra[it].y + 0.05f * ra2[it].y;
                v.z = 0.2375f * ra[it].z + 0.05f * ra2[it].z;
                v.w = 0.2375f * ra[it].w + 0.05f * ra2[it].w;
            } else {
                float4 s = *(const float4*)(bnA + k0 + qa * 4);
                float4 h = *(const float4*)(bnC + k0 + qa * 4);
                v.x = fmaxf(fmaf(ra[it].x, s.x, h.x), 0.f);
                v.y = fmaxf(fmaf(ra[it].y, s.y, h.y), 0.f);
                v.z = fmaxf(fmaf(ra[it].z, s.z, h.z), 0.f);
                v.w = fmaxf(fmaf(ra[it].w, s.w, h.w), 0.f);
            }
            bool valid = it ? val1 : val0;
            if (!valid) v = make_float4(0, 0, 0, 0);
            uint32_t h01, l01, h23, l23;
            split_pack(v.x, v.y, h01, l01);
            split_pack(v.z, v.w, h23, l23);
            int r = ra0 + it * 64;
            *(uint2*)&sAhi[r * LDS + qa * 4] = make_uint2(h01, h23);
            *(uint2*)&sAlo[r * LDS + qa * 4] = make_uint2(l01, l23);
        }
        // B direct global -> smem (weights are L2-hot)
#pragma unroll
        for (int it = 0; it < 2; it++) {
            int n = nb0 + it * 128;
            size_t goff = (size_t)n * KDIM + k0 + qb * 8;
            *(uint4*)&sBhi[n * LDS + qb * 8] = *(const uint4*)(Bhi + goff);
            *(uint4*)&sBlo[n * LDS + qb * 8] = *(const uint4*)(Blo + goff);
        }
        __syncthreads();
        // prefetch next A chunk into regs
        if (ch + 1 < NCH) {
            int kn = (ch + 1) * 32;
            ra[0] = val0 ? *(const float4*)(Arow0 + kn) : make_float4(0, 0, 0, 0);
            ra[1] = val1 ? *(const float4*)(Arow1 + kn) : make_float4(0, 0, 0, 0);
            if (PHASE == 1) {
                ra2[0] = val0 ? *(const float4*)(A2row0 + kn) : make_float4(0, 0, 0, 0);
                ra2[1] = val1 ? *(const float4*)(A2row1 + kn) : make_float4(0, 0, 0, 0);
            }
        }
        // compute: two k16 steps
#pragma unroll
        for (int ks = 0; ks < 2; ks++) {
            int kc = ks * 16;
            uint32_t ah[2][4], al[2][4];
#pragma unroll
            for (int mt = 0; mt < 2; mt++) {
                int r = warp_m * 32 + mt * 16 + (lane & 15);
                uint32_t off = (uint32_t)(r * LDS + kc + ((lane >> 4) << 3)) * 2;
                ldm_x4(ah[mt], aAhi + off);
                ldm_x4(al[mt], aAlo + off);
            }
#pragma unroll
            for (int nt = 0; nt < 8; nt++) {
                int n = warp_n * 64 + nt * 8 + (lane & 7);
                uint32_t off = (uint32_t)(n * LDS + kc + (((lane & 15) >> 3) << 3)) * 2;
                uint32_t bh[2], bl[2];
                ldm_x2(bh, aBhi + off);
                ldm_x2(bl, aBlo + off);
#pragma unroll
                for (int mt = 0; mt < 2; mt++) {
                    mma_bf16(c[mt][nt], ah[mt], bh);
                    mma_bf16(c[mt][nt], al[mt], bh);
                    mma_bf16(c[mt][nt], ah[mt], bl);
                }
            }
        }
        __syncthreads();
    }

    // ---- epilogue: store y + fused BN stats ----
    int colb = warp_n * 64 + ((lane & 3) << 1);
    int rb = row0 + warp_m * 32 + (lane >> 2);
#pragma unroll
    for (int mt = 0; mt < 2; mt++) {
        int gr = rb + mt * 16;
#pragma unroll
        for (int nt = 0; nt < 8; nt++) {
            int col = colb + nt * 8;
            if (gr < NN)
                *(float2*)(out + (size_t)gr * HH + col) = make_float2(c[mt][nt][0], c[mt][nt][1]);
            if (gr + 8 < NN)
                *(float2*)(out + (size_t)(gr + 8) * HH + col) = make_float2(c[mt][nt][2], c[mt][nt][3]);
        }
    }
#pragma unroll
    for (int nt = 0; nt < 8; nt++) {
        float s0 = c[0][nt][0] + c[0][nt][2] + c[1][nt][0] + c[1][nt][2];
        float s1 = c[0][nt][1] + c[0][nt][3] + c[1][nt][1] + c[1][nt][3];
        float q0 = c[0][nt][0] * c[0][nt][0] + c[0][nt][2] * c[0][nt][2] +
                   c[1][nt][0] * c[1][nt][0] + c[1][nt][2] * c[1][nt][2];
        float q1 = c[0][nt][1] * c[0][nt][1] + c[0][nt][3] * c[0][nt][3] +
                   c[1][nt][1] * c[1][nt][1] + c[1][nt][3] * c[1][nt][3];
#pragma unroll
        for (int m = 4; m < 32; m <<= 1) {
            s0 += __shfl_xor_sync(0xffffffffu, s0, m);
            s1 += __shfl_xor_sync(0xffffffffu, s1, m);
            q0 += __shfl_xor_sync(0xffffffffu, q0, m);
            q1 += __shfl_xor_sync(0xffffffffu, q1, m);
        }
        if (lane < 4) {
            int col = warp_n * 64 + nt * 8 + lane * 2;
            atomicAdd(&stats[col], s0);
            atomicAdd(&stats[col + 1], s1);
            atomicAdd(&stats[HH + col], q0);
            atomicAdd(&stats[HH + col + 1], q1);
        }
    }
}

// ---------------- GEMM3 (K=256, N=40): 256 threads, NTILE=64 ----------------
__global__ __launch_bounds__(256) void k_mma3(
    const float* __restrict__ A,
    const __nv_bfloat16* __restrict__ Bhi, const __nv_bfloat16* __restrict__ Blo,
    const float* __restrict__ bnA, const float* __restrict__ bnC,
    const float* __restrict__ bias, float* __restrict__ out)
{
    constexpr int KDIM = 256, NTILE = 64, LDS = 40;
    constexpr int WN = NTILE / 4, NT8 = WN / 8;   // 16, 2

    __shared__ __align__(16) __nv_bfloat16 sAhi[128 * LDS];
    __shared__ __align__(16) __nv_bfloat16 sAlo[128 * LDS];
    __shared__ __align__(16) __nv_bfloat16 sBhi[NTILE * LDS];
    __shared__ __align__(16) __nv_bfloat16 sBlo[NTILE * LDS];

    int tid = threadIdx.x, lane = tid & 31, wid = tid >> 5;
    int warp_m = wid & 1, warp_n = wid >> 1;
    int row0 = blockIdx.x * 128;

    float c[4][NT8][4];
#pragma unroll
    for (int mt = 0; mt < 4; mt++)
#pragma unroll
        for (int nt = 0; nt < NT8; nt++)
#pragma unroll
            for (int q = 0; q < 4; q++) c[mt][nt][q] = 0.0f;

    uint32_t aAhi = smem_u32(sAhi), aAlo = smem_u32(sAlo);
    uint32_t aBhi = smem_u32(sBhi), aBlo = smem_u32(sBlo);

#pragma unroll 1
    for (int ch = 0; ch < KDIM / 32; ch++) {
        int k0 = ch * 32;
#pragma unroll
        for (int it = 0; it < 4; it++) {
            int idx = tid + it * 256;
            int r = idx >> 3, q = idx & 7;
            int gi = row0 + r;
            float4 v = make_float4(0.f, 0.f, 0.f, 0.f);
            if (gi < NN) {
                float4 a = ((const float4*)(A + (size_t)gi * KDIM + k0))[q];
                int kc = k0 + q * 4;
                float4 s = *(const float4*)(bnA + kc);
                float4 h = *(const float4*)(bnC + kc);
                v.x = fmaxf(fmaf(a.x, s.x, h.x), 0.f);
                v.y = fmaxf(fmaf(a.y, s.y, h.y), 0.f);
                v.z = fmaxf(fmaf(a.z, s.z, h.z), 0.f);
                v.w = fmaxf(fmaf(a.w, s.w, h.w), 0.f);
            }
            uint32_t h01, l01, h23, l23;
            split_pack(v.x, v.y, h01, l01);
            split_pack(v.z, v.w, h23, l23);
            *(uint2*)&sAhi[r * LDS + q * 4] = make_uint2(h01, h23);
            *(uint2*)&sAlo[r * LDS + q * 4] = make_uint2(l01, l23);
        }
        {
            int idx = tid;                      // NTILE*4 = 256 uint4 per split
            int n = idx >> 2, q = idx & 3;
            size_t goff = (size_t)n * KDIM + k0 + q * 8;
            *(uint4*)&sBhi[n * LDS + q * 8] = *(const uint4*)(Bhi + goff);
            *(uint4*)&sBlo[n * LDS + q * 8] = *(const uint4*)(Blo + goff);
        }
        __syncthreads();
#pragma unroll
        for (int ks = 0; ks < 2; ks++) {
            int kc = ks * 16;
            uint32_t bh[NT8][2], bl[NT8][2];
#pragma unroll
            for (int nt = 0; nt < NT8; nt++) {
                int n = warp_n * WN + nt * 8 + (lane & 7);
                uint32_t off = (uint32_t)(n * LDS + kc + (((lane & 15) >> 3) << 3)) * 2;
                ldm_x2(bh[nt], aBhi + off);
                ldm_x2(bl[nt], aBlo + off);
            }
#pragma unroll
            for (int mt = 0; mt < 4; mt++) {
                int r = warp_m * 64 + mt * 16 + (lane & 15);
                uint32_t off = (uint32_t)(r * LDS + kc + ((lane >> 4) << 3)) * 2;
                uint32_t ah[4], al[4];
                ldm_x4(ah, aAhi + off);
                ldm_x4(al, aAlo + off);
#pragma unroll
                for (int nt = 0; nt < NT8; nt++) {
                    mma_bf16(c[mt][nt], ah, bh[nt]);
                    mma_bf16(c[mt][nt], al, bh[nt]);
                    mma_bf16(c[mt][nt], ah, bl[nt]);
                }
            }
        }
        __syncthreads();
    }

    int colbase = warp_n * WN + ((lane & 3) << 1);
    int rbase = row0 + warp_m * 64 + (lane >> 2);
#pragma unroll
    for (int mt = 0; mt < 4; mt++) {
        int r0g = rbase + mt * 16;
#pragma unroll
        for (int nt = 0; nt < NT8; nt++) {
            int col = colbase + nt * 8;
            if (col >= CC) continue;
            float bx = bias[col], by = bias[col + 1];
            if (r0g < NN)
                *(float2*)(out + (size_t)r0g * CC + col) =
                    make_float2(c[mt][nt][0] + bx, c[mt][nt][1] + by);
            if (r0g + 8 < NN)
                *(float2*)(out + (size_t)(r0g + 8) * CC + col) =
                    make_float2(c[mt][nt][2] + bx, c[mt][nt][3] + by);
        }
    }
}

__global__ void k_bnfin(const float* __restrict__ stats, const float* __restrict__ g,
                        const float* __restrict__ be, float* __restrict__ bnA,
                        float* __restrict__ bnC) {
    int col = threadIdx.x;
    if (col < HH) {
        float inv = 1.0f / (float)NN;
        float mean = stats[col] * inv;
        float var = stats[HH + col] * inv - mean * mean;
        float rstd = rsqrtf(var + BNEPS);
        float a = g[col] * rstd;
        bnA[col] = a;
        bnC[col] = be[col] - a * mean;
    }
}

// ---------------- launch ----------------
extern "C" void kernel_launch(void* const* d_in, const int* in_sizes, int n_in,
                              void* d_out, int out_size) {
    const float* feat = (const float*)d_in[0];
    const int*   src  = (const int*)d_in[1];
    const int*   dst  = (const int*)d_in[2];
    const float* W1   = (const float*)d_in[3];
    const float* g1   = (const float*)d_in[5];
    const float* be1  = (const float*)d_in[6];
    const float* W2   = (const float*)d_in[7];
    const float* g2   = (const float*)d_in[9];
    const float* be2  = (const float*)d_in[10];
    const float* W3   = (const float*)d_in[11];
    const float* b3   = (const float*)d_in[12];
    float* out = (float*)d_out;

    float *p_zA, *p_zB, *p_acc, *p_y1, *p_y2, *p_stats;
    float *p_bnA1, *p_bnC1, *p_bnA2, *p_bnC2;
    __nv_bfloat16 *p_w1h, *p_w1l, *p_w2h, *p_w2l, *p_w3h, *p_w3l;
    cudaGetSymbolAddress((void**)&p_zA, g_zA);
    cudaGetSymbolAddress((void**)&p_zB, g_zB);
    cudaGetSymbolAddress((void**)&p_acc, g_acc);
    cudaGetSymbolAddress((void**)&p_y1, g_y1);
    cudaGetSymbolAddress((void**)&p_y2, g_y2);
    cudaGetSymbolAddress((void**)&p_stats, g_stats);
    cudaGetSymbolAddress((void**)&p_bnA1, g_bnA1);
    cudaGetSymbolAddress((void**)&p_bnC1, g_bnC1);
    cudaGetSymbolAddress((void**)&p_bnA2, g_bnA2);
    cudaGetSymbolAddress((void**)&p_bnC2, g_bnC2);
    cudaGetSymbolAddress((void**)&p_w1h, g_w1h);
    cudaGetSymbolAddress((void**)&p_w1l, g_w1l);
    cudaGetSymbolAddress((void**)&p_w2h, g_w2h);
    cudaGetSymbolAddress((void**)&p_w2l, g_w2l);
    cudaGetSymbolAddress((void**)&p_w3h, g_w3h);
    cudaGetSymbolAddress((void**)&p_w3l, g_w3l);

    const int SMBIG = 61440;
    cudaFuncSetAttribute((const void*)k_mma_big<64, 1>,
                         cudaFuncAttributeMaxDynamicSharedMemorySize, SMBIG);
    cudaFuncSetAttribute((const void*)k_mma_big<256, 2>,
                         cudaFuncAttributeMaxDynamicSharedMemorySize, SMBIG);

    // CSR build
    k_init<<<(NN + 255) / 256, 256>>>();
    k_count<<<(EE + 255) / 256, 256>>>(dst);
    k_scan1<<<NB_SCAN, 1024>>>();
    k_scan2<<<1, 128>>>();
    k_scan3<<<NB_SCAN, 1024>>>();
    k_fill<<<(EE + 255) / 256, 256>>>(src, dst);

    // weight split/transpose
    k_wt<<<(HH * DD + 255) / 256, 256>>>(W1, p_w1h, p_w1l, DD, HH, HH);
    k_wt<<<(HH * HH + 255) / 256, 256>>>(W2, p_w2h, p_w2l, HH, HH, HH);
    k_wt<<<(64 * HH + 255) / 256, 256>>>(W3, p_w3h, p_w3l, HH, CC, 64);

    // propagation (prescale fused into first gather)
    int gblocks = (NN * 32 + 255) / 256;
    k_gather<1><<<gblocks, 256>>>(feat, p_zB, 1);
    k_gather<0><<<gblocks, 256>>>(p_zB, p_zA, 0);
    k_gather<0><<<gblocks, 256>>>(p_zA, p_zB, 0);
    k_gather<0><<<gblocks, 256>>>(p_zB, p_zA, 0);

    int mgrid = (NN + 127) / 128;  // 782
    k_mma_big<64, 1><<<mgrid, 512, SMBIG>>>(
        p_acc, feat, p_w1h, p_w1l, nullptr, nullptr, p_y1, p_stats);
    k_bnfin<<<1, 256>>>(p_stats, g1, be1, p_bnA1, p_bnC1);
    k_mma_big<256, 2><<<mgrid, 512, SMBIG>>>(
        p_y1, nullptr, p_w2h, p_w2l, p_bnA1, p_bnC1, p_y2, p_stats + 2 * HH);
    k_bnfin<<<1, 256>>>(p_stats + 2 * HH, g2, be2, p_bnA2, p_bnC2);
    k_mma3<<<mgrid, 256>>>(p_y2, p_w3h, p_w3l, p_bnA2, p_bnC2, b3, out);
}

// round 5
// speedup vs baseline: 1.6708x; 1.0526x over previous
#include <cuda_runtime.h>
#include <cuda_bf16.h>
#include <math.h>
#include <stdint.h>

#define NN 100000
#define EE 1250000
#define DD 64
#define HH 256
#define CC 40
#define BNEPS 1e-5f
#define NB_SCAN 98

// ---------------- device scratch ----------------
__device__ float g_z1[NN * DD];
__device__ float g_z2[NN * DD];
__device__ float g_z3[NN * DD];
__device__ float g_z4[NN * DD];
__device__ float g_norm[NN];
__device__ float g_sdeg[NN];
__device__ int   g_deg[NN];
__device__ int   g_off[NN + 1];
__device__ int   g_cursor[NN];
__device__ int   g_csr[EE];
__device__ int   g_bsum[NB_SCAN];
__device__ float g_y1[NN * HH];
__device__ float g_y2[NN * HH];
__device__ float g_stats[4 * HH];
__device__ float g_bnA1[HH], g_bnC1[HH], g_bnA2[HH], g_bnC2[HH];
__device__ __nv_bfloat16 g_w1h[HH * DD], g_w1l[HH * DD];
__device__ __nv_bfloat16 g_w2h[HH * HH], g_w2l[HH * HH];
__device__ __nv_bfloat16 g_w3h[64 * HH], g_w3l[64 * HH];

// ---------------- helpers ----------------
__device__ __forceinline__ uint32_t smem_u32(const void* p) {
    uint32_t a;
    asm("{ .reg .u64 t; cvta.to.shared.u64 t, %1; cvt.u32.u64 %0, t; }" : "=r"(a) : "l"(p));
    return a;
}
__device__ __forceinline__ void ldm_x4(uint32_t* r, uint32_t addr) {
    asm volatile("ldmatrix.sync.aligned.m8n8.x4.shared.b16 {%0,%1,%2,%3}, [%4];"
                 : "=r"(r[0]), "=r"(r[1]), "=r"(r[2]), "=r"(r[3]) : "r"(addr));
}
__device__ __forceinline__ void ldm_x2(uint32_t* r, uint32_t addr) {
    asm volatile("ldmatrix.sync.aligned.m8n8.x2.shared.b16 {%0,%1}, [%2];"
                 : "=r"(r[0]), "=r"(r[1]) : "r"(addr));
}
__device__ __forceinline__ void mma_bf16(float* c, const uint32_t* a, const uint32_t* b) {
    asm volatile(
        "mma.sync.aligned.m16n8k16.row.col.f32.bf16.bf16.f32 "
        "{%0,%1,%2,%3}, {%4,%5,%6,%7}, {%8,%9}, {%0,%1,%2,%3};"
        : "+f"(c[0]), "+f"(c[1]), "+f"(c[2]), "+f"(c[3])
        : "r"(a[0]), "r"(a[1]), "r"(a[2]), "r"(a[3]), "r"(b[0]), "r"(b[1]));
}
__device__ __forceinline__ void split_pack(float x, float y, uint32_t& hi, uint32_t& lo) {
    __nv_bfloat16 hx = __float2bfloat16(x), hy = __float2bfloat16(y);
    float rx = x - __bfloat162float(hx), ry = y - __bfloat162float(hy);
    __nv_bfloat16 lx = __float2bfloat16(rx), ly = __float2bfloat16(ry);
    hi = (uint32_t)__bfloat16_as_ushort(hx) | ((uint32_t)__bfloat16_as_ushort(hy) << 16);
    lo = (uint32_t)__bfloat16_as_ushort(lx) | ((uint32_t)__bfloat16_as_ushort(ly) << 16);
}
__device__ __forceinline__ void wsplit(const float* W, __nv_bfloat16* hi, __nv_bfloat16* lo,
                                       int idx, int K, int Nsrc) {
    int n = idx / K, k = idx - n * K;
    float v = (n < Nsrc) ? W[(size_t)k * Nsrc + n] : 0.0f;
    __nv_bfloat16 h = __float2bfloat16(v);
    hi[idx] = h;
    lo[idx] = __float2bfloat16(v - __bfloat162float(h));
}

// ---------------- prep: init + weight split (merged) ----------------
__global__ void k_prep(const float* __restrict__ W1, const float* __restrict__ W2,
                       const float* __restrict__ W3) {
    int i = blockIdx.x * blockDim.x + threadIdx.x;
    if (i < NN) g_deg[i] = 0;
    if (i < 4 * HH) g_stats[i] = 0.0f;
    if (i < HH * DD) wsplit(W1, g_w1h, g_w1l, i, DD, HH);
    else if (i < HH * DD + HH * HH) wsplit(W2, g_w2h, g_w2l, i - HH * DD, HH, HH);
    else if (i < HH * DD + HH * HH + 64 * HH) wsplit(W3, g_w3h, g_w3l, i - HH * DD - HH * HH, HH, CC);
}
__global__ void k_count(const int* __restrict__ dst) {
    int e = blockIdx.x * blockDim.x + threadIdx.x;
    if (e < EE) atomicAdd(&g_deg[dst[e]], 1);
}
__global__ void k_scan1() {
    __shared__ int s[1024];
    int t = threadIdx.x;
    int i = blockIdx.x * 1024 + t;
    int v = (i < NN) ? g_deg[i] : 0;
    s[t] = v;
    __syncthreads();
    for (int off = 1; off < 1024; off <<= 1) {
        int x = (t >= off) ? s[t - off] : 0;
        __syncthreads();
        s[t] += x;
        __syncthreads();
    }
    if (i < NN) g_off[i] = s[t] - v;
    if (t == 1023) g_bsum[blockIdx.x] = s[1023];
}
// scan3 with inline block-prefix of bsum (scan2 folded in)
__global__ void k_scan3() {
    __shared__ int sb[128];
    int t = threadIdx.x;
    if (t < 128) sb[t] = (t < NB_SCAN) ? g_bsum[t] : 0;
    __syncthreads();
    for (int off = 1; off < 128; off <<= 1) {
        int x = 0;
        if (t < 128 && t >= off) x = sb[t - off];
        __syncthreads();
        if (t < 128) sb[t] += x;
        __syncthreads();
    }
    int base = (blockIdx.x > 0) ? sb[blockIdx.x - 1] : 0;   // exclusive prefix
    int i = blockIdx.x * 1024 + t;
    if (i < NN) {
        int off = g_off[i] + base;
        g_off[i] = off;
        g_cursor[i] = off;
        int d = g_deg[i];
        int dc = (d > 0) ? d : 1;
        g_norm[i] = rsqrtf((float)dc);
        g_sdeg[i] = sqrtf((float)dc);
    }
    if (i == NN) g_off[NN] = EE;
}
__global__ void k_fill(const int* __restrict__ src, const int* __restrict__ dst) {
    int e = blockIdx.x * blockDim.x + threadIdx.x;
    if (e < EE) {
        int p = atomicAdd(&g_cursor[dst[e]], 1);
        g_csr[p] = src[e];
    }
}

// ---------------- propagation: z-only (z_r = norm^2 * sum_j z_{r-1}[j]) -------
template <int FIRST>
__global__ __launch_bounds__(256) void k_gather(const float* __restrict__ zin,
                                                float* __restrict__ zout) {
    int warp = (blockIdx.x * blockDim.x + threadIdx.x) >> 5;
    int lane = threadIdx.x & 31;
    if (warp >= NN) return;
    int beg = g_off[warp], end = g_off[warp + 1];
    const float2* z2 = (const float2*)zin;
    float ax = 0.f, ay = 0.f, bx = 0.f, by = 0.f;
    int e = beg;
    for (; e + 4 <= end; e += 4) {
        int j0 = g_csr[e], j1 = g_csr[e + 1], j2 = g_csr[e + 2], j3 = g_csr[e + 3];
        float2 v0 = z2[j0 * 32 + lane];
        float2 v1 = z2[j1 * 32 + lane];
        float2 v2 = z2[j2 * 32 + lane];
        float2 v3 = z2[j3 * 32 + lane];
        if (FIRST) {
            float n0 = g_norm[j0], n1 = g_norm[j1], n2 = g_norm[j2], n3 = g_norm[j3];
            ax = fmaf(n0, v0.x, ax); ay = fmaf(n0, v0.y, ay);
            bx = fmaf(n1, v1.x, bx); by = fmaf(n1, v1.y, by);
            ax = fmaf(n2, v2.x, ax); ay = fmaf(n2, v2.y, ay);
            bx = fmaf(n3, v3.x, bx); by = fmaf(n3, v3.y, by);
        } else {
            ax += v0.x; ay += v0.y; bx += v1.x; by += v1.y;
            ax += v2.x; ay += v2.y; bx += v3.x; by += v3.y;
        }
    }
    for (; e < end; e++) {
        int j = g_csr[e];
        float2 v = z2[j * 32 + lane];
        if (FIRST) {
            float nj = g_norm[j];
            ax = fmaf(nj, v.x, ax); ay = fmaf(nj, v.y, ay);
        } else {
            ax += v.x; ay += v.y;
        }
    }
    ax += bx; ay += by;
    float ni = g_norm[warp];
    float n2s = ni * ni;
    ((float2*)zout)[warp * 32 + lane] = make_float2(n2s * ax, n2s * ay);
}

// ---------------- GEMM1: 128x256, K=64; A = 0.2375*sdeg*(z1+z2+z3+z4)+0.05*feat
__global__ __launch_bounds__(512, 1) void k_mma1(
    const float* __restrict__ Z1, const float* __restrict__ Z2,
    const float* __restrict__ Z3, const float* __restrict__ Z4,
    const float* __restrict__ feat,
    const __nv_bfloat16* __restrict__ Bhi, const __nv_bfloat16* __restrict__ Blo,
    float* __restrict__ out, float* __restrict__ stats)
{
    constexpr int KDIM = DD, LDS = 40;
    extern __shared__ __align__(16) char smem[];
    __nv_bfloat16* sAhi = (__nv_bfloat16*)(smem);
    __nv_bfloat16* sAlo = (__nv_bfloat16*)(smem + 10240);
    __nv_bfloat16* sBhi = (__nv_bfloat16*)(smem + 20480);
    __nv_bfloat16* sBlo = (__nv_bfloat16*)(smem + 40960);

    int tid = threadIdx.x, lane = tid & 31, wid = tid >> 5;
    int warp_m = wid & 3, warp_n = wid >> 2;
    int row0 = blockIdx.x * 128;

    float c[2][8][4];
#pragma unroll
    for (int mt = 0; mt < 2; mt++)
#pragma unroll
        for (int nt = 0; nt < 8; nt++)
#pragma unroll
            for (int q = 0; q < 4; q++) c[mt][nt][q] = 0.0f;

    uint32_t aAhi = smem_u32(sAhi), aAlo = smem_u32(sAlo);
    uint32_t aBhi = smem_u32(sBhi), aBlo = smem_u32(sBlo);

    int qa = tid & 7, ra0 = tid >> 3;
    int qb = tid & 3, nb0 = tid >> 2;
    bool val0 = (row0 + ra0) < NN;
    bool val1 = (row0 + ra0 + 64) < NN;
    float sd0 = val0 ? (0.2375f * g_sdeg[row0 + ra0]) : 0.f;
    float sd1 = val1 ? (0.2375f * g_sdeg[row0 + ra0 + 64]) : 0.f;

#pragma unroll 1
    for (int ch = 0; ch < KDIM / 32; ch++) {
        int k0 = ch * 32;
#pragma unroll
        for (int it = 0; it < 2; it++) {
            int r = ra0 + it * 64;
            bool valid = it ? val1 : val0;
            float sd = it ? sd1 : sd0;
            float4 v = make_float4(0, 0, 0, 0);
            if (valid) {
                size_t o = (size_t)(row0 + r) * KDIM + k0 + qa * 4;
                float4 z1 = *(const float4*)(Z1 + o);
                float4 z2 = *(const float4*)(Z2 + o);
                float4 z3 = *(const float4*)(Z3 + o);
                float4 z4 = *(const float4*)(Z4 + o);
                float4 f = *(const float4*)(feat + o);
                v.x = sd * (z1.x + z2.x + z3.x + z4.x) + 0.05f * f.x;
                v.y = sd * (z1.y + z2.y + z3.y + z4.y) + 0.05f * f.y;
                v.z = sd * (z1.z + z2.z + z3.z + z4.z) + 0.05f * f.z;
                v.w = sd * (z1.w + z2.w + z3.w + z4.w) + 0.05f * f.w;
            }
            uint32_t h01, l01, h23, l23;
            split_pack(v.x, v.y, h01, l01);
            split_pack(v.z, v.w, h23, l23);
            *(uint2*)&sAhi[r * LDS + qa * 4] = make_uint2(h01, h23);
            *(uint2*)&sAlo[r * LDS + qa * 4] = make_uint2(l01, l23);
        }
#pragma unroll
        for (int it = 0; it < 2; it++) {
            int n = nb0 + it * 128;
            size_t goff = (size_t)n * KDIM + k0 + qb * 8;
            *(uint4*)&sBhi[n * LDS + qb * 8] = *(const uint4*)(Bhi + goff);
            *(uint4*)&sBlo[n * LDS + qb * 8] = *(const uint4*)(Blo + goff);
        }
        __syncthreads();
#pragma unroll
        for (int ks = 0; ks < 2; ks++) {
            int kc = ks * 16;
            uint32_t ah[2][4], al[2][4];
#pragma unroll
            for (int mt = 0; mt < 2; mt++) {
                int r = warp_m * 32 + mt * 16 + (lane & 15);
                uint32_t off = (uint32_t)(r * LDS + kc + ((lane >> 4) << 3)) * 2;
                ldm_x4(ah[mt], aAhi + off);
                ldm_x4(al[mt], aAlo + off);
            }
#pragma unroll
            for (int nt = 0; nt < 8; nt++) {
                int n = warp_n * 64 + nt * 8 + (lane & 7);
                uint32_t off = (uint32_t)(n * LDS + kc + (((lane & 15) >> 3) << 3)) * 2;
                uint32_t bh[2], bl[2];
                ldm_x2(bh, aBhi + off);
                ldm_x2(bl, aBlo + off);
#pragma unroll
                for (int mt = 0; mt < 2; mt++) {
                    mma_bf16(c[mt][nt], ah[mt], bh);
                    mma_bf16(c[mt][nt], al[mt], bh);
                    mma_bf16(c[mt][nt], ah[mt], bl);
                }
            }
        }
        __syncthreads();
    }
    // epilogue: store + fused stats
    int colb = warp_n * 64 + ((lane & 3) << 1);
    int rb = row0 + warp_m * 32 + (lane >> 2);
#pragma unroll
    for (int mt = 0; mt < 2; mt++) {
        int gr = rb + mt * 16;
#pragma unroll
        for (int nt = 0; nt < 8; nt++) {
            int col = colb + nt * 8;
            if (gr < NN)
                *(float2*)(out + (size_t)gr * HH + col) = make_float2(c[mt][nt][0], c[mt][nt][1]);
            if (gr + 8 < NN)
                *(float2*)(out + (size_t)(gr + 8) * HH + col) = make_float2(c[mt][nt][2], c[mt][nt][3]);
        }
    }
#pragma unroll
    for (int nt = 0; nt < 8; nt++) {
        float s0 = c[0][nt][0] + c[0][nt][2] + c[1][nt][0] + c[1][nt][2];
        float s1 = c[0][nt][1] + c[0][nt][3] + c[1][nt][1] + c[1][nt][3];
        float q0 = c[0][nt][0] * c[0][nt][0] + c[0][nt][2] * c[0][nt][2] +
                   c[1][nt][0] * c[1][nt][0] + c[1][nt][2] * c[1][nt][2];
        float q1 = c[0][nt][1] * c[0][nt][1] + c[0][nt][3] * c[0][nt][3] +
                   c[1][nt][1] * c[1][nt][1] + c[1][nt][3] * c[1][nt][3];
#pragma unroll
        for (int m = 4; m < 32; m <<= 1) {
            s0 += __shfl_xor_sync(0xffffffffu, s0, m);
            s1 += __shfl_xor_sync(0xffffffffu, s1, m);
            q0 += __shfl_xor_sync(0xffffffffu, q0, m);
            q1 += __shfl_xor_sync(0xffffffffu, q1, m);
        }
        if (lane < 4) {
            int col = warp_n * 64 + nt * 8 + lane * 2;
            atomicAdd(&stats[col], s0);
            atomicAdd(&stats[col + 1], s1);
            atomicAdd(&stats[HH + col], q0);
            atomicAdd(&stats[HH + col + 1], q1);
        }
    }
}

// ---------------- GEMM2: 128x256, K=256; A = relu(y1*bnA+bnC); A+B reg pipeline
__global__ __launch_bounds__(512, 1) void k_mma2(
    const float* __restrict__ A,
    const __nv_bfloat16* __restrict__ Bhi, const __nv_bfloat16* __restrict__ Blo,
    const float* __restrict__ bnA, const float* __restrict__ bnC,
    float* __restrict__ out, float* __restrict__ stats)
{
    constexpr int KDIM = HH, LDS = 40;
    extern __shared__ __align__(16) char smem[];
    __nv_bfloat16* sAhi = (__nv_bfloat16*)(smem);
    __nv_bfloat16* sAlo = (__nv_bfloat16*)(smem + 10240);
    __nv_bfloat16* sBhi = (__nv_bfloat16*)(smem + 20480);
    __nv_bfloat16* sBlo = (__nv_bfloat16*)(smem + 40960);

    int tid = threadIdx.x, lane = tid & 31, wid = tid >> 5;
    int warp_m = wid & 3, warp_n = wid >> 2;
    int row0 = blockIdx.x * 128;

    float c[2][8][4];
#pragma unroll
    for (int mt = 0; mt < 2; mt++)
#pragma unroll
        for (int nt = 0; nt < 8; nt++)
#pragma unroll
            for (int q = 0; q < 4; q++) c[mt][nt][q] = 0.0f;

    uint32_t aAhi = smem_u32(sAhi), aAlo = smem_u32(sAlo);
    uint32_t aBhi = smem_u32(sBhi), aBlo = smem_u32(sBlo);

    int qa = tid & 7, ra0 = tid >> 3;
    int qb = tid & 3, nb0 = tid >> 2;
    bool val0 = (row0 + ra0) < NN;
    bool val1 = (row0 + ra0 + 64) < NN;
    const float* Arow0 = A + (size_t)(row0 + ra0) * KDIM + qa * 4;
    const float* Arow1 = Arow0 + (size_t)64 * KDIM;
    const __nv_bfloat16* B0h = Bhi + (size_t)nb0 * KDIM + qb * 8;
    const __nv_bfloat16* B1h = B0h + (size_t)128 * KDIM;
    const __nv_bfloat16* B0l = Blo + (size_t)nb0 * KDIM + qb * 8;
    const __nv_bfloat16* B1l = B0l + (size_t)128 * KDIM;

    const int NCH = KDIM / 32;
    float4 ra[2];
    uint4 rbh[2], rbl[2];
    ra[0] = val0 ? *(const float4*)(Arow0) : make_float4(0, 0, 0, 0);
    ra[1] = val1 ? *(const float4*)(Arow1) : make_float4(0, 0, 0, 0);
    rbh[0] = *(const uint4*)(B0h); rbh[1] = *(const uint4*)(B1h);
    rbl[0] = *(const uint4*)(B0l); rbl[1] = *(const uint4*)(B1l);

#pragma unroll 1
    for (int ch = 0; ch < NCH; ch++) {
        int k0 = ch * 32;
        float4 s = *(const float4*)(bnA + k0 + qa * 4);
        float4 h = *(const float4*)(bnC + k0 + qa * 4);
#pragma unroll
        for (int it = 0; it < 2; it++) {
            float4 v;
            v.x = fmaxf(fmaf(ra[it].x, s.x, h.x), 0.f);
            v.y = fmaxf(fmaf(ra[it].y, s.y, h.y), 0.f);
            v.z = fmaxf(fmaf(ra[it].z, s.z, h.z), 0.f);
            v.w = fmaxf(fmaf(ra[it].w, s.w, h.w), 0.f);
            if (!(it ? val1 : val0)) v = make_float4(0, 0, 0, 0);
            uint32_t h01, l01, h23, l23;
            split_pack(v.x, v.y, h01, l01);
            split_pack(v.z, v.w, h23, l23);
            int r = ra0 + it * 64;
            *(uint2*)&sAhi[r * LDS + qa * 4] = make_uint2(h01, h23);
            *(uint2*)&sAlo[r * LDS + qa * 4] = make_uint2(l01, l23);
        }
#pragma unroll
        for (int it = 0; it < 2; it++) {
            int n = nb0 + it * 128;
            *(uint4*)&sBhi[n * LDS + qb * 8] = rbh[it];
            *(uint4*)&sBlo[n * LDS + qb * 8] = rbl[it];
        }
        __syncthreads();
        if (ch + 1 < NCH) {
            int kn = (ch + 1) * 32;
            ra[0] = val0 ? *(const float4*)(Arow0 + kn) : make_float4(0, 0, 0, 0);
            ra[1] = val1 ? *(const float4*)(Arow1 + kn) : make_float4(0, 0, 0, 0);
            rbh[0] = *(const uint4*)(B0h + kn); rbh[1] = *(const uint4*)(B1h + kn);
            rbl[0] = *(const uint4*)(B0l + kn); rbl[1] = *(const uint4*)(B1l + kn);
        }
#pragma unroll
        for (int ks = 0; ks < 2; ks++) {
            int kc = ks * 16;
            uint32_t ah[2][4], al[2][4];
#pragma unroll
            for (int mt = 0; mt < 2; mt++) {
                int r = warp_m * 32 + mt * 16 + (lane & 15);
                uint32_t off = (uint32_t)(r * LDS + kc + ((lane >> 4) << 3)) * 2;
                ldm_x4(ah[mt], aAhi + off);
                ldm_x4(al[mt], aAlo + off);
            }
#pragma unroll
            for (int nt = 0; nt < 8; nt++) {
                int n = warp_n * 64 + nt * 8 + (lane & 7);
                uint32_t off = (uint32_t)(n * LDS + kc + (((lane & 15) >> 3) << 3)) * 2;
                uint32_t bh[2], bl[2];
                ldm_x2(bh, aBhi + off);
                ldm_x2(bl, aBlo + off);
#pragma unroll
                for (int mt = 0; mt < 2; mt++) {
                    mma_bf16(c[mt][nt], ah[mt], bh);
                    mma_bf16(c[mt][nt], al[mt], bh);
                    mma_bf16(c[mt][nt], ah[mt], bl);
                }
            }
        }
        __syncthreads();
    }
    // epilogue
    int colb = warp_n * 64 + ((lane & 3) << 1);
    int rb = row0 + warp_m * 32 + (lane >> 2);
#pragma unroll
    for (int mt = 0; mt < 2; mt++) {
        int gr = rb + mt * 16;
#pragma unroll
        for (int nt = 0; nt < 8; nt++) {
            int col = colb + nt * 8;
            if (gr < NN)
                *(float2*)(out + (size_t)gr * HH + col) = make_float2(c[mt][nt][0], c[mt][nt][1]);
            if (gr + 8 < NN)
                *(float2*)(out + (size_t)(gr + 8) * HH + col) = make_float2(c[mt][nt][2], c[mt][nt][3]);
        }
    }
#pragma unroll
    for (int nt = 0; nt < 8; nt++) {
        float s0 = c[0][nt][0] + c[0][nt][2] + c[1][nt][0] + c[1][nt][2];
        float s1 = c[0][nt][1] + c[0][nt][3] + c[1][nt][1] + c[1][nt][3];
        float q0 = c[0][nt][0] * c[0][nt][0] + c[0][nt][2] * c[0][nt][2] +
                   c[1][nt][0] * c[1][nt][0] + c[1][nt][2] * c[1][nt][2];
        float q1 = c[0][nt][1] * c[0][nt][1] + c[0][nt][3] * c[0][nt][3] +
                   c[1][nt][1] * c[1][nt][1] + c[1][nt][3] * c[1][nt][3];
#pragma unroll
        for (int m = 4; m < 32; m <<= 1) {
            s0 += __shfl_xor_sync(0xffffffffu, s0, m);
            s1 += __shfl_xor_sync(0xffffffffu, s1, m);
            q0 += __shfl_xor_sync(0xffffffffu, q0, m);
            q1 += __shfl_xor_sync(0xffffffffu, q1, m);
        }
        if (lane < 4) {
            int col = warp_n * 64 + nt * 8 + lane * 2;
            atomicAdd(&stats[col], s0);
            atomicAdd(&stats[col + 1], s1);
            atomicAdd(&stats[HH + col], q0);
            atomicAdd(&stats[HH + col + 1], q1);
        }
    }
}

// ---------------- GEMM3 (K=256, N=40) ----------------
__global__ __launch_bounds__(256) void k_mma3(
    const float* __restrict__ A,
    const __nv_bfloat16* __restrict__ Bhi, const __nv_bfloat16* __restrict__ Blo,
    const float* __restrict__ bnA, const float* __restrict__ bnC,
    const float* __restrict__ bias, float* __restrict__ out)
{
    constexpr int KDIM = 256, NTILE = 64, LDS = 40;
    constexpr int WN = NTILE / 4, NT8 = WN / 8;

    __shared__ __align__(16) __nv_bfloat16 sAhi[128 * LDS];
    __shared__ __align__(16) __nv_bfloat16 sAlo[128 * LDS];
    __shared__ __align__(16) __nv_bfloat16 sBhi[NTILE * LDS];
    __shared__ __align__(16) __nv_bfloat16 sBlo[NTILE * LDS];

    int tid = threadIdx.x, lane = tid & 31, wid = tid >> 5;
    int warp_m = wid & 1, warp_n = wid >> 1;
    int row0 = blockIdx.x * 128;

    float c[4][NT8][4];
#pragma unroll
    for (int mt = 0; mt < 4; mt++)
#pragma unroll
        for (int nt = 0; nt < NT8; nt++)
#pragma unroll
            for (int q = 0; q < 4; q++) c[mt][nt][q] = 0.0f;

    uint32_t aAhi = smem_u32(sAhi), aAlo = smem_u32(sAlo);
    uint32_t aBhi = smem_u32(sBhi), aBlo = smem_u32(sBlo);

#pragma unroll 1
    for (int ch = 0; ch < KDIM / 32; ch++) {
        int k0 = ch * 32;
#pragma unroll
        for (int it = 0; it < 4; it++) {
            int idx = tid + it * 256;
            int r = idx >> 3, q = idx & 7;
            int gi = row0 + r;
            float4 v = make_float4(0.f, 0.f, 0.f, 0.f);
            if (gi < NN) {
                float4 a = ((const float4*)(A + (size_t)gi * KDIM + k0))[q];
                int kc = k0 + q * 4;
                float4 s = *(const float4*)(bnA + kc);
                float4 h = *(const float4*)(bnC + kc);
                v.x = fmaxf(fmaf(a.x, s.x, h.x), 0.f);
                v.y = fmaxf(fmaf(a.y, s.y, h.y), 0.f);
                v.z = fmaxf(fmaf(a.z, s.z, h.z), 0.f);
                v.w = fmaxf(fmaf(a.w, s.w, h.w), 0.f);
            }
            uint32_t h01, l01, h23, l23;
            split_pack(v.x, v.y, h01, l01);
            split_pack(v.z, v.w, h23, l23);
            *(uint2*)&sAhi[r * LDS + q * 4] = make_uint2(h01, h23);
            *(uint2*)&sAlo[r * LDS + q * 4] = make_uint2(l01, l23);
        }
        {
            int n = tid >> 2, q = tid & 3;
            size_t goff = (size_t)n * KDIM + k0 + q * 8;
            *(uint4*)&sBhi[n * LDS + q * 8] = *(const uint4*)(Bhi + goff);
            *(uint4*)&sBlo[n * LDS + q * 8] = *(const uint4*)(Blo + goff);
        }
        __syncthreads();
#pragma unroll
        for (int ks = 0; ks < 2; ks++) {
            int kc = ks * 16;
            uint32_t bh[NT8][2], bl[NT8][2];
#pragma unroll
            for (int nt = 0; nt < NT8; nt++) {
                int n = warp_n * WN + nt * 8 + (lane & 7);
                uint32_t off = (uint32_t)(n * LDS + kc + (((lane & 15) >> 3) << 3)) * 2;
                ldm_x2(bh[nt], aBhi + off);
                ldm_x2(bl[nt], aBlo + off);
            }
#pragma unroll
            for (int mt = 0; mt < 4; mt++) {
                int r = warp_m * 64 + mt * 16 + (lane & 15);
                uint32_t off = (uint32_t)(r * LDS + kc + ((lane >> 4) << 3)) * 2;
                uint32_t ah[4], al[4];
                ldm_x4(ah, aAhi + off);
                ldm_x4(al, aAlo + off);
#pragma unroll
                for (int nt = 0; nt < NT8; nt++) {
                    mma_bf16(c[mt][nt], ah, bh[nt]);
                    mma_bf16(c[mt][nt], al, bh[nt]);
                    mma_bf16(c[mt][nt], ah, bl[nt]);
                }
            }
        }
        __syncthreads();
    }

    int colbase = warp_n * WN + ((lane & 3) << 1);
    int rbase = row0 + warp_m * 64 + (lane >> 2);
#pragma unroll
    for (int mt = 0; mt < 4; mt++) {
        int r0g = rbase + mt * 16;
#pragma unroll
        for (int nt = 0; nt < NT8; nt++) {
            int col = colbase + nt * 8;
            if (col >= CC) continue;
            float bx = bias[col], by = bias[col + 1];
            if (r0g < NN)
                *(float2*)(out + (size_t)r0g * CC + col) =
                    make_float2(c[mt][nt][0] + bx, c[mt][nt][1] + by);
            if (r0g + 8 < NN)
                *(float2*)(out + (size_t)(r0g + 8) * CC + col) =
                    make_float2(c[mt][nt][2] + bx, c[mt][nt][3] + by);
        }
    }
}

__global__ void k_bnfin(const float* __restrict__ stats, const float* __restrict__ g,
                        const float* __restrict__ be, float* __restrict__ bnA,
                        float* __restrict__ bnC) {
    int col = threadIdx.x;
    if (col < HH) {
        float inv = 1.0f / (float)NN;
        float mean = stats[col] * inv;
        float var = stats[HH + col] * inv - mean * mean;
        float rstd = rsqrtf(var + BNEPS);
        float a = g[col] * rstd;
        bnA[col] = a;
        bnC[col] = be[col] - a * mean;
    }
}

// ---------------- launch ----------------
extern "C" void kernel_launch(void* const* d_in, const int* in_sizes, int n_in,
                              void* d_out, int out_size) {
    const float* feat = (const float*)d_in[0];
    const int*   src  = (const int*)d_in[1];
    const int*   dst  = (const int*)d_in[2];
    const float* W1   = (const float*)d_in[3];
    const float* g1   = (const float*)d_in[5];
    const float* be1  = (const float*)d_in[6];
    const float* W2   = (const float*)d_in[7];
    const float* g2   = (const float*)d_in[9];
    const float* be2  = (const float*)d_in[10];
    const float* W3   = (const float*)d_in[11];
    const float* b3   = (const float*)d_in[12];
    float* out = (float*)d_out;

    float *p_z1, *p_z2, *p_z3, *p_z4, *p_y1, *p_y2, *p_stats;
    float *p_bnA1, *p_bnC1, *p_bnA2, *p_bnC2;
    __nv_bfloat16 *p_w1h, *p_w1l, *p_w2h, *p_w2l, *p_w3h, *p_w3l;
    cudaGetSymbolAddress((void**)&p_z1, g_z1);
    cudaGetSymbolAddress((void**)&p_z2, g_z2);
    cudaGetSymbolAddress((void**)&p_z3, g_z3);
    cudaGetSymbolAddress((void**)&p_z4, g_z4);
    cudaGetSymbolAddress((void**)&p_y1, g_y1);
    cudaGetSymbolAddress((void**)&p_y2, g_y2);
    cudaGetSymbolAddress((void**)&p_stats, g_stats);
    cudaGetSymbolAddress((void**)&p_bnA1, g_bnA1);
    cudaGetSymbolAddress((void**)&p_bnC1, g_bnC1);
    cudaGetSymbolAddress((void**)&p_bnA2, g_bnA2);
    cudaGetSymbolAddress((void**)&p_bnC2, g_bnC2);
    cudaGetSymbolAddress((void**)&p_w1h, g_w1h);
    cudaGetSymbolAddress((void**)&p_w1l, g_w1l);
    cudaGetSymbolAddress((void**)&p_w2h, g_w2h);
    cudaGetSymbolAddress((void**)&p_w2l, g_w2l);
    cudaGetSymbolAddress((void**)&p_w3h, g_w3h);
    cudaGetSymbolAddress((void**)&p_w3l, g_w3l);

    const int SMBIG = 61440;
    cudaFuncSetAttribute((const void*)k_mma1,
                         cudaFuncAttributeMaxDynamicSharedMemorySize, SMBIG);
    cudaFuncSetAttribute((const void*)k_mma2,
                         cudaFuncAttributeMaxDynamicSharedMemorySize, SMBIG);

    // prep + CSR
    k_prep<<<(NN + 255) / 256, 256>>>(W1, W2, W3);
    k_count<<<(EE + 255) / 256, 256>>>(dst);
    k_scan1<<<NB_SCAN, 1024>>>();
    k_scan3<<<NB_SCAN, 1024>>>();
    k_fill<<<(EE + 255) / 256, 256>>>(src, dst);

    // propagation (z-only)
    int gblocks = (NN * 32 + 255) / 256;
    k_gather<1><<<gblocks, 256>>>(feat, p_z1);
    k_gather<0><<<gblocks, 256>>>(p_z1, p_z2);
    k_gather<0><<<gblocks, 256>>>(p_z2, p_z3);
    k_gather<0><<<gblocks, 256>>>(p_z3, p_z4);

    int mgrid = (NN + 127) / 128;
    k_mma1<<<mgrid, 512, SMBIG>>>(p_z1, p_z2, p_z3, p_z4, feat,
                                  p_w1h, p_w1l, p_y1, p_stats);
    k_bnfin<<<1, 256>>>(p_stats, g1, be1, p_bnA1, p_bnC1);
    k_mma2<<<mgrid, 512, SMBIG>>>(p_y1, p_w2h, p_w2l, p_bnA1, p_bnC1,
                                  p_y2, p_stats + 2 * HH);
    k_bnfin<<<1, 256>>>(p_stats + 2 * HH, g2, be2, p_bnA2, p_bnC2);
    k_mma3<<<mgrid, 256>>>(p_y2, p_w3h, p_w3l, p_bnA2, p_bnC2, b3, out);
}

// round 6
// speedup vs baseline: 1.6825x; 1.0070x over previous
#include <cuda_runtime.h>
#include <cuda_bf16.h>
#include <math.h>
#include <stdint.h>

#define NN 100000
#define EE 1250000
#define DD 64
#define HH 256
#define CC 40
#define BNEPS 1e-5f
#define NB_SCAN 98

// ---------------- device scratch ----------------
__device__ float g_z1[NN * DD];
__device__ float g_z2[NN * DD];
__device__ float g_z3[NN * DD];
__device__ float g_z4[NN * DD];
__device__ float g_norm[NN];
__device__ float g_sdeg[NN];
__device__ int   g_deg[NN];
__device__ int   g_off[NN + 1];
__device__ int   g_cursor[NN];
__device__ int   g_csr[EE];
__device__ int   g_bsum[NB_SCAN];
__device__ float g_y1[NN * HH];
__device__ float g_y2[NN * HH];
__device__ float g_stats[4 * HH];
__device__ float g_bnA1[HH], g_bnC1[HH], g_bnA2[HH], g_bnC2[HH];
__device__ __nv_bfloat16 g_w1h[HH * DD], g_w1l[HH * DD];
__device__ __nv_bfloat16 g_w2h[HH * HH], g_w2l[HH * HH];
__device__ __nv_bfloat16 g_w3h[64 * HH], g_w3l[64 * HH];

// ---------------- helpers ----------------
__device__ __forceinline__ uint32_t smem_u32(const void* p) {
    uint32_t a;
    asm("{ .reg .u64 t; cvta.to.shared.u64 t, %1; cvt.u32.u64 %0, t; }" : "=r"(a) : "l"(p));
    return a;
}
__device__ __forceinline__ void ldm_x4(uint32_t* r, uint32_t addr) {
    asm volatile("ldmatrix.sync.aligned.m8n8.x4.shared.b16 {%0,%1,%2,%3}, [%4];"
                 : "=r"(r[0]), "=r"(r[1]), "=r"(r[2]), "=r"(r[3]) : "r"(addr));
}
__device__ __forceinline__ void ldm_x2(uint32_t* r, uint32_t addr) {
    asm volatile("ldmatrix.sync.aligned.m8n8.x2.shared.b16 {%0,%1}, [%2];"
                 : "=r"(r[0]), "=r"(r[1]) : "r"(addr));
}
__device__ __forceinline__ void mma_bf16(float* c, const uint32_t* a, const uint32_t* b) {
    asm volatile(
        "mma.sync.aligned.m16n8k16.row.col.f32.bf16.bf16.f32 "
        "{%0,%1,%2,%3}, {%4,%5,%6,%7}, {%8,%9}, {%0,%1,%2,%3};"
        : "+f"(c[0]), "+f"(c[1]), "+f"(c[2]), "+f"(c[3])
        : "r"(a[0]), "r"(a[1]), "r"(a[2]), "r"(a[3]), "r"(b[0]), "r"(b[1]));
}
__device__ __forceinline__ void split_pack(float x, float y, uint32_t& hi, uint32_t& lo) {
    __nv_bfloat16 hx = __float2bfloat16(x), hy = __float2bfloat16(y);
    float rx = x - __bfloat162float(hx), ry = y - __bfloat162float(hy);
    __nv_bfloat16 lx = __float2bfloat16(rx), ly = __float2bfloat16(ry);
    hi = (uint32_t)__bfloat16_as_ushort(hx) | ((uint32_t)__bfloat16_as_ushort(hy) << 16);
    lo = (uint32_t)__bfloat16_as_ushort(lx) | ((uint32_t)__bfloat16_as_ushort(ly) << 16);
}
__device__ __forceinline__ void wsplit(const float* W, __nv_bfloat16* hi, __nv_bfloat16* lo,
                                       int idx, int K, int Nsrc) {
    int n = idx / K, k = idx - n * K;
    float v = (n < Nsrc) ? W[(size_t)k * Nsrc + n] : 0.0f;
    __nv_bfloat16 h = __float2bfloat16(v);
    hi[idx] = h;
    lo[idx] = __float2bfloat16(v - __bfloat162float(h));
}

// ---------------- prep ----------------
__global__ void k_prep(const float* __restrict__ W1, const float* __restrict__ W2,
                       const float* __restrict__ W3) {
    int i = blockIdx.x * blockDim.x + threadIdx.x;
    if (i < NN) g_deg[i] = 0;
    if (i < 4 * HH) g_stats[i] = 0.0f;
    if (i < HH * DD) wsplit(W1, g_w1h, g_w1l, i, DD, HH);
    else if (i < HH * DD + HH * HH) wsplit(W2, g_w2h, g_w2l, i - HH * DD, HH, HH);
    else if (i < HH * DD + HH * HH + 64 * HH) wsplit(W3, g_w3h, g_w3l, i - HH * DD - HH * HH, HH, CC);
}
__global__ void k_count(const int* __restrict__ dst) {
    int e = blockIdx.x * blockDim.x + threadIdx.x;
    if (e < EE) atomicAdd(&g_deg[dst[e]], 1);
}
__global__ void k_scan1() {
    __shared__ int s[1024];
    int t = threadIdx.x;
    int i = blockIdx.x * 1024 + t;
    int v = (i < NN) ? g_deg[i] : 0;
    s[t] = v;
    __syncthreads();
    for (int off = 1; off < 1024; off <<= 1) {
        int x = (t >= off) ? s[t - off] : 0;
        __syncthreads();
        s[t] += x;
        __syncthreads();
    }
    if (i < NN) g_off[i] = s[t] - v;
    if (t == 1023) g_bsum[blockIdx.x] = s[1023];
}
__global__ void k_scan3() {
    __shared__ int sb[128];
    int t = threadIdx.x;
    if (t < 128) sb[t] = (t < NB_SCAN) ? g_bsum[t] : 0;
    __syncthreads();
    for (int off = 1; off < 128; off <<= 1) {
        int x = 0;
        if (t < 128 && t >= off) x = sb[t - off];
        __syncthreads();
        if (t < 128) sb[t] += x;
        __syncthreads();
    }
    int base = (blockIdx.x > 0) ? sb[blockIdx.x - 1] : 0;
    int i = blockIdx.x * 1024 + t;
    if (i < NN) {
        int off = g_off[i] + base;
        g_off[i] = off;
        g_cursor[i] = off;
        int d = g_deg[i];
        int dc = (d > 0) ? d : 1;
        g_norm[i] = rsqrtf((float)dc);
        g_sdeg[i] = sqrtf((float)dc);
    }
    if (i == NN) g_off[NN] = EE;
}
__global__ void k_fill(const int* __restrict__ src, const int* __restrict__ dst) {
    int e = blockIdx.x * blockDim.x + threadIdx.x;
    if (e < EE) {
        int p = atomicAdd(&g_cursor[dst[e]], 1);
        g_csr[p] = src[e];
    }
}

// ---------------- propagation: 16-lane edge groups, float4 lanes ----------
// z_r = norm^2 * sum_j z_{r-1}[j]; FIRST multiplies norm[j] (raw feat input).
template <int FIRST>
__global__ __launch_bounds__(256) void k_gather(const float* __restrict__ zin,
                                                float* __restrict__ zout) {
    int warp = (blockIdx.x * blockDim.x + threadIdx.x) >> 5;
    int lane = threadIdx.x & 31;
    if (warp >= NN) return;
    int beg = g_off[warp], end = g_off[warp + 1];
    int grp = lane >> 4, sub = lane & 15;
    const float4* z4 = (const float4*)zin;        // node row = 16 float4
    float4 a = make_float4(0.f, 0.f, 0.f, 0.f);
    float4 b = make_float4(0.f, 0.f, 0.f, 0.f);
    int e = beg + grp;
    // two edges in flight per group per iteration (4 per warp)
    for (; e + 2 < end; e += 4) {
        int j0 = g_csr[e], j1 = g_csr[e + 2];
        float4 v0 = z4[j0 * 16 + sub];
        float4 v1 = z4[j1 * 16 + sub];
        if (FIRST) {
            float n0 = g_norm[j0], n1 = g_norm[j1];
            a.x = fmaf(n0, v0.x, a.x); a.y = fmaf(n0, v0.y, a.y);
            a.z = fmaf(n0, v0.z, a.z); a.w = fmaf(n0, v0.w, a.w);
            b.x = fmaf(n1, v1.x, b.x); b.y = fmaf(n1, v1.y, b.y);
            b.z = fmaf(n1, v1.z, b.z); b.w = fmaf(n1, v1.w, b.w);
        } else {
            a.x += v0.x; a.y += v0.y; a.z += v0.z; a.w += v0.w;
            b.x += v1.x; b.y += v1.y; b.z += v1.z; b.w += v1.w;
        }
    }
    if (e < end) {
        int j = g_csr[e];
        float4 v = z4[j * 16 + sub];
        if (FIRST) {
            float nj = g_norm[j];
            a.x = fmaf(nj, v.x, a.x); a.y = fmaf(nj, v.y, a.y);
            a.z = fmaf(nj, v.z, a.z); a.w = fmaf(nj, v.w, a.w);
        } else {
            a.x += v.x; a.y += v.y; a.z += v.z; a.w += v.w;
        }
    }
    a.x += b.x; a.y += b.y; a.z += b.z; a.w += b.w;
    // merge the two 16-lane groups
    a.x += __shfl_xor_sync(0xffffffffu, a.x, 16);
    a.y += __shfl_xor_sync(0xffffffffu, a.y, 16);
    a.z += __shfl_xor_sync(0xffffffffu, a.z, 16);
    a.w += __shfl_xor_sync(0xffffffffu, a.w, 16);
    if (grp == 0) {
        float ni = g_norm[warp];
        float n2 = ni * ni;
        ((float4*)zout)[warp * 16 + sub] =
            make_float4(n2 * a.x, n2 * a.y, n2 * a.z, n2 * a.w);
    }
}

// ---------------- GEMM1: 128x256, K=64 ----------------
__global__ __launch_bounds__(512, 1) void k_mma1(
    const float* __restrict__ Z1, const float* __restrict__ Z2,
    const float* __restrict__ Z3, const float* __restrict__ Z4,
    const float* __restrict__ feat,
    const __nv_bfloat16* __restrict__ Bhi, const __nv_bfloat16* __restrict__ Blo,
    float* __restrict__ out, float* __restrict__ stats)
{
    constexpr int KDIM = DD, LDS = 40;
    extern __shared__ __align__(16) char smem[];
    __nv_bfloat16* sAhi = (__nv_bfloat16*)(smem);
    __nv_bfloat16* sAlo = (__nv_bfloat16*)(smem + 10240);
    __nv_bfloat16* sBhi = (__nv_bfloat16*)(smem + 20480);
    __nv_bfloat16* sBlo = (__nv_bfloat16*)(smem + 40960);

    int tid = threadIdx.x, lane = tid & 31, wid = tid >> 5;
    int warp_m = wid & 3, warp_n = wid >> 2;
    int row0 = blockIdx.x * 128;

    float c[2][8][4];
#pragma unroll
    for (int mt = 0; mt < 2; mt++)
#pragma unroll
        for (int nt = 0; nt < 8; nt++)
#pragma unroll
            for (int q = 0; q < 4; q++) c[mt][nt][q] = 0.0f;

    uint32_t aAhi = smem_u32(sAhi), aAlo = smem_u32(sAlo);
    uint32_t aBhi = smem_u32(sBhi), aBlo = smem_u32(sBlo);

    int qa = tid & 7, ra0 = tid >> 3;
    int qb = tid & 3, nb0 = tid >> 2;
    bool val0 = (row0 + ra0) < NN;
    bool val1 = (row0 + ra0 + 64) < NN;
    float sd0 = val0 ? (0.2375f * g_sdeg[row0 + ra0]) : 0.f;
    float sd1 = val1 ? (0.2375f * g_sdeg[row0 + ra0 + 64]) : 0.f;

#pragma unroll 1
    for (int ch = 0; ch < KDIM / 32; ch++) {
        int k0 = ch * 32;
#pragma unroll
        for (int it = 0; it < 2; it++) {
            int r = ra0 + it * 64;
            bool valid = it ? val1 : val0;
            float sd = it ? sd1 : sd0;
            float4 v = make_float4(0, 0, 0, 0);
            if (valid) {
                size_t o = (size_t)(row0 + r) * KDIM + k0 + qa * 4;
                float4 z1 = *(const float4*)(Z1 + o);
                float4 z2 = *(const float4*)(Z2 + o);
                float4 z3 = *(const float4*)(Z3 + o);
                float4 z4 = *(const float4*)(Z4 + o);
                float4 f = *(const float4*)(feat + o);
                v.x = sd * (z1.x + z2.x + z3.x + z4.x) + 0.05f * f.x;
                v.y = sd * (z1.y + z2.y + z3.y + z4.y) + 0.05f * f.y;
                v.z = sd * (z1.z + z2.z + z3.z + z4.z) + 0.05f * f.z;
                v.w = sd * (z1.w + z2.w + z3.w + z4.w) + 0.05f * f.w;
            }
            uint32_t h01, l01, h23, l23;
            split_pack(v.x, v.y, h01, l01);
            split_pack(v.z, v.w, h23, l23);
            *(uint2*)&sAhi[r * LDS + qa * 4] = make_uint2(h01, h23);
            *(uint2*)&sAlo[r * LDS + qa * 4] = make_uint2(l01, l23);
        }
#pragma unroll
        for (int it = 0; it < 2; it++) {
            int n = nb0 + it * 128;
            size_t goff = (size_t)n * KDIM + k0 + qb * 8;
            *(uint4*)&sBhi[n * LDS + qb * 8] = *(const uint4*)(Bhi + goff);
            *(uint4*)&sBlo[n * LDS + qb * 8] = *(const uint4*)(Blo + goff);
        }
        __syncthreads();
#pragma unroll
        for (int ks = 0; ks < 2; ks++) {
            int kc = ks * 16;
            uint32_t ah[2][4], al[2][4];
#pragma unroll
            for (int mt = 0; mt < 2; mt++) {
                int r = warp_m * 32 + mt * 16 + (lane & 15);
                uint32_t off = (uint32_t)(r * LDS + kc + ((lane >> 4) << 3)) * 2;
                ldm_x4(ah[mt], aAhi + off);
                ldm_x4(al[mt], aAlo + off);
            }
#pragma unroll
            for (int nt = 0; nt < 8; nt++) {
                int n = warp_n * 64 + nt * 8 + (lane & 7);
                uint32_t off = (uint32_t)(n * LDS + kc + (((lane & 15) >> 3) << 3)) * 2;
                uint32_t bh[2], bl[2];
                ldm_x2(bh, aBhi + off);
                ldm_x2(bl, aBlo + off);
#pragma unroll
                for (int mt = 0; mt < 2; mt++) {
                    mma_bf16(c[mt][nt], ah[mt], bh);
                    mma_bf16(c[mt][nt], al[mt], bh);
                    mma_bf16(c[mt][nt], ah[mt], bl);
                }
            }
        }
        __syncthreads();
    }
    int colb = warp_n * 64 + ((lane & 3) << 1);
    int rb = row0 + warp_m * 32 + (lane >> 2);
#pragma unroll
    for (int mt = 0; mt < 2; mt++) {
        int gr = rb + mt * 16;
#pragma unroll
        for (int nt = 0; nt < 8; nt++) {
            int col = colb + nt * 8;
            if (gr < NN)
                *(float2*)(out + (size_t)gr * HH + col) = make_float2(c[mt][nt][0], c[mt][nt][1]);
            if (gr + 8 < NN)
                *(float2*)(out + (size_t)(gr + 8) * HH + col) = make_float2(c[mt][nt][2], c[mt][nt][3]);
        }
    }
#pragma unroll
    for (int nt = 0; nt < 8; nt++) {
        float s0 = c[0][nt][0] + c[0][nt][2] + c[1][nt][0] + c[1][nt][2];
        float s1 = c[0][nt][1] + c[0][nt][3] + c[1][nt][1] + c[1][nt][3];
        float q0 = c[0][nt][0] * c[0][nt][0] + c[0][nt][2] * c[0][nt][2] +
                   c[1][nt][0] * c[1][nt][0] + c[1][nt][2] * c[1][nt][2];
        float q1 = c[0][nt][1] * c[0][nt][1] + c[0][nt][3] * c[0][nt][3] +
                   c[1][nt][1] * c[1][nt][1] + c[1][nt][3] * c[1][nt][3];
#pragma unroll
        for (int m = 4; m < 32; m <<= 1) {
            s0 += __shfl_xor_sync(0xffffffffu, s0, m);
            s1 += __shfl_xor_sync(0xffffffffu, s1, m);
            q0 += __shfl_xor_sync(0xffffffffu, q0, m);
            q1 += __shfl_xor_sync(0xffffffffu, q1, m);
        }
        if (lane < 4) {
            int col = warp_n * 64 + nt * 8 + lane * 2;
            atomicAdd(&stats[col], s0);
            atomicAdd(&stats[col + 1], s1);
            atomicAdd(&stats[HH + col], q0);
            atomicAdd(&stats[HH + col + 1], q1);
        }
    }
}

// ---------------- GEMM2: 128x256, K=256; A+B reg pipeline ----------------
__global__ __launch_bounds__(512, 1) void k_mma2(
    const float* __restrict__ A,
    const __nv_bfloat16* __restrict__ Bhi, const __nv_bfloat16* __restrict__ Blo,
    const float* __restrict__ bnA, const float* __restrict__ bnC,
    float* __restrict__ out, float* __restrict__ stats)
{
    constexpr int KDIM = HH, LDS = 40;
    extern __shared__ __align__(16) char smem[];
    __nv_bfloat16* sAhi = (__nv_bfloat16*)(smem);
    __nv_bfloat16* sAlo = (__nv_bfloat16*)(smem + 10240);
    __nv_bfloat16* sBhi = (__nv_bfloat16*)(smem + 20480);
    __nv_bfloat16* sBlo = (__nv_bfloat16*)(smem + 40960);

    int tid = threadIdx.x, lane = tid & 31, wid = tid >> 5;
    int warp_m = wid & 3, warp_n = wid >> 2;
    int row0 = blockIdx.x * 128;

    float c[2][8][4];
#pragma unroll
    for (int mt = 0; mt < 2; mt++)
#pragma unroll
        for (int nt = 0; nt < 8; nt++)
#pragma unroll
            for (int q = 0; q < 4; q++) c[mt][nt][q] = 0.0f;

    uint32_t aAhi = smem_u32(sAhi), aAlo = smem_u32(sAlo);
    uint32_t aBhi = smem_u32(sBhi), aBlo = smem_u32(sBlo);

    int qa = tid & 7, ra0 = tid >> 3;
    int qb = tid & 3, nb0 = tid >> 2;
    bool val0 = (row0 + ra0) < NN;
    bool val1 = (row0 + ra0 + 64) < NN;
    const float* Arow0 = A + (size_t)(row0 + ra0) * KDIM + qa * 4;
    const float* Arow1 = Arow0 + (size_t)64 * KDIM;
    const __nv_bfloat16* B0h = Bhi + (size_t)nb0 * KDIM + qb * 8;
    const __nv_bfloat16* B1h = B0h + (size_t)128 * KDIM;
    const __nv_bfloat16* B0l = Blo + (size_t)nb0 * KDIM + qb * 8;
    const __nv_bfloat16* B1l = B0l + (size_t)128 * KDIM;

    const int NCH = KDIM / 32;
    float4 ra[2];
    uint4 rbh[2], rbl[2];
    ra[0] = val0 ? *(const float4*)(Arow0) : make_float4(0, 0, 0, 0);
    ra[1] = val1 ? *(const float4*)(Arow1) : make_float4(0, 0, 0, 0);
    rbh[0] = *(const uint4*)(B0h); rbh[1] = *(const uint4*)(B1h);
    rbl[0] = *(const uint4*)(B0l); rbl[1] = *(const uint4*)(B1l);

#pragma unroll 1
    for (int ch = 0; ch < NCH; ch++) {
        int k0 = ch * 32;
        float4 s = *(const float4*)(bnA + k0 + qa * 4);
        float4 h = *(const float4*)(bnC + k0 + qa * 4);
#pragma unroll
        for (int it = 0; it < 2; it++) {
            float4 v;
            v.x = fmaxf(fmaf(ra[it].x, s.x, h.x), 0.f);
            v.y = fmaxf(fmaf(ra[it].y, s.y, h.y), 0.f);
            v.z = fmaxf(fmaf(ra[it].z, s.z, h.z), 0.f);
            v.w = fmaxf(fmaf(ra[it].w, s.w, h.w), 0.f);
            if (!(it ? val1 : val0)) v = make_float4(0, 0, 0, 0);
            uint32_t h01, l01, h23, l23;
            split_pack(v.x, v.y, h01, l01);
            split_pack(v.z, v.w, h23, l23);
            int r = ra0 + it * 64;
            *(uint2*)&sAhi[r * LDS + qa * 4] = make_uint2(h01, h23);
            *(uint2*)&sAlo[r * LDS + qa * 4] = make_uint2(l01, l23);
        }
#pragma unroll
        for (int it = 0; it < 2; it++) {
            int n = nb0 + it * 128;
            *(uint4*)&sBhi[n * LDS + qb * 8] = rbh[it];
            *(uint4*)&sBlo[n * LDS + qb * 8] = rbl[it];
        }
        __syncthreads();
        if (ch + 1 < NCH) {
            int kn = (ch + 1) * 32;
            ra[0] = val0 ? *(const float4*)(Arow0 + kn) : make_float4(0, 0, 0, 0);
            ra[1] = val1 ? *(const float4*)(Arow1 + kn) : make_float4(0, 0, 0, 0);
            rbh[0] = *(const uint4*)(B0h + kn); rbh[1] = *(const uint4*)(B1h + kn);
            rbl[0] = *(const uint4*)(B0l + kn); rbl[1] = *(const uint4*)(B1l + kn);
        }
#pragma unroll
        for (int ks = 0; ks < 2; ks++) {
            int kc = ks * 16;
            uint32_t ah[2][4], al[2][4];
#pragma unroll
            for (int mt = 0; mt < 2; mt++) {
                int r = warp_m * 32 + mt * 16 + (lane & 15);
                uint32_t off = (uint32_t)(r * LDS + kc + ((lane >> 4) << 3)) * 2;
                ldm_x4(ah[mt], aAhi + off);
                ldm_x4(al[mt], aAlo + off);
            }
#pragma unroll
            for (int nt = 0; nt < 8; nt++) {
                int n = warp_n * 64 + nt * 8 + (lane & 7);
                uint32_t off = (uint32_t)(n * LDS + kc + (((lane & 15) >> 3) << 3)) * 2;
                uint32_t bh[2], bl[2];
                ldm_x2(bh, aBhi + off);
                ldm_x2(bl, aBlo + off);
#pragma unroll
                for (int mt = 0; mt < 2; mt++) {
                    mma_bf16(c[mt][nt], ah[mt], bh);
                    mma_bf16(c[mt][nt], al[mt], bh);
                    mma_bf16(c[mt][nt], ah[mt], bl);
                }
            }
        }
        __syncthreads();
    }
    int colb = warp_n * 64 + ((lane & 3) << 1);
    int rb = row0 + warp_m * 32 + (lane >> 2);
#pragma unroll
    for (int mt = 0; mt < 2; mt++) {
        int gr = rb + mt * 16;
#pragma unroll
        for (int nt = 0; nt < 8; nt++) {
            int col = colb + nt * 8;
            if (gr < NN)
                *(float2*)(out + (size_t)gr * HH + col) = make_float2(c[mt][nt][0], c[mt][nt][1]);
            if (gr + 8 < NN)
                *(float2*)(out + (size_t)(gr + 8) * HH + col) = make_float2(c[mt][nt][2], c[mt][nt][3]);
        }
    }
#pragma unroll
    for (int nt = 0; nt < 8; nt++) {
        float s0 = c[0][nt][0] + c[0][nt][2] + c[1][nt][0] + c[1][nt][2];
        float s1 = c[0][nt][1] + c[0][nt][3] + c[1][nt][1] + c[1][nt][3];
        float q0 = c[0][nt][0] * c[0][nt][0] + c[0][nt][2] * c[0][nt][2] +
                   c[1][nt][0] * c[1][nt][0] + c[1][nt][2] * c[1][nt][2];
        float q1 = c[0][nt][1] * c[0][nt][1] + c[0][nt][3] * c[0][nt][3] +
                   c[1][nt][1] * c[1][nt][1] + c[1][nt][3] * c[1][nt][3];
#pragma unroll
        for (int m = 4; m < 32; m <<= 1) {
            s0 += __shfl_xor_sync(0xffffffffu, s0, m);
            s1 += __shfl_xor_sync(0xffffffffu, s1, m);
            q0 += __shfl_xor_sync(0xffffffffu, q0, m);
            q1 += __shfl_xor_sync(0xffffffffu, q1, m);
        }
        if (lane < 4) {
            int col = warp_n * 64 + nt * 8 + lane * 2;
            atomicAdd(&stats[col], s0);
            atomicAdd(&stats[col + 1], s1);
            atomicAdd(&stats[HH + col], q0);
            atomicAdd(&stats[HH + col + 1], q1);
        }
    }
}

// ---------------- GEMM3 (K=256, N=40) ----------------
__global__ __launch_bounds__(256) void k_mma3(
    const float* __restrict__ A,
    const __nv_bfloat16* __restrict__ Bhi, const __nv_bfloat16* __restrict__ Blo,
    const float* __restrict__ bnA, const float* __restrict__ bnC,
    const float* __restrict__ bias, float* __restrict__ out)
{
    constexpr int KDIM = 256, NTILE = 64, LDS = 40;
    constexpr int WN = NTILE / 4, NT8 = WN / 8;

    __shared__ __align__(16) __nv_bfloat16 sAhi[128 * LDS];
    __shared__ __align__(16) __nv_bfloat16 sAlo[128 * LDS];
    __shared__ __align__(16) __nv_bfloat16 sBhi[NTILE * LDS];
    __shared__ __align__(16) __nv_bfloat16 sBlo[NTILE * LDS];

    int tid = threadIdx.x, lane = tid & 31, wid = tid >> 5;
    int warp_m = wid & 1, warp_n = wid >> 1;
    int row0 = blockIdx.x * 128;

    float c[4][NT8][4];
#pragma unroll
    for (int mt = 0; mt < 4; mt++)
#pragma unroll
        for (int nt = 0; nt < NT8; nt++)
#pragma unroll
            for (int q = 0; q < 4; q++) c[mt][nt][q] = 0.0f;

    uint32_t aAhi = smem_u32(sAhi), aAlo = smem_u32(sAlo);
    uint32_t aBhi = smem_u32(sBhi), aBlo = smem_u32(sBlo);

#pragma unroll 1
    for (int ch = 0; ch < KDIM / 32; ch++) {
        int k0 = ch * 32;
#pragma unroll
        for (int it = 0; it < 4; it++) {
            int idx = tid + it * 256;
            int r = idx >> 3, q = idx & 7;
            int gi = row0 + r;
            float4 v = make_float4(0.f, 0.f, 0.f, 0.f);
            if (gi < NN) {
                float4 a = ((const float4*)(A + (size_t)gi * KDIM + k0))[q];
                int kc = k0 + q * 4;
                float4 s = *(const float4*)(bnA + kc);
                float4 h = *(const float4*)(bnC + kc);
                v.x = fmaxf(fmaf(a.x, s.x, h.x), 0.f);
                v.y = fmaxf(fmaf(a.y, s.y, h.y), 0.f);
                v.z = fmaxf(fmaf(a.z, s.z, h.z), 0.f);
                v.w = fmaxf(fmaf(a.w, s.w, h.w), 0.f);
            }
            uint32_t h01, l01, h23, l23;
            split_pack(v.x, v.y, h01, l01);
            split_pack(v.z, v.w, h23, l23);
            *(uint2*)&sAhi[r * LDS + q * 4] = make_uint2(h01, h23);
            *(uint2*)&sAlo[r * LDS + q * 4] = make_uint2(l01, l23);
        }
        {
            int n = tid >> 2, q = tid & 3;
            size_t goff = (size_t)n * KDIM + k0 + q * 8;
            *(uint4*)&sBhi[n * LDS + q * 8] = *(const uint4*)(Bhi + goff);
            *(uint4*)&sBlo[n * LDS + q * 8] = *(const uint4*)(Blo + goff);
        }
        __syncthreads();
#pragma unroll
        for (int ks = 0; ks < 2; ks++) {
            int kc = ks * 16;
            uint32_t bh[NT8][2], bl[NT8][2];
#pragma unroll
            for (int nt = 0; nt < NT8; nt++) {
                int n = warp_n * WN + nt * 8 + (lane & 7);
                uint32_t off = (uint32_t)(n * LDS + kc + (((lane & 15) >> 3) << 3)) * 2;
                ldm_x2(bh[nt], aBhi + off);
                ldm_x2(bl[nt], aBlo + off);
            }
#pragma unroll
            for (int mt = 0; mt < 4; mt++) {
                int r = warp_m * 64 + mt * 16 + (lane & 15);
                uint32_t off = (uint32_t)(r * LDS + kc + ((lane >> 4) << 3)) * 2;
                uint32_t ah[4], al[4];
                ldm_x4(ah, aAhi + off);
                ldm_x4(al, aAlo + off);
#pragma unroll
                for (int nt = 0; nt < NT8; nt++) {
                    mma_bf16(c[mt][nt], ah, bh[nt]);
                    mma_bf16(c[mt][nt], al, bh[nt]);
                    mma_bf16(c[mt][nt], ah, bl[nt]);
                }
            }
        }
        __syncthreads();
    }

    int colbase = warp_n * WN + ((lane & 3) << 1);
    int rbase = row0 + warp_m * 64 + (lane >> 2);
#pragma unroll
    for (int mt = 0; mt < 4; mt++) {
        int r0g = rbase + mt * 16;
#pragma unroll
        for (int nt = 0; nt < NT8; nt++) {
            int col = colbase + nt * 8;
            if (col >= CC) continue;
            float bx = bias[col], by = bias[col + 1];
            if (r0g < NN)
                *(float2*)(out + (size_t)r0g * CC + col) =
                    make_float2(c[mt][nt][0] + bx, c[mt][nt][1] + by);
            if (r0g + 8 < NN)
                *(float2*)(out + (size_t)(r0g + 8) * CC + col) =
                    make_float2(c[mt][nt][2] + bx, c[mt][nt][3] + by);
        }
    }
}

__global__ void k_bnfin(const float* __restrict__ stats, const float* __restrict__ g,
                        const float* __restrict__ be, float* __restrict__ bnA,
                        float* __restrict__ bnC) {
    int col = threadIdx.x;
    if (col < HH) {
        float inv = 1.0f / (float)NN;
        float mean = stats[col] * inv;
        float var = stats[HH + col] * inv - mean * mean;
        float rstd = rsqrtf(var + BNEPS);
        float a = g[col] * rstd;
        bnA[col] = a;
        bnC[col] = be[col] - a * mean;
    }
}

// ---------------- launch ----------------
extern "C" void kernel_launch(void* const* d_in, const int* in_sizes, int n_in,
                              void* d_out, int out_size) {
    const float* feat = (const float*)d_in[0];
    const int*   src  = (const int*)d_in[1];
    const int*   dst  = (const int*)d_in[2];
    const float* W1   = (const float*)d_in[3];
    const float* g1   = (const float*)d_in[5];
    const float* be1  = (const float*)d_in[6];
    const float* W2   = (const float*)d_in[7];
    const float* g2   = (const float*)d_in[9];
    const float* be2  = (const float*)d_in[10];
    const float* W3   = (const float*)d_in[11];
    const float* b3   = (const float*)d_in[12];
    float* out = (float*)d_out;

    float *p_z1, *p_z2, *p_z3, *p_z4, *p_y1, *p_y2, *p_stats;
    float *p_bnA1, *p_bnC1, *p_bnA2, *p_bnC2;
    __nv_bfloat16 *p_w1h, *p_w1l, *p_w2h, *p_w2l, *p_w3h, *p_w3l;
    cudaGetSymbolAddress((void**)&p_z1, g_z1);
    cudaGetSymbolAddress((void**)&p_z2, g_z2);
    cudaGetSymbolAddress((void**)&p_z3, g_z3);
    cudaGetSymbolAddress((void**)&p_z4, g_z4);
    cudaGetSymbolAddress((void**)&p_y1, g_y1);
    cudaGetSymbolAddress((void**)&p_y2, g_y2);
    cudaGetSymbolAddress((void**)&p_stats, g_stats);
    cudaGetSymbolAddress((void**)&p_bnA1, g_bnA1);
    cudaGetSymbolAddress((void**)&p_bnC1, g_bnC1);
    cudaGetSymbolAddress((void**)&p_bnA2, g_bnA2);
    cudaGetSymbolAddress((void**)&p_bnC2, g_bnC2);
    cudaGetSymbolAddress((void**)&p_w1h, g_w1h);
    cudaGetSymbolAddress((void**)&p_w1l, g_w1l);
    cudaGetSymbolAddress((void**)&p_w2h, g_w2h);
    cudaGetSymbolAddress((void**)&p_w2l, g_w2l);
    cudaGetSymbolAddress((void**)&p_w3h, g_w3h);
    cudaGetSymbolAddress((void**)&p_w3l, g_w3l);

    const int SMBIG = 61440;
    cudaFuncSetAttribute((const void*)k_mma1,
                         cudaFuncAttributeMaxDynamicSharedMemorySize, SMBIG);
    cudaFuncSetAttribute((const void*)k_mma2,
                         cudaFuncAttributeMaxDynamicSharedMemorySize, SMBIG);

    // prep + CSR
    k_prep<<<(NN + 255) / 256, 256>>>(W1, W2, W3);
    k_count<<<(EE + 255) / 256, 256>>>(dst);
    k_scan1<<<NB_SCAN, 1024>>>();
    k_scan3<<<NB_SCAN, 1024>>>();
    k_fill<<<(EE + 255) / 256, 256>>>(src, dst);

    // propagation
    int gblocks = (NN * 32 + 255) / 256;
    k_gather<1><<<gblocks, 256>>>(feat, p_z1);
    k_gather<0><<<gblocks, 256>>>(p_z1, p_z2);
    k_gather<0><<<gblocks, 256>>>(p_z2, p_z3);
    k_gather<0><<<gblocks, 256>>>(p_z3, p_z4);

    int mgrid = (NN + 127) / 128;
    k_mma1<<<mgrid, 512, SMBIG>>>(p_z1, p_z2, p_z3, p_z4, feat,
                                  p_w1h, p_w1l, p_y1, p_stats);
    k_bnfin<<<1, 256>>>(p_stats, g1, be1, p_bnA1, p_bnC1);
    k_mma2<<<mgrid, 512, SMBIG>>>(p_y1, p_w2h, p_w2l, p_bnA1, p_bnC1,
                                  p_y2, p_stats + 2 * HH);
    k_bnfin<<<1, 256>>>(p_stats + 2 * HH, g2, be2, p_bnA2, p_bnC2);
    k_mma3<<<mgrid, 256>>>(p_y2, p_w3h, p_w3l, p_bnA2, p_bnC2, b3, out);
}

// round 7
// speedup vs baseline: 1.8765x; 1.1154x over previous
#include <cuda_runtime.h>
#include <cuda_bf16.h>
#include <math.h>
#include <stdint.h>

#define NN 100000
#define EE 1250000
#define DD 64
#define HH 256
#define CC 40
#define BNEPS 1e-5f
#define NB_SCAN 98

// ---------------- device scratch ----------------
__device__ float g_z1[NN * DD];
__device__ float g_z2[NN * DD];
__device__ float g_z3[NN * DD];
__device__ float g_z4[NN * DD];
__device__ float g_norm[NN];
__device__ float g_sdeg[NN];
__device__ int   g_deg[NN];
__device__ int   g_off[NN + 1];
__device__ int   g_cursor[NN];
__device__ int   g_csr[EE];
__device__ int   g_bsum[NB_SCAN];
__device__ float g_y1[NN * HH];
__device__ float g_y2[NN * HH];
__device__ float g_stats[4 * HH];
__device__ __nv_bfloat16 g_w1h[HH * DD], g_w1l[HH * DD];
__device__ __nv_bfloat16 g_w2h[HH * HH], g_w2l[HH * HH];
__device__ __nv_bfloat16 g_w3h[64 * HH], g_w3l[64 * HH];

// ---------------- helpers ----------------
__device__ __forceinline__ uint32_t smem_u32(const void* p) {
    uint32_t a;
    asm("{ .reg .u64 t; cvta.to.shared.u64 t, %1; cvt.u32.u64 %0, t; }" : "=r"(a) : "l"(p));
    return a;
}
__device__ __forceinline__ void ldm_x4(uint32_t* r, uint32_t addr) {
    asm volatile("ldmatrix.sync.aligned.m8n8.x4.shared.b16 {%0,%1,%2,%3}, [%4];"
                 : "=r"(r[0]), "=r"(r[1]), "=r"(r[2]), "=r"(r[3]) : "r"(addr));
}
__device__ __forceinline__ void ldm_x2(uint32_t* r, uint32_t addr) {
    asm volatile("ldmatrix.sync.aligned.m8n8.x2.shared.b16 {%0,%1}, [%2];"
                 : "=r"(r[0]), "=r"(r[1]) : "r"(addr));
}
__device__ __forceinline__ void mma_bf16(float* c, const uint32_t* a, const uint32_t* b) {
    asm volatile(
        "mma.sync.aligned.m16n8k16.row.col.f32.bf16.bf16.f32 "
        "{%0,%1,%2,%3}, {%4,%5,%6,%7}, {%8,%9}, {%0,%1,%2,%3};"
        : "+f"(c[0]), "+f"(c[1]), "+f"(c[2]), "+f"(c[3])
        : "r"(a[0]), "r"(a[1]), "r"(a[2]), "r"(a[3]), "r"(b[0]), "r"(b[1]));
}
__device__ __forceinline__ void split_pack(float x, float y, uint32_t& hi, uint32_t& lo) {
    __nv_bfloat16 hx = __float2bfloat16(x), hy = __float2bfloat16(y);
    float rx = x - __bfloat162float(hx), ry = y - __bfloat162float(hy);
    __nv_bfloat16 lx = __float2bfloat16(rx), ly = __float2bfloat16(ry);
    hi = (uint32_t)__bfloat16_as_ushort(hx) | ((uint32_t)__bfloat16_as_ushort(hy) << 16);
    lo = (uint32_t)__bfloat16_as_ushort(lx) | ((uint32_t)__bfloat16_as_ushort(ly) << 16);
}
__device__ __forceinline__ void wsplit(const float* W, __nv_bfloat16* hi, __nv_bfloat16* lo,
                                       int idx, int K, int Nsrc) {
    int n = idx / K, k = idx - n * K;
    float v = (n < Nsrc) ? W[(size_t)k * Nsrc + n] : 0.0f;
    __nv_bfloat16 h = __float2bfloat16(v);
    hi[idx] = h;
    lo[idx] = __float2bfloat16(v - __bfloat162float(h));
}

// ---------------- prep ----------------
__global__ void k_prep(const float* __restrict__ W1, const float* __restrict__ W2,
                       const float* __restrict__ W3) {
    int i = blockIdx.x * blockDim.x + threadIdx.x;
    if (i < NN) g_deg[i] = 0;
    if (i < 4 * HH) g_stats[i] = 0.0f;
    if (i < HH * DD) wsplit(W1, g_w1h, g_w1l, i, DD, HH);
    else if (i < HH * DD + HH * HH) wsplit(W2, g_w2h, g_w2l, i - HH * DD, HH, HH);
    else if (i < HH * DD + HH * HH + 64 * HH) wsplit(W3, g_w3h, g_w3l, i - HH * DD - HH * HH, HH, CC);
}
__global__ void k_count(const int* __restrict__ dst) {
    int e = blockIdx.x * blockDim.x + threadIdx.x;
    if (e < EE) atomicAdd(&g_deg[dst[e]], 1);
}
__global__ void k_scan1() {
    __shared__ int s[1024];
    int t = threadIdx.x;
    int i = blockIdx.x * 1024 + t;
    int v = (i < NN) ? g_deg[i] : 0;
    s[t] = v;
    __syncthreads();
    for (int off = 1; off < 1024; off <<= 1) {
        int x = (t >= off) ? s[t - off] : 0;
        __syncthreads();
        s[t] += x;
        __syncthreads();
    }
    if (i < NN) g_off[i] = s[t] - v;
    if (t == 1023) g_bsum[blockIdx.x] = s[1023];
}
__global__ void k_scan3() {
    __shared__ int sb[128];
    int t = threadIdx.x;
    if (t < 128) sb[t] = (t < NB_SCAN) ? g_bsum[t] : 0;
    __syncthreads();
    for (int off = 1; off < 128; off <<= 1) {
        int x = 0;
        if (t < 128 && t >= off) x = sb[t - off];
        __syncthreads();
        if (t < 128) sb[t] += x;
        __syncthreads();
    }
    int base = (blockIdx.x > 0) ? sb[blockIdx.x - 1] : 0;
    int i = blockIdx.x * 1024 + t;
    if (i < NN) {
        int off = g_off[i] + base;
        g_off[i] = off;
        g_cursor[i] = off;
        int d = g_deg[i];
        int dc = (d > 0) ? d : 1;
        g_norm[i] = rsqrtf((float)dc);
        g_sdeg[i] = sqrtf((float)dc);
    }
    if (i == NN) g_off[NN] = EE;
}
__global__ void k_fill(const int* __restrict__ src, const int* __restrict__ dst) {
    int e = blockIdx.x * blockDim.x + threadIdx.x;
    if (e < EE) {
        int p = atomicAdd(&g_cursor[dst[e]], 1);
        g_csr[p] = src[e];
    }
}

// ---------------- propagation ----------------
template <int FIRST>
__global__ __launch_bounds__(256) void k_gather(const float* __restrict__ zin,
                                                float* __restrict__ zout) {
    int warp = (blockIdx.x * blockDim.x + threadIdx.x) >> 5;
    int lane = threadIdx.x & 31;
    if (warp >= NN) return;
    int beg = g_off[warp], end = g_off[warp + 1];
    int grp = lane >> 4, sub = lane & 15;
    const float4* z4 = (const float4*)zin;
    float4 a = make_float4(0.f, 0.f, 0.f, 0.f);
    float4 b = make_float4(0.f, 0.f, 0.f, 0.f);
    int e = beg + grp;
    for (; e + 2 < end; e += 4) {
        int j0 = g_csr[e], j1 = g_csr[e + 2];
        float4 v0 = z4[j0 * 16 + sub];
        float4 v1 = z4[j1 * 16 + sub];
        if (FIRST) {
            float n0 = g_norm[j0], n1 = g_norm[j1];
            a.x = fmaf(n0, v0.x, a.x); a.y = fmaf(n0, v0.y, a.y);
            a.z = fmaf(n0, v0.z, a.z); a.w = fmaf(n0, v0.w, a.w);
            b.x = fmaf(n1, v1.x, b.x); b.y = fmaf(n1, v1.y, b.y);
            b.z = fmaf(n1, v1.z, b.z); b.w = fmaf(n1, v1.w, b.w);
        } else {
            a.x += v0.x; a.y += v0.y; a.z += v0.z; a.w += v0.w;
            b.x += v1.x; b.y += v1.y; b.z += v1.z; b.w += v1.w;
        }
    }
    if (e < end) {
        int j = g_csr[e];
        float4 v = z4[j * 16 + sub];
        if (FIRST) {
            float nj = g_norm[j];
            a.x = fmaf(nj, v.x, a.x); a.y = fmaf(nj, v.y, a.y);
            a.z = fmaf(nj, v.z, a.z); a.w = fmaf(nj, v.w, a.w);
        } else {
            a.x += v.x; a.y += v.y; a.z += v.z; a.w += v.w;
        }
    }
    a.x += b.x; a.y += b.y; a.z += b.z; a.w += b.w;
    a.x += __shfl_xor_sync(0xffffffffu, a.x, 16);
    a.y += __shfl_xor_sync(0xffffffffu, a.y, 16);
    a.z += __shfl_xor_sync(0xffffffffu, a.z, 16);
    a.w += __shfl_xor_sync(0xffffffffu, a.w, 16);
    if (grp == 0) {
        float ni = g_norm[warp];
        float n2 = ni * ni;
        ((float4*)zout)[warp * 16 + sub] =
            make_float4(n2 * a.x, n2 * a.y, n2 * a.z, n2 * a.w);
    }
}

// ---------------- GEMM1: 128x256, K=64 (2 chunks; single-stage) -------------
__global__ __launch_bounds__(512, 1) void k_mma1(
    const float* __restrict__ Z1, const float* __restrict__ Z2,
    const float* __restrict__ Z3, const float* __restrict__ Z4,
    const float* __restrict__ feat,
    const __nv_bfloat16* __restrict__ Bhi, const __nv_bfloat16* __restrict__ Blo,
    float* __restrict__ out, float* __restrict__ stats)
{
    constexpr int KDIM = DD, LDS = 40;
    extern __shared__ __align__(16) char smem[];
    __nv_bfloat16* sAhi = (__nv_bfloat16*)(smem);
    __nv_bfloat16* sAlo = (__nv_bfloat16*)(smem + 10240);
    __nv_bfloat16* sBhi = (__nv_bfloat16*)(smem + 20480);
    __nv_bfloat16* sBlo = (__nv_bfloat16*)(smem + 40960);

    int tid = threadIdx.x, lane = tid & 31, wid = tid >> 5;
    int warp_m = wid & 3, warp_n = wid >> 2;
    int row0 = blockIdx.x * 128;

    float c[2][8][4];
#pragma unroll
    for (int mt = 0; mt < 2; mt++)
#pragma unroll
        for (int nt = 0; nt < 8; nt++)
#pragma unroll
            for (int q = 0; q < 4; q++) c[mt][nt][q] = 0.0f;

    uint32_t aAhi = smem_u32(sAhi), aAlo = smem_u32(sAlo);
    uint32_t aBhi = smem_u32(sBhi), aBlo = smem_u32(sBlo);

    int qa = tid & 7, ra0 = tid >> 3;
    int qb = tid & 3, nb0 = tid >> 2;
    bool val0 = (row0 + ra0) < NN;
    bool val1 = (row0 + ra0 + 64) < NN;
    float sd0 = val0 ? (0.2375f * g_sdeg[row0 + ra0]) : 0.f;
    float sd1 = val1 ? (0.2375f * g_sdeg[row0 + ra0 + 64]) : 0.f;

#pragma unroll 1
    for (int ch = 0; ch < KDIM / 32; ch++) {
        int k0 = ch * 32;
#pragma unroll
        for (int it = 0; it < 2; it++) {
            int r = ra0 + it * 64;
            bool valid = it ? val1 : val0;
            float sd = it ? sd1 : sd0;
            float4 v = make_float4(0, 0, 0, 0);
            if (valid) {
                size_t o = (size_t)(row0 + r) * KDIM + k0 + qa * 4;
                float4 z1 = *(const float4*)(Z1 + o);
                float4 z2 = *(const float4*)(Z2 + o);
                float4 z3 = *(const float4*)(Z3 + o);
                float4 z4 = *(const float4*)(Z4 + o);
                float4 f = *(const float4*)(feat + o);
                v.x = sd * (z1.x + z2.x + z3.x + z4.x) + 0.05f * f.x;
                v.y = sd * (z1.y + z2.y + z3.y + z4.y) + 0.05f * f.y;
                v.z = sd * (z1.z + z2.z + z3.z + z4.z) + 0.05f * f.z;
                v.w = sd * (z1.w + z2.w + z3.w + z4.w) + 0.05f * f.w;
            }
            uint32_t h01, l01, h23, l23;
            split_pack(v.x, v.y, h01, l01);
            split_pack(v.z, v.w, h23, l23);
            *(uint2*)&sAhi[r * LDS + qa * 4] = make_uint2(h01, h23);
            *(uint2*)&sAlo[r * LDS + qa * 4] = make_uint2(l01, l23);
        }
#pragma unroll
        for (int it = 0; it < 2; it++) {
            int n = nb0 + it * 128;
            size_t goff = (size_t)n * KDIM + k0 + qb * 8;
            *(uint4*)&sBhi[n * LDS + qb * 8] = *(const uint4*)(Bhi + goff);
            *(uint4*)&sBlo[n * LDS + qb * 8] = *(const uint4*)(Blo + goff);
        }
        __syncthreads();
#pragma unroll
        for (int ks = 0; ks < 2; ks++) {
            int kc = ks * 16;
            uint32_t ah[2][4], al[2][4];
#pragma unroll
            for (int mt = 0; mt < 2; mt++) {
                int r = warp_m * 32 + mt * 16 + (lane & 15);
                uint32_t off = (uint32_t)(r * LDS + kc + ((lane >> 4) << 3)) * 2;
                ldm_x4(ah[mt], aAhi + off);
                ldm_x4(al[mt], aAlo + off);
            }
#pragma unroll
            for (int nt = 0; nt < 8; nt++) {
                int n = warp_n * 64 + nt * 8 + (lane & 7);
                uint32_t off = (uint32_t)(n * LDS + kc + (((lane & 15) >> 3) << 3)) * 2;
                uint32_t bh[2], bl[2];
                ldm_x2(bh, aBhi + off);
                ldm_x2(bl, aBlo + off);
#pragma unroll
                for (int mt = 0; mt < 2; mt++) {
                    mma_bf16(c[mt][nt], ah[mt], bh);
                    mma_bf16(c[mt][nt], al[mt], bh);
                    mma_bf16(c[mt][nt], ah[mt], bl);
                }
            }
        }
        __syncthreads();
    }
    int colb = warp_n * 64 + ((lane & 3) << 1);
    int rb = row0 + warp_m * 32 + (lane >> 2);
#pragma unroll
    for (int mt = 0; mt < 2; mt++) {
        int gr = rb + mt * 16;
#pragma unroll
        for (int nt = 0; nt < 8; nt++) {
            int col = colb + nt * 8;
            if (gr < NN)
                *(float2*)(out + (size_t)gr * HH + col) = make_float2(c[mt][nt][0], c[mt][nt][1]);
            if (gr + 8 < NN)
                *(float2*)(out + (size_t)(gr + 8) * HH + col) = make_float2(c[mt][nt][2], c[mt][nt][3]);
        }
    }
#pragma unroll
    for (int nt = 0; nt < 8; nt++) {
        float s0 = c[0][nt][0] + c[0][nt][2] + c[1][nt][0] + c[1][nt][2];
        float s1 = c[0][nt][1] + c[0][nt][3] + c[1][nt][1] + c[1][nt][3];
        float q0 = c[0][nt][0] * c[0][nt][0] + c[0][nt][2] * c[0][nt][2] +
                   c[1][nt][0] * c[1][nt][0] + c[1][nt][2] * c[1][nt][2];
        float q1 = c[0][nt][1] * c[0][nt][1] + c[0][nt][3] * c[0][nt][3] +
                   c[1][nt][1] * c[1][nt][1] + c[1][nt][3] * c[1][nt][3];
#pragma unroll
        for (int m = 4; m < 32; m <<= 1) {
            s0 += __shfl_xor_sync(0xffffffffu, s0, m);
            s1 += __shfl_xor_sync(0xffffffffu, s1, m);
            q0 += __shfl_xor_sync(0xffffffffu, q0, m);
            q1 += __shfl_xor_sync(0xffffffffu, q1, m);
        }
        if (lane < 4) {
            int col = warp_n * 64 + nt * 8 + lane * 2;
            atomicAdd(&stats[col], s0);
            atomicAdd(&stats[col + 1], s1);
            atomicAdd(&stats[HH + col], q0);
            atomicAdd(&stats[HH + col + 1], q1);
        }
    }
}

// ---------------- GEMM2: 128x256, K=256; double-buffered, fused BN prologue --
// smem layout (bytes): A stage s: hi s*20480, lo s*20480+10240;
// B stage s: hi 40960+s*40960, lo 40960+s*40960+20480; bnA 122880, bnC 123904.
__global__ __launch_bounds__(512, 1) void k_mma2(
    const float* __restrict__ A,
    const __nv_bfloat16* __restrict__ Bhi, const __nv_bfloat16* __restrict__ Blo,
    const float* __restrict__ stats, const float* __restrict__ gamma,
    const float* __restrict__ beta,
    float* __restrict__ out, float* __restrict__ statsOut)
{
    constexpr int KDIM = HH, LDS = 40;
    extern __shared__ __align__(16) char smem[];
    float* sBnA = (float*)(smem + 122880);
    float* sBnC = (float*)(smem + 123904);

    int tid = threadIdx.x, lane = tid & 31, wid = tid >> 5;
    int warp_m = wid & 3, warp_n = wid >> 2;
    int row0 = blockIdx.x * 128;

    // fused BN finalize (redundant per CTA)
    if (tid < HH) {
        float inv = 1.0f / (float)NN;
        float mean = stats[tid] * inv;
        float var = stats[HH + tid] * inv - mean * mean;
        float rstd = rsqrtf(var + BNEPS);
        float a = gamma[tid] * rstd;
        sBnA[tid] = a;
        sBnC[tid] = beta[tid] - a * mean;
    }

    float c[2][8][4];
#pragma unroll
    for (int mt = 0; mt < 2; mt++)
#pragma unroll
        for (int nt = 0; nt < 8; nt++)
#pragma unroll
            for (int q = 0; q < 4; q++) c[mt][nt][q] = 0.0f;

    uint32_t sb = smem_u32(smem);
    int qa = tid & 7, ra0 = tid >> 3;
    int qb = tid & 3, nb0 = tid >> 2;
    bool val0 = (row0 + ra0) < NN;
    bool val1 = (row0 + ra0 + 64) < NN;
    const float* Arow0 = A + (size_t)(row0 + ra0) * KDIM + qa * 4;
    const float* Arow1 = Arow0 + (size_t)64 * KDIM;
    const __nv_bfloat16* B0h = Bhi + (size_t)nb0 * KDIM + qb * 8;
    const __nv_bfloat16* B1h = B0h + (size_t)128 * KDIM;
    const __nv_bfloat16* B0l = Blo + (size_t)nb0 * KDIM + qb * 8;
    const __nv_bfloat16* B1l = B0l + (size_t)128 * KDIM;

    const int NCH = KDIM / 32;
    float4 ra[2];
    uint4 rbh[2], rbl[2];
    ra[0] = val0 ? *(const float4*)(Arow0) : make_float4(0, 0, 0, 0);
    ra[1] = val1 ? *(const float4*)(Arow1) : make_float4(0, 0, 0, 0);
    rbh[0] = *(const uint4*)(B0h); rbh[1] = *(const uint4*)(B1h);
    rbl[0] = *(const uint4*)(B0l); rbl[1] = *(const uint4*)(B1l);

    __syncthreads();   // bn tables ready

    // store chunk 0 into stage 0
    {
        float4 s = *(const float4*)&sBnA[qa * 4];
        float4 h = *(const float4*)&sBnC[qa * 4];
#pragma unroll
        for (int it = 0; it < 2; it++) {
            float4 v;
            v.x = fmaxf(fmaf(ra[it].x, s.x, h.x), 0.f);
            v.y = fmaxf(fmaf(ra[it].y, s.y, h.y), 0.f);
            v.z = fmaxf(fmaf(ra[it].z, s.z, h.z), 0.f);
            v.w = fmaxf(fmaf(ra[it].w, s.w, h.w), 0.f);
            if (!(it ? val1 : val0)) v = make_float4(0, 0, 0, 0);
            uint32_t h01, l01, h23, l23;
            split_pack(v.x, v.y, h01, l01);
            split_pack(v.z, v.w, h23, l23);
            int r = ra0 + it * 64;
            *(uint2*)(smem + (r * LDS + qa * 4) * 2) = make_uint2(h01, h23);
            *(uint2*)(smem + 10240 + (r * LDS + qa * 4) * 2) = make_uint2(l01, l23);
        }
#pragma unroll
        for (int it = 0; it < 2; it++) {
            int n = nb0 + it * 128;
            *(uint4*)(smem + 40960 + (n * LDS + qb * 8) * 2) = rbh[it];
            *(uint4*)(smem + 40960 + 20480 + (n * LDS + qb * 8) * 2) = rbl[it];
        }
    }

#pragma unroll 1
    for (int ch = 0; ch < NCH; ch++) {
        __syncthreads();  // stage ch&1 ready; other stage free
        if (ch + 1 < NCH) {
            int kn = (ch + 1) * 32;
            ra[0] = val0 ? *(const float4*)(Arow0 + kn) : make_float4(0, 0, 0, 0);
            ra[1] = val1 ? *(const float4*)(Arow1 + kn) : make_float4(0, 0, 0, 0);
            rbh[0] = *(const uint4*)(B0h + kn); rbh[1] = *(const uint4*)(B1h + kn);
            rbl[0] = *(const uint4*)(B0l + kn); rbl[1] = *(const uint4*)(B1l + kn);
        }
        uint32_t stA = (uint32_t)(ch & 1) * 20480;
        uint32_t stB = 40960 + (uint32_t)(ch & 1) * 40960;
#pragma unroll
        for (int ks = 0; ks < 2; ks++) {
            int kc = ks * 16;
            uint32_t ah[2][4], al[2][4];
#pragma unroll
            for (int mt = 0; mt < 2; mt++) {
                int r = warp_m * 32 + mt * 16 + (lane & 15);
                uint32_t off = (uint32_t)(r * LDS + kc + ((lane >> 4) << 3)) * 2;
                ldm_x4(ah[mt], sb + stA + off);
                ldm_x4(al[mt], sb + stA + 10240 + off);
            }
#pragma unroll
            for (int nt = 0; nt < 8; nt++) {
                int n = warp_n * 64 + nt * 8 + (lane & 7);
                uint32_t off = (uint32_t)(n * LDS + kc + (((lane & 15) >> 3) << 3)) * 2;
                uint32_t bh[2], bl[2];
                ldm_x2(bh, sb + stB + off);
                ldm_x2(bl, sb + stB + 20480 + off);
#pragma unroll
                for (int mt = 0; mt < 2; mt++) {
                    mma_bf16(c[mt][nt], ah[mt], bh);
                    mma_bf16(c[mt][nt], al[mt], bh);
                    mma_bf16(c[mt][nt], ah[mt], bl);
                }
            }
        }
        if (ch + 1 < NCH) {
            int kn = (ch + 1) * 32;
            uint32_t nsA = (uint32_t)((ch + 1) & 1) * 20480;
            uint32_t nsB = 40960 + (uint32_t)((ch + 1) & 1) * 40960;
            float4 s = *(const float4*)&sBnA[kn + qa * 4];
            float4 h = *(const float4*)&sBnC[kn + qa * 4];
#pragma unroll
            for (int it = 0; it < 2; it++) {
                float4 v;
                v.x = fmaxf(fmaf(ra[it].x, s.x, h.x), 0.f);
                v.y = fmaxf(fmaf(ra[it].y, s.y, h.y), 0.f);
                v.z = fmaxf(fmaf(ra[it].z, s.z, h.z), 0.f);
                v.w = fmaxf(fmaf(ra[it].w, s.w, h.w), 0.f);
                if (!(it ? val1 : val0)) v = make_float4(0, 0, 0, 0);
                uint32_t h01, l01, h23, l23;
                split_pack(v.x, v.y, h01, l01);
                split_pack(v.z, v.w, h23, l23);
                int r = ra0 + it * 64;
                *(uint2*)(smem + nsA + (r * LDS + qa * 4) * 2) = make_uint2(h01, h23);
                *(uint2*)(smem + nsA + 10240 + (r * LDS + qa * 4) * 2) = make_uint2(l01, l23);
            }
#pragma unroll
            for (int it = 0; it < 2; it++) {
                int n = nb0 + it * 128;
                *(uint4*)(smem + nsB + (n * LDS + qb * 8) * 2) = rbh[it];
                *(uint4*)(smem + nsB + 20480 + (n * LDS + qb * 8) * 2) = rbl[it];
            }
        }
    }

    // epilogue
    int colb = warp_n * 64 + ((lane & 3) << 1);
    int rb = row0 + warp_m * 32 + (lane >> 2);
#pragma unroll
    for (int mt = 0; mt < 2; mt++) {
        int gr = rb + mt * 16;
#pragma unroll
        for (int nt = 0; nt < 8; nt++) {
            int col = colb + nt * 8;
            if (gr < NN)
                *(float2*)(out + (size_t)gr * HH + col) = make_float2(c[mt][nt][0], c[mt][nt][1]);
            if (gr + 8 < NN)
                *(float2*)(out + (size_t)(gr + 8) * HH + col) = make_float2(c[mt][nt][2], c[mt][nt][3]);
        }
    }
#pragma unroll
    for (int nt = 0; nt < 8; nt++) {
        float s0 = c[0][nt][0] + c[0][nt][2] + c[1][nt][0] + c[1][nt][2];
        float s1 = c[0][nt][1] + c[0][nt][3] + c[1][nt][1] + c[1][nt][3];
        float q0 = c[0][nt][0] * c[0][nt][0] + c[0][nt][2] * c[0][nt][2] +
                   c[1][nt][0] * c[1][nt][0] + c[1][nt][2] * c[1][nt][2];
        float q1 = c[0][nt][1] * c[0][nt][1] + c[0][nt][3] * c[0][nt][3] +
                   c[1][nt][1] * c[1][nt][1] + c[1][nt][3] * c[1][nt][3];
#pragma unroll
        for (int m = 4; m < 32; m <<= 1) {
            s0 += __shfl_xor_sync(0xffffffffu, s0, m);
            s1 += __shfl_xor_sync(0xffffffffu, s1, m);
            q0 += __shfl_xor_sync(0xffffffffu, q0, m);
            q1 += __shfl_xor_sync(0xffffffffu, q1, m);
        }
        if (lane < 4) {
            int col = warp_n * 64 + nt * 8 + lane * 2;
            atomicAdd(&statsOut[col], s0);
            atomicAdd(&statsOut[col + 1], s1);
            atomicAdd(&statsOut[HH + col], q0);
            atomicAdd(&statsOut[HH + col + 1], q1);
        }
    }
}

// ---------------- GEMM3 (K=256, N=40): double-buffered, fused BN prologue ----
// smem: A stage s: hi s*20480, lo +10240; B stage s: hi 40960+s*10240, lo +5120;
// bnA 61440, bnC 62464. Total 63488.
__global__ __launch_bounds__(256) void k_mma3(
    const float* __restrict__ A,
    const __nv_bfloat16* __restrict__ Bhi, const __nv_bfloat16* __restrict__ Blo,
    const float* __restrict__ stats, const float* __restrict__ gamma,
    const float* __restrict__ beta,
    const float* __restrict__ bias, float* __restrict__ out)
{
    constexpr int KDIM = 256, NTILE = 64, LDS = 40;
    constexpr int WN = NTILE / 4, NT8 = WN / 8;
    extern __shared__ __align__(16) char smem[];
    float* sBnA = (float*)(smem + 61440);
    float* sBnC = (float*)(smem + 62464);

    int tid = threadIdx.x, lane = tid & 31, wid = tid >> 5;
    int warp_m = wid & 1, warp_n = wid >> 1;
    int row0 = blockIdx.x * 128;

    if (tid < HH) {
        float inv = 1.0f / (float)NN;
        float mean = stats[tid] * inv;
        float var = stats[HH + tid] * inv - mean * mean;
        float rstd = rsqrtf(var + BNEPS);
        float a = gamma[tid] * rstd;
        sBnA[tid] = a;
        sBnC[tid] = beta[tid] - a * mean;
    }

    float c[4][NT8][4];
#pragma unroll
    for (int mt = 0; mt < 4; mt++)
#pragma unroll
        for (int nt = 0; nt < NT8; nt++)
#pragma unroll
            for (int q = 0; q < 4; q++) c[mt][nt][q] = 0.0f;

    uint32_t sb = smem_u32(smem);
    const int NCH = KDIM / 32;
    // A: 4 float4 per thread per chunk; r,q fixed
    int qa = tid & 7;
    int rA[4]; bool vA[4];
#pragma unroll
    for (int it = 0; it < 4; it++) {
        rA[it] = (tid + it * 256) >> 3;
        vA[it] = (row0 + rA[it]) < NN;
    }
    int nb = tid >> 2, qb = tid & 3;

    float4 ra[4];
    uint4 rbh, rbl;
#pragma unroll
    for (int it = 0; it < 4; it++)
        ra[it] = vA[it] ? *(const float4*)(A + (size_t)(row0 + rA[it]) * KDIM + qa * 4)
                        : make_float4(0, 0, 0, 0);
    rbh = *(const uint4*)(Bhi + (size_t)nb * KDIM + qb * 8);
    rbl = *(const uint4*)(Blo + (size_t)nb * KDIM + qb * 8);

    __syncthreads();

    // store chunk 0 -> stage 0
    {
        float4 s = *(const float4*)&sBnA[qa * 4];
        float4 h = *(const float4*)&sBnC[qa * 4];
#pragma unroll
        for (int it = 0; it < 4; it++) {
            float4 v;
            v.x = fmaxf(fmaf(ra[it].x, s.x, h.x), 0.f);
            v.y = fmaxf(fmaf(ra[it].y, s.y, h.y), 0.f);
            v.z = fmaxf(fmaf(ra[it].z, s.z, h.z), 0.f);
            v.w = fmaxf(fmaf(ra[it].w, s.w, h.w), 0.f);
            if (!vA[it]) v = make_float4(0, 0, 0, 0);
            uint32_t h01, l01, h23, l23;
            split_pack(v.x, v.y, h01, l01);
            split_pack(v.z, v.w, h23, l23);
            *(uint2*)(smem + (rA[it] * LDS + qa * 4) * 2) = make_uint2(h01, h23);
            *(uint2*)(smem + 10240 + (rA[it] * LDS + qa * 4) * 2) = make_uint2(l01, l23);
        }
        *(uint4*)(smem + 40960 + (nb * LDS + qb * 8) * 2) = rbh;
        *(uint4*)(smem + 40960 + 5120 + (nb * LDS + qb * 8) * 2) = rbl;
    }

#pragma unroll 1
    for (int ch = 0; ch < NCH; ch++) {
        __syncthreads();
        if (ch + 1 < NCH) {
            int kn = (ch + 1) * 32;
#pragma unroll
            for (int it = 0; it < 4; it++)
                ra[it] = vA[it] ? *(const float4*)(A + (size_t)(row0 + rA[it]) * KDIM + kn + qa * 4)
                                : make_float4(0, 0, 0, 0);
            rbh = *(const uint4*)(Bhi + (size_t)nb * KDIM + kn + qb * 8);
            rbl = *(const uint4*)(Blo + (size_t)nb * KDIM + kn + qb * 8);
        }
        uint32_t stA = (uint32_t)(ch & 1) * 20480;
        uint32_t stB = 40960 + (uint32_t)(ch & 1) * 10240;
#pragma unroll
        for (int ks = 0; ks < 2; ks++) {
            int kc = ks * 16;
            uint32_t bh[NT8][2], bl[NT8][2];
#pragma unroll
            for (int nt = 0; nt < NT8; nt++) {
                int n = warp_n * WN + nt * 8 + (lane & 7);
                uint32_t off = (uint32_t)(n * LDS + kc + (((lane & 15) >> 3) << 3)) * 2;
                ldm_x2(bh[nt], sb + stB + off);
                ldm_x2(bl[nt], sb + stB + 5120 + off);
            }
#pragma unroll
            for (int mt = 0; mt < 4; mt++) {
                int r = warp_m * 64 + mt * 16 + (lane & 15);
                uint32_t off = (uint32_t)(r * LDS + kc + ((lane >> 4) << 3)) * 2;
                uint32_t ah[4], al[4];
                ldm_x4(ah, sb + stA + off);
                ldm_x4(al, sb + stA + 10240 + off);
#pragma unroll
                for (int nt = 0; nt < NT8; nt++) {
                    mma_bf16(c[mt][nt], ah, bh[nt]);
                    mma_bf16(c[mt][nt], al, bh[nt]);
                    mma_bf16(c[mt][nt], ah, bl[nt]);
                }
            }
        }
        if (ch + 1 < NCH) {
            int kn = (ch + 1) * 32;
            uint32_t nsA = (uint32_t)((ch + 1) & 1) * 20480;
            uint32_t nsB = 40960 + (uint32_t)((ch + 1) & 1) * 10240;
            float4 s = *(const float4*)&sBnA[kn + qa * 4];
            float4 h = *(const float4*)&sBnC[kn + qa * 4];
#pragma unroll
            for (int it = 0; it < 4; it++) {
                float4 v;
                v.x = fmaxf(fmaf(ra[it].x, s.x, h.x), 0.f);
                v.y = fmaxf(fmaf(ra[it].y, s.y, h.y), 0.f);
                v.z = fmaxf(fmaf(ra[it].z, s.z, h.z), 0.f);
                v.w = fmaxf(fmaf(ra[it].w, s.w, h.w), 0.f);
                if (!vA[it]) v = make_float4(0, 0, 0, 0);
                uint32_t h01, l01, h23, l23;
                split_pack(v.x, v.y, h01, l01);
                split_pack(v.z, v.w, h23, l23);
                *(uint2*)(smem + nsA + (rA[it] * LDS + qa * 4) * 2) = make_uint2(h01, h23);
                *(uint2*)(smem + nsA + 10240 + (rA[it] * LDS + qa * 4) * 2) = make_uint2(l01, l23);
            }
            *(uint4*)(smem + nsB + (nb * LDS + qb * 8) * 2) = rbh;
            *(uint4*)(smem + nsB + 5120 + (nb * LDS + qb * 8) * 2) = rbl;
        }
    }

    int colbase = warp_n * WN + ((lane & 3) << 1);
    int rbase = row0 + warp_m * 64 + (lane >> 2);
#pragma unroll
    for (int mt = 0; mt < 4; mt++) {
        int r0g = rbase + mt * 16;
#pragma unroll
        for (int nt = 0; nt < NT8; nt++) {
            int col = colbase + nt * 8;
            if (col >= CC) continue;
            float bx = bias[col], by = bias[col + 1];
            if (r0g < NN)
                *(float2*)(out + (size_t)r0g * CC + col) =
                    make_float2(c[mt][nt][0] + bx, c[mt][nt][1] + by);
            if (r0g + 8 < NN)
                *(float2*)(out + (size_t)(r0g + 8) * CC + col) =
                    make_float2(c[mt][nt][2] + bx, c[mt][nt][3] + by);
        }
    }
}

// ---------------- launch ----------------
extern "C" void kernel_launch(void* const* d_in, const int* in_sizes, int n_in,
                              void* d_out, int out_size) {
    const float* feat = (const float*)d_in[0];
    const int*   src  = (const int*)d_in[1];
    const int*   dst  = (const int*)d_in[2];
    const float* W1   = (const float*)d_in[3];
    const float* g1   = (const float*)d_in[5];
    const float* be1  = (const float*)d_in[6];
    const float* W2   = (const float*)d_in[7];
    const float* g2   = (const float*)d_in[9];
    const float* be2  = (const float*)d_in[10];
    const float* W3   = (const float*)d_in[11];
    const float* b3   = (const float*)d_in[12];
    float* out = (float*)d_out;

    float *p_z1, *p_z2, *p_z3, *p_z4, *p_y1, *p_y2, *p_stats;
    __nv_bfloat16 *p_w1h, *p_w1l, *p_w2h, *p_w2l, *p_w3h, *p_w3l;
    cudaGetSymbolAddress((void**)&p_z1, g_z1);
    cudaGetSymbolAddress((void**)&p_z2, g_z2);
    cudaGetSymbolAddress((void**)&p_z3, g_z3);
    cudaGetSymbolAddress((void**)&p_z4, g_z4);
    cudaGetSymbolAddress((void**)&p_y1, g_y1);
    cudaGetSymbolAddress((void**)&p_y2, g_y2);
    cudaGetSymbolAddress((void**)&p_stats, g_stats);
    cudaGetSymbolAddress((void**)&p_w1h, g_w1h);
    cudaGetSymbolAddress((void**)&p_w1l, g_w1l);
    cudaGetSymbolAddress((void**)&p_w2h, g_w2h);
    cudaGetSymbolAddress((void**)&p_w2l, g_w2l);
    cudaGetSymbolAddress((void**)&p_w3h, g_w3h);
    cudaGetSymbolAddress((void**)&p_w3l, g_w3l);

    const int SM1 = 61440;
    const int SM2 = 124928;
    const int SM3 = 63488;
    cudaFuncSetAttribute((const void*)k_mma1,
                         cudaFuncAttributeMaxDynamicSharedMemorySize, SM1);
    cudaFuncSetAttribute((const void*)k_mma2,
                         cudaFuncAttributeMaxDynamicSharedMemorySize, SM2);
    cudaFuncSetAttribute((const void*)k_mma3,
                         cudaFuncAttributeMaxDynamicSharedMemorySize, SM3);

    // prep + CSR
    k_prep<<<(NN + 255) / 256, 256>>>(W1, W2, W3);
    k_count<<<(EE + 255) / 256, 256>>>(dst);
    k_scan1<<<NB_SCAN, 1024>>>();
    k_scan3<<<NB_SCAN, 1024>>>();
    k_fill<<<(EE + 255) / 256, 256>>>(src, dst);

    // propagation
    int gblocks = (NN * 32 + 255) / 256;
    k_gather<1><<<gblocks, 256>>>(feat, p_z1);
    k_gather<0><<<gblocks, 256>>>(p_z1, p_z2);
    k_gather<0><<<gblocks, 256>>>(p_z2, p_z3);
    k_gather<0><<<gblocks, 256>>>(p_z3, p_z4);

    int mgrid = (NN + 127) / 128;
    k_mma1<<<mgrid, 512, SM1>>>(p_z1, p_z2, p_z3, p_z4, feat,
                                p_w1h, p_w1l, p_y1, p_stats);
    k_mma2<<<mgrid, 512, SM2>>>(p_y1, p_w2h, p_w2l,
                                p_stats, g1, be1, p_y2, p_stats + 2 * HH);
    k_mma3<<<mgrid, 256, SM3>>>(p_y2, p_w3h, p_w3l,
                                p_stats + 2 * HH, g2, be2, b3, out);
}

// round 8
// speedup vs baseline: 1.8833x; 1.0036x over previous
#include <cuda_runtime.h>
#include <cuda_bf16.h>
#include <math.h>
#include <stdint.h>

#define NN 100000
#define EE 1250000
#define DD 64
#define HH 256
#define CC 40
#define BNEPS 1e-5f
#define NB_SCAN 98

// ---------------- device scratch ----------------
__device__ float g_z1[NN * DD];
__device__ float g_z2[NN * DD];
__device__ float g_z3[NN * DD];
__device__ float g_z4[NN * DD];
__device__ float g_norm[NN];
__device__ float g_sdeg[NN];
__device__ int   g_deg[NN];
__device__ int   g_off[NN + 1];
__device__ int   g_cursor[NN];
__device__ int   g_csr[EE];
__device__ int   g_bsum[NB_SCAN];
__device__ float g_y1[NN * HH];
__device__ float g_y2[NN * HH];
__device__ float g_stats[4 * HH];
__device__ __nv_bfloat16 g_w1h[HH * DD], g_w1l[HH * DD];
__device__ __nv_bfloat16 g_w2h[HH * HH], g_w2l[HH * HH];
__device__ __nv_bfloat16 g_w3h[64 * HH], g_w3l[64 * HH];

// ---------------- helpers ----------------
__device__ __forceinline__ uint32_t smem_u32(const void* p) {
    uint32_t a;
    asm("{ .reg .u64 t; cvta.to.shared.u64 t, %1; cvt.u32.u64 %0, t; }" : "=r"(a) : "l"(p));
    return a;
}
__device__ __forceinline__ void ldm_x4(uint32_t* r, uint32_t addr) {
    asm volatile("ldmatrix.sync.aligned.m8n8.x4.shared.b16 {%0,%1,%2,%3}, [%4];"
                 : "=r"(r[0]), "=r"(r[1]), "=r"(r[2]), "=r"(r[3]) : "r"(addr));
}
__device__ __forceinline__ void mma_bf16(float* c, const uint32_t* a, const uint32_t* b) {
    asm volatile(
        "mma.sync.aligned.m16n8k16.row.col.f32.bf16.bf16.f32 "
        "{%0,%1,%2,%3}, {%4,%5,%6,%7}, {%8,%9}, {%0,%1,%2,%3};"
        : "+f"(c[0]), "+f"(c[1]), "+f"(c[2]), "+f"(c[3])
        : "r"(a[0]), "r"(a[1]), "r"(a[2]), "r"(a[3]), "r"(b[0]), "r"(b[1]));
}
__device__ __forceinline__ void split_pack(float x, float y, uint32_t& hi, uint32_t& lo) {
    __nv_bfloat16 hx = __float2bfloat16(x), hy = __float2bfloat16(y);
    float rx = x - __bfloat162float(hx), ry = y - __bfloat162float(hy);
    __nv_bfloat16 lx = __float2bfloat16(rx), ly = __float2bfloat16(ry);
    hi = (uint32_t)__bfloat16_as_ushort(hx) | ((uint32_t)__bfloat16_as_ushort(hy) << 16);
    lo = (uint32_t)__bfloat16_as_ushort(lx) | ((uint32_t)__bfloat16_as_ushort(ly) << 16);
}
__device__ __forceinline__ void wsplit(const float* W, __nv_bfloat16* hi, __nv_bfloat16* lo,
                                       int idx, int K, int Nsrc) {
    int n = idx / K, k = idx - n * K;
    float v = (n < Nsrc) ? W[(size_t)k * Nsrc + n] : 0.0f;
    __nv_bfloat16 h = __float2bfloat16(v);
    hi[idx] = h;
    lo[idx] = __float2bfloat16(v - __bfloat162float(h));
}

// ---------------- prep ----------------
__global__ void k_prep(const float* __restrict__ W1, const float* __restrict__ W2,
                       const float* __restrict__ W3) {
    int i = blockIdx.x * blockDim.x + threadIdx.x;
    if (i < NN) g_deg[i] = 0;
    if (i < 4 * HH) g_stats[i] = 0.0f;
    if (i < HH * DD) wsplit(W1, g_w1h, g_w1l, i, DD, HH);
    else if (i < HH * DD + HH * HH) wsplit(W2, g_w2h, g_w2l, i - HH * DD, HH, HH);
    else if (i < HH * DD + HH * HH + 64 * HH) wsplit(W3, g_w3h, g_w3l, i - HH * DD - HH * HH, HH, CC);
}
__global__ void k_count(const int* __restrict__ dst) {
    int e = blockIdx.x * blockDim.x + threadIdx.x;
    if (e < EE) atomicAdd(&g_deg[dst[e]], 1);
}
__global__ void k_scan1() {
    __shared__ int s[1024];
    int t = threadIdx.x;
    int i = blockIdx.x * 1024 + t;
    int v = (i < NN) ? g_deg[i] : 0;
    s[t] = v;
    __syncthreads();
    for (int off = 1; off < 1024; off <<= 1) {
        int x = (t >= off) ? s[t - off] : 0;
        __syncthreads();
        s[t] += x;
        __syncthreads();
    }
    if (i < NN) g_off[i] = s[t] - v;
    if (t == 1023) g_bsum[blockIdx.x] = s[1023];
}
__global__ void k_scan3() {
    __shared__ int sb[128];
    int t = threadIdx.x;
    if (t < 128) sb[t] = (t < NB_SCAN) ? g_bsum[t] : 0;
    __syncthreads();
    for (int off = 1; off < 128; off <<= 1) {
        int x = 0;
        if (t < 128 && t >= off) x = sb[t - off];
        __syncthreads();
        if (t < 128) sb[t] += x;
        __syncthreads();
    }
    int base = (blockIdx.x > 0) ? sb[blockIdx.x - 1] : 0;
    int i = blockIdx.x * 1024 + t;
    if (i < NN) {
        int off = g_off[i] + base;
        g_off[i] = off;
        g_cursor[i] = off;
        int d = g_deg[i];
        int dc = (d > 0) ? d : 1;
        g_norm[i] = rsqrtf((float)dc);
        g_sdeg[i] = sqrtf((float)dc);
    }
    if (i == NN) g_off[NN] = EE;
}
__global__ void k_fill(const int* __restrict__ src, const int* __restrict__ dst) {
    int e = blockIdx.x * blockDim.x + threadIdx.x;
    if (e < EE) {
        int p = atomicAdd(&g_cursor[dst[e]], 1);
        g_csr[p] = src[e];
    }
}

// ---------------- propagation ----------------
template <int FIRST>
__global__ __launch_bounds__(256) void k_gather(const float* __restrict__ zin,
                                                float* __restrict__ zout) {
    int warp = (blockIdx.x * blockDim.x + threadIdx.x) >> 5;
    int lane = threadIdx.x & 31;
    if (warp >= NN) return;
    int beg = g_off[warp], end = g_off[warp + 1];
    int grp = lane >> 4, sub = lane & 15;
    const float4* z4 = (const float4*)zin;
    float4 a = make_float4(0.f, 0.f, 0.f, 0.f);
    float4 b = make_float4(0.f, 0.f, 0.f, 0.f);
    int e = beg + grp;
    for (; e + 2 < end; e += 4) {
        int j0 = g_csr[e], j1 = g_csr[e + 2];
        float4 v0 = z4[j0 * 16 + sub];
        float4 v1 = z4[j1 * 16 + sub];
        if (FIRST) {
            float n0 = g_norm[j0], n1 = g_norm[j1];
            a.x = fmaf(n0, v0.x, a.x); a.y = fmaf(n0, v0.y, a.y);
            a.z = fmaf(n0, v0.z, a.z); a.w = fmaf(n0, v0.w, a.w);
            b.x = fmaf(n1, v1.x, b.x); b.y = fmaf(n1, v1.y, b.y);
            b.z = fmaf(n1, v1.z, b.z); b.w = fmaf(n1, v1.w, b.w);
        } else {
            a.x += v0.x; a.y += v0.y; a.z += v0.z; a.w += v0.w;
            b.x += v1.x; b.y += v1.y; b.z += v1.z; b.w += v1.w;
        }
    }
    if (e < end) {
        int j = g_csr[e];
        float4 v = z4[j * 16 + sub];
        if (FIRST) {
            float nj = g_norm[j];
            a.x = fmaf(nj, v.x, a.x); a.y = fmaf(nj, v.y, a.y);
            a.z = fmaf(nj, v.z, a.z); a.w = fmaf(nj, v.w, a.w);
        } else {
            a.x += v.x; a.y += v.y; a.z += v.z; a.w += v.w;
        }
    }
    a.x += b.x; a.y += b.y; a.z += b.z; a.w += b.w;
    a.x += __shfl_xor_sync(0xffffffffu, a.x, 16);
    a.y += __shfl_xor_sync(0xffffffffu, a.y, 16);
    a.z += __shfl_xor_sync(0xffffffffu, a.z, 16);
    a.w += __shfl_xor_sync(0xffffffffu, a.w, 16);
    if (grp == 0) {
        float ni = g_norm[warp];
        float n2 = ni * ni;
        ((float4*)zout)[warp * 16 + sub] =
            make_float4(n2 * a.x, n2 * a.y, n2 * a.z, n2 * a.w);
    }
}

// B paired-fragment address: pair p covers n8-tiles 2p,2p+1 of this warp.
// lanes 0-7: rows n..n+7 col kc; 8-15: same rows col kc+8;
// 16-23: rows n+8..n+15 col kc; 24-31: col kc+8.
__device__ __forceinline__ uint32_t bpair_off(int warpN64, int p, int kc, int lane, int LDS) {
    int r = warpN64 + p * 16 + (lane & 7) + ((lane & 16) >> 1);
    int col = kc + (((lane & 15) >> 3) << 3);
    return (uint32_t)(r * LDS + col) * 2;
}

// ---------------- GEMM1: 128x256, K=64 (2 chunks; single-stage) -------------
__global__ __launch_bounds__(512, 1) void k_mma1(
    const float* __restrict__ Z1, const float* __restrict__ Z2,
    const float* __restrict__ Z3, const float* __restrict__ Z4,
    const float* __restrict__ feat,
    const __nv_bfloat16* __restrict__ Bhi, const __nv_bfloat16* __restrict__ Blo,
    float* __restrict__ out, float* __restrict__ stats)
{
    constexpr int KDIM = DD, LDS = 40;
    extern __shared__ __align__(16) char smem[];
    __nv_bfloat16* sAhi = (__nv_bfloat16*)(smem);
    __nv_bfloat16* sAlo = (__nv_bfloat16*)(smem + 10240);
    __nv_bfloat16* sBhi = (__nv_bfloat16*)(smem + 20480);
    __nv_bfloat16* sBlo = (__nv_bfloat16*)(smem + 40960);

    int tid = threadIdx.x, lane = tid & 31, wid = tid >> 5;
    int warp_m = wid & 3, warp_n = wid >> 2;
    int row0 = blockIdx.x * 128;

    float c[2][8][4];
#pragma unroll
    for (int mt = 0; mt < 2; mt++)
#pragma unroll
        for (int nt = 0; nt < 8; nt++)
#pragma unroll
            for (int q = 0; q < 4; q++) c[mt][nt][q] = 0.0f;

    uint32_t aAhi = smem_u32(sAhi), aAlo = smem_u32(sAlo);
    uint32_t aBhi = smem_u32(sBhi), aBlo = smem_u32(sBlo);

    int qa = tid & 7, ra0 = tid >> 3;
    int qb = tid & 3, nb0 = tid >> 2;
    bool val0 = (row0 + ra0) < NN;
    bool val1 = (row0 + ra0 + 64) < NN;
    float sd0 = val0 ? (0.2375f * g_sdeg[row0 + ra0]) : 0.f;
    float sd1 = val1 ? (0.2375f * g_sdeg[row0 + ra0 + 64]) : 0.f;

#pragma unroll 1
    for (int ch = 0; ch < KDIM / 32; ch++) {
        int k0 = ch * 32;
#pragma unroll
        for (int it = 0; it < 2; it++) {
            int r = ra0 + it * 64;
            bool valid = it ? val1 : val0;
            float sd = it ? sd1 : sd0;
            float4 v = make_float4(0, 0, 0, 0);
            if (valid) {
                size_t o = (size_t)(row0 + r) * KDIM + k0 + qa * 4;
                float4 z1 = *(const float4*)(Z1 + o);
                float4 z2 = *(const float4*)(Z2 + o);
                float4 z3 = *(const float4*)(Z3 + o);
                float4 z4 = *(const float4*)(Z4 + o);
                float4 f = *(const float4*)(feat + o);
                v.x = sd * (z1.x + z2.x + z3.x + z4.x) + 0.05f * f.x;
                v.y = sd * (z1.y + z2.y + z3.y + z4.y) + 0.05f * f.y;
                v.z = sd * (z1.z + z2.z + z3.z + z4.z) + 0.05f * f.z;
                v.w = sd * (z1.w + z2.w + z3.w + z4.w) + 0.05f * f.w;
            }
            uint32_t h01, l01, h23, l23;
            split_pack(v.x, v.y, h01, l01);
            split_pack(v.z, v.w, h23, l23);
            *(uint2*)&sAhi[r * LDS + qa * 4] = make_uint2(h01, h23);
            *(uint2*)&sAlo[r * LDS + qa * 4] = make_uint2(l01, l23);
        }
#pragma unroll
        for (int it = 0; it < 2; it++) {
            int n = nb0 + it * 128;
            size_t goff = (size_t)n * KDIM + k0 + qb * 8;
            *(uint4*)&sBhi[n * LDS + qb * 8] = *(const uint4*)(Bhi + goff);
            *(uint4*)&sBlo[n * LDS + qb * 8] = *(const uint4*)(Blo + goff);
        }
        __syncthreads();
#pragma unroll
        for (int ks = 0; ks < 2; ks++) {
            int kc = ks * 16;
            uint32_t ah[2][4], al[2][4];
#pragma unroll
            for (int mt = 0; mt < 2; mt++) {
                int r = warp_m * 32 + mt * 16 + (lane & 15);
                uint32_t off = (uint32_t)(r * LDS + kc + ((lane >> 4) << 3)) * 2;
                ldm_x4(ah[mt], aAhi + off);
                ldm_x4(al[mt], aAlo + off);
            }
#pragma unroll
            for (int p = 0; p < 4; p++) {
                uint32_t off = bpair_off(warp_n * 64, p, kc, lane, LDS);
                uint32_t bh[4], bl[4];
                ldm_x4(bh, aBhi + off);
                ldm_x4(bl, aBlo + off);
#pragma unroll
                for (int half = 0; half < 2; half++) {
                    int nt = p * 2 + half;
#pragma unroll
                    for (int mt = 0; mt < 2; mt++) {
                        mma_bf16(c[mt][nt], ah[mt], bh + half * 2);
                        mma_bf16(c[mt][nt], al[mt], bh + half * 2);
                        mma_bf16(c[mt][nt], ah[mt], bl + half * 2);
                    }
                }
            }
        }
        __syncthreads();
    }
    int colb = warp_n * 64 + ((lane & 3) << 1);
    int rb = row0 + warp_m * 32 + (lane >> 2);
#pragma unroll
    for (int mt = 0; mt < 2; mt++) {
        int gr = rb + mt * 16;
#pragma unroll
        for (int nt = 0; nt < 8; nt++) {
            int col = colb + nt * 8;
            if (gr < NN)
                *(float2*)(out + (size_t)gr * HH + col) = make_float2(c[mt][nt][0], c[mt][nt][1]);
            if (gr + 8 < NN)
                *(float2*)(out + (size_t)(gr + 8) * HH + col) = make_float2(c[mt][nt][2], c[mt][nt][3]);
        }
    }
#pragma unroll
    for (int nt = 0; nt < 8; nt++) {
        float s0 = c[0][nt][0] + c[0][nt][2] + c[1][nt][0] + c[1][nt][2];
        float s1 = c[0][nt][1] + c[0][nt][3] + c[1][nt][1] + c[1][nt][3];
        float q0 = c[0][nt][0] * c[0][nt][0] + c[0][nt][2] * c[0][nt][2] +
                   c[1][nt][0] * c[1][nt][0] + c[1][nt][2] * c[1][nt][2];
        float q1 = c[0][nt][1] * c[0][nt][1] + c[0][nt][3] * c[0][nt][3] +
                   c[1][nt][1] * c[1][nt][1] + c[1][nt][3] * c[1][nt][3];
#pragma unroll
        for (int m = 4; m < 32; m <<= 1) {
            s0 += __shfl_xor_sync(0xffffffffu, s0, m);
            s1 += __shfl_xor_sync(0xffffffffu, s1, m);
            q0 += __shfl_xor_sync(0xffffffffu, q0, m);
            q1 += __shfl_xor_sync(0xffffffffu, q1, m);
        }
        if (lane < 4) {
            int col = warp_n * 64 + nt * 8 + lane * 2;
            atomicAdd(&stats[col], s0);
            atomicAdd(&stats[col + 1], s1);
            atomicAdd(&stats[HH + col], q0);
            atomicAdd(&stats[HH + col + 1], q1);
        }
    }
}

// ---------------- GEMM2: 128x256, K=256; double-buffered, fused BN prologue --
__global__ __launch_bounds__(512, 1) void k_mma2(
    const float* __restrict__ A,
    const __nv_bfloat16* __restrict__ Bhi, const __nv_bfloat16* __restrict__ Blo,
    const float* __restrict__ stats, const float* __restrict__ gamma,
    const float* __restrict__ beta,
    float* __restrict__ out, float* __restrict__ statsOut)
{
    constexpr int KDIM = HH, LDS = 40;
    extern __shared__ __align__(16) char smem[];
    float* sBnA = (float*)(smem + 122880);
    float* sBnC = (float*)(smem + 123904);

    int tid = threadIdx.x, lane = tid & 31, wid = tid >> 5;
    int warp_m = wid & 3, warp_n = wid >> 2;
    int row0 = blockIdx.x * 128;

    if (tid < HH) {
        float inv = 1.0f / (float)NN;
        float mean = stats[tid] * inv;
        float var = stats[HH + tid] * inv - mean * mean;
        float rstd = rsqrtf(var + BNEPS);
        float a = gamma[tid] * rstd;
        sBnA[tid] = a;
        sBnC[tid] = beta[tid] - a * mean;
    }

    float c[2][8][4];
#pragma unroll
    for (int mt = 0; mt < 2; mt++)
#pragma unroll
        for (int nt = 0; nt < 8; nt++)
#pragma unroll
            for (int q = 0; q < 4; q++) c[mt][nt][q] = 0.0f;

    uint32_t sb = smem_u32(smem);
    int qa = tid & 7, ra0 = tid >> 3;
    int qb = tid & 3, nb0 = tid >> 2;
    bool val0 = (row0 + ra0) < NN;
    bool val1 = (row0 + ra0 + 64) < NN;
    const float* Arow0 = A + (size_t)(row0 + ra0) * KDIM + qa * 4;
    const float* Arow1 = Arow0 + (size_t)64 * KDIM;
    const __nv_bfloat16* B0h = Bhi + (size_t)nb0 * KDIM + qb * 8;
    const __nv_bfloat16* B1h = B0h + (size_t)128 * KDIM;
    const __nv_bfloat16* B0l = Blo + (size_t)nb0 * KDIM + qb * 8;
    const __nv_bfloat16* B1l = B0l + (size_t)128 * KDIM;

    const int NCH = KDIM / 32;
    float4 ra[2];
    uint4 rbh[2], rbl[2];
    ra[0] = val0 ? *(const float4*)(Arow0) : make_float4(0, 0, 0, 0);
    ra[1] = val1 ? *(const float4*)(Arow1) : make_float4(0, 0, 0, 0);
    rbh[0] = *(const uint4*)(B0h); rbh[1] = *(const uint4*)(B1h);
    rbl[0] = *(const uint4*)(B0l); rbl[1] = *(const uint4*)(B1l);

    __syncthreads();   // bn tables ready

    {
        float4 s = *(const float4*)&sBnA[qa * 4];
        float4 h = *(const float4*)&sBnC[qa * 4];
#pragma unroll
        for (int it = 0; it < 2; it++) {
            float4 v;
            v.x = fmaxf(fmaf(ra[it].x, s.x, h.x), 0.f);
            v.y = fmaxf(fmaf(ra[it].y, s.y, h.y), 0.f);
            v.z = fmaxf(fmaf(ra[it].z, s.z, h.z), 0.f);
            v.w = fmaxf(fmaf(ra[it].w, s.w, h.w), 0.f);
            if (!(it ? val1 : val0)) v = make_float4(0, 0, 0, 0);
            uint32_t h01, l01, h23, l23;
            split_pack(v.x, v.y, h01, l01);
            split_pack(v.z, v.w, h23, l23);
            int r = ra0 + it * 64;
            *(uint2*)(smem + (r * LDS + qa * 4) * 2) = make_uint2(h01, h23);
            *(uint2*)(smem + 10240 + (r * LDS + qa * 4) * 2) = make_uint2(l01, l23);
        }
#pragma unroll
        for (int it = 0; it < 2; it++) {
            int n = nb0 + it * 128;
            *(uint4*)(smem + 40960 + (n * LDS + qb * 8) * 2) = rbh[it];
            *(uint4*)(smem + 40960 + 20480 + (n * LDS + qb * 8) * 2) = rbl[it];
        }
    }

#pragma unroll 1
    for (int ch = 0; ch < NCH; ch++) {
        __syncthreads();
        if (ch + 1 < NCH) {
            int kn = (ch + 1) * 32;
            ra[0] = val0 ? *(const float4*)(Arow0 + kn) : make_float4(0, 0, 0, 0);
            ra[1] = val1 ? *(const float4*)(Arow1 + kn) : make_float4(0, 0, 0, 0);
            rbh[0] = *(const uint4*)(B0h + kn); rbh[1] = *(const uint4*)(B1h + kn);
            rbl[0] = *(const uint4*)(B0l + kn); rbl[1] = *(const uint4*)(B1l + kn);
        }
        uint32_t stA = (uint32_t)(ch & 1) * 20480;
        uint32_t stB = 40960 + (uint32_t)(ch & 1) * 40960;
#pragma unroll
        for (int ks = 0; ks < 2; ks++) {
            int kc = ks * 16;
            uint32_t ah[2][4], al[2][4];
#pragma unroll
            for (int mt = 0; mt < 2; mt++) {
                int r = warp_m * 32 + mt * 16 + (lane & 15);
                uint32_t off = (uint32_t)(r * LDS + kc + ((lane >> 4) << 3)) * 2;
                ldm_x4(ah[mt], sb + stA + off);
                ldm_x4(al[mt], sb + stA + 10240 + off);
            }
#pragma unroll
            for (int p = 0; p < 4; p++) {
                uint32_t off = bpair_off(warp_n * 64, p, kc, lane, LDS);
                uint32_t bh[4], bl[4];
                ldm_x4(bh, sb + stB + off);
                ldm_x4(bl, sb + stB + 20480 + off);
#pragma unroll
                for (int half = 0; half < 2; half++) {
                    int nt = p * 2 + half;
#pragma unroll
                    for (int mt = 0; mt < 2; mt++) {
                        mma_bf16(c[mt][nt], ah[mt], bh + half * 2);
                        mma_bf16(c[mt][nt], al[mt], bh + half * 2);
                        mma_bf16(c[mt][nt], ah[mt], bl + half * 2);
                    }
                }
            }
        }
        if (ch + 1 < NCH) {
            int kn = (ch + 1) * 32;
            uint32_t nsA = (uint32_t)((ch + 1) & 1) * 20480;
            uint32_t nsB = 40960 + (uint32_t)((ch + 1) & 1) * 40960;
            float4 s = *(const float4*)&sBnA[kn + qa * 4];
            float4 h = *(const float4*)&sBnC[kn + qa * 4];
#pragma unroll
            for (int it = 0; it < 2; it++) {
                float4 v;
                v.x = fmaxf(fmaf(ra[it].x, s.x, h.x), 0.f);
                v.y = fmaxf(fmaf(ra[it].y, s.y, h.y), 0.f);
                v.z = fmaxf(fmaf(ra[it].z, s.z, h.z), 0.f);
                v.w = fmaxf(fmaf(ra[it].w, s.w, h.w), 0.f);
                if (!(it ? val1 : val0)) v = make_float4(0, 0, 0, 0);
                uint32_t h01, l01, h23, l23;
                split_pack(v.x, v.y, h01, l01);
                split_pack(v.z, v.w, h23, l23);
                int r = ra0 + it * 64;
                *(uint2*)(smem + nsA + (r * LDS + qa * 4) * 2) = make_uint2(h01, h23);
                *(uint2*)(smem + nsA + 10240 + (r * LDS + qa * 4) * 2) = make_uint2(l01, l23);
            }
#pragma unroll
            for (int it = 0; it < 2; it++) {
                int n = nb0 + it * 128;
                *(uint4*)(smem + nsB + (n * LDS + qb * 8) * 2) = rbh[it];
                *(uint4*)(smem + nsB + 20480 + (n * LDS + qb * 8) * 2) = rbl[it];
            }
        }
    }

    int colb = warp_n * 64 + ((lane & 3) << 1);
    int rb = row0 + warp_m * 32 + (lane >> 2);
#pragma unroll
    for (int mt = 0; mt < 2; mt++) {
        int gr = rb + mt * 16;
#pragma unroll
        for (int nt = 0; nt < 8; nt++) {
            int col = colb + nt * 8;
            if (gr < NN)
                *(float2*)(out + (size_t)gr * HH + col) = make_float2(c[mt][nt][0], c[mt][nt][1]);
            if (gr + 8 < NN)
                *(float2*)(out + (size_t)(gr + 8) * HH + col) = make_float2(c[mt][nt][2], c[mt][nt][3]);
        }
    }
#pragma unroll
    for (int nt = 0; nt < 8; nt++) {
        float s0 = c[0][nt][0] + c[0][nt][2] + c[1][nt][0] + c[1][nt][2];
        float s1 = c[0][nt][1] + c[0][nt][3] + c[1][nt][1] + c[1][nt][3];
        float q0 = c[0][nt][0] * c[0][nt][0] + c[0][nt][2] * c[0][nt][2] +
                   c[1][nt][0] * c[1][nt][0] + c[1][nt][2] * c[1][nt][2];
        float q1 = c[0][nt][1] * c[0][nt][1] + c[0][nt][3] * c[0][nt][3] +
                   c[1][nt][1] * c[1][nt][1] + c[1][nt][3] * c[1][nt][3];
#pragma unroll
        for (int m = 4; m < 32; m <<= 1) {
            s0 += __shfl_xor_sync(0xffffffffu, s0, m);
            s1 += __shfl_xor_sync(0xffffffffu, s1, m);
            q0 += __shfl_xor_sync(0xffffffffu, q0, m);
            q1 += __shfl_xor_sync(0xffffffffu, q1, m);
        }
        if (lane < 4) {
            int col = warp_n * 64 + nt * 8 + lane * 2;
            atomicAdd(&statsOut[col], s0);
            atomicAdd(&statsOut[col + 1], s1);
            atomicAdd(&statsOut[HH + col], q0);
            atomicAdd(&statsOut[HH + col + 1], q1);
        }
    }
}

// ---------------- GEMM3 (K=256, N=40): double-buffered, fused BN prologue ----
__global__ __launch_bounds__(256) void k_mma3(
    const float* __restrict__ A,
    const __nv_bfloat16* __restrict__ Bhi, const __nv_bfloat16* __restrict__ Blo,
    const float* __restrict__ stats, const float* __restrict__ gamma,
    const float* __restrict__ beta,
    const float* __restrict__ bias, float* __restrict__ out)
{
    constexpr int KDIM = 256, NTILE = 64, LDS = 40;
    constexpr int WN = NTILE / 4, NT8 = WN / 8;
    extern __shared__ __align__(16) char smem[];
    float* sBnA = (float*)(smem + 61440);
    float* sBnC = (float*)(smem + 62464);

    int tid = threadIdx.x, lane = tid & 31, wid = tid >> 5;
    int warp_m = wid & 1, warp_n = wid >> 1;
    int row0 = blockIdx.x * 128;

    if (tid < HH) {
        float inv = 1.0f / (float)NN;
        float mean = stats[tid] * inv;
        float var = stats[HH + tid] * inv - mean * mean;
        float rstd = rsqrtf(var + BNEPS);
        float a = gamma[tid] * rstd;
        sBnA[tid] = a;
        sBnC[tid] = beta[tid] - a * mean;
    }

    float c[4][NT8][4];
#pragma unroll
    for (int mt = 0; mt < 4; mt++)
#pragma unroll
        for (int nt = 0; nt < NT8; nt++)
#pragma unroll
            for (int q = 0; q < 4; q++) c[mt][nt][q] = 0.0f;

    uint32_t sb = smem_u32(smem);
    const int NCH = KDIM / 32;
    int qa = tid & 7;
    int rA[4]; bool vA[4];
#pragma unroll
    for (int it = 0; it < 4; it++) {
        rA[it] = (tid + it * 256) >> 3;
        vA[it] = (row0 + rA[it]) < NN;
    }
    int nb = tid >> 2, qb = tid & 3;

    float4 ra[4];
    uint4 rbh, rbl;
#pragma unroll
    for (int it = 0; it < 4; it++)
        ra[it] = vA[it] ? *(const float4*)(A + (size_t)(row0 + rA[it]) * KDIM + qa * 4)
                        : make_float4(0, 0, 0, 0);
    rbh = *(const uint4*)(Bhi + (size_t)nb * KDIM + qb * 8);
    rbl = *(const uint4*)(Blo + (size_t)nb * KDIM + qb * 8);

    __syncthreads();

    {
        float4 s = *(const float4*)&sBnA[qa * 4];
        float4 h = *(const float4*)&sBnC[qa * 4];
#pragma unroll
        for (int it = 0; it < 4; it++) {
            float4 v;
            v.x = fmaxf(fmaf(ra[it].x, s.x, h.x), 0.f);
            v.y = fmaxf(fmaf(ra[it].y, s.y, h.y), 0.f);
            v.z = fmaxf(fmaf(ra[it].z, s.z, h.z), 0.f);
            v.w = fmaxf(fmaf(ra[it].w, s.w, h.w), 0.f);
            if (!vA[it]) v = make_float4(0, 0, 0, 0);
            uint32_t h01, l01, h23, l23;
            split_pack(v.x, v.y, h01, l01);
            split_pack(v.z, v.w, h23, l23);
            *(uint2*)(smem + (rA[it] * LDS + qa * 4) * 2) = make_uint2(h01, h23);
            *(uint2*)(smem + 10240 + (rA[it] * LDS + qa * 4) * 2) = make_uint2(l01, l23);
        }
        *(uint4*)(smem + 40960 + (nb * LDS + qb * 8) * 2) = rbh;
        *(uint4*)(smem + 40960 + 5120 + (nb * LDS + qb * 8) * 2) = rbl;
    }

#pragma unroll 1
    for (int ch = 0; ch < NCH; ch++) {
        __syncthreads();
        if (ch + 1 < NCH) {
            int kn = (ch + 1) * 32;
#pragma unroll
            for (int it = 0; it < 4; it++)
                ra[it] = vA[it] ? *(const float4*)(A + (size_t)(row0 + rA[it]) * KDIM + kn + qa * 4)
                                : make_float4(0, 0, 0, 0);
            rbh = *(const uint4*)(Bhi + (size_t)nb * KDIM + kn + qb * 8);
            rbl = *(const uint4*)(Blo + (size_t)nb * KDIM + kn + qb * 8);
        }
        uint32_t stA = (uint32_t)(ch & 1) * 20480;
        uint32_t stB = 40960 + (uint32_t)(ch & 1) * 10240;
#pragma unroll
        for (int ks = 0; ks < 2; ks++) {
            int kc = ks * 16;
            uint32_t bh[4], bl[4];
            uint32_t off = bpair_off(warp_n * WN, 0, kc, lane, LDS);
            ldm_x4(bh, sb + stB + off);
            ldm_x4(bl, sb + stB + 5120 + off);
#pragma unroll
            for (int mt = 0; mt < 4; mt++) {
                int r = warp_m * 64 + mt * 16 + (lane & 15);
                uint32_t aoff = (uint32_t)(r * LDS + kc + ((lane >> 4) << 3)) * 2;
                uint32_t ah[4], al[4];
                ldm_x4(ah, sb + stA + aoff);
                ldm_x4(al, sb + stA + 10240 + aoff);
#pragma unroll
                for (int half = 0; half < 2; half++) {
                    mma_bf16(c[mt][half], ah, bh + half * 2);
                    mma_bf16(c[mt][half], al, bh + half * 2);
                    mma_bf16(c[mt][half], ah, bl + half * 2);
                }
            }
        }
        if (ch + 1 < NCH) {
            int kn = (ch + 1) * 32;
            uint32_t nsA = (uint32_t)((ch + 1) & 1) * 20480;
            uint32_t nsB = 40960 + (uint32_t)((ch + 1) & 1) * 10240;
            float4 s = *(const float4*)&sBnA[kn + qa * 4];
            float4 h = *(const float4*)&sBnC[kn + qa * 4];
#pragma unroll
            for (int it = 0; it < 4; it++) {
                float4 v;
                v.x = fmaxf(fmaf(ra[it].x, s.x, h.x), 0.f);
                v.y = fmaxf(fmaf(ra[it].y, s.y, h.y), 0.f);
                v.z = fmaxf(fmaf(ra[it].z, s.z, h.z), 0.f);
                v.w = fmaxf(fmaf(ra[it].w, s.w, h.w), 0.f);
                if (!vA[it]) v = make_float4(0, 0, 0, 0);
                uint32_t h01, l01, h23, l23;
                split_pack(v.x, v.y, h01, l01);
                split_pack(v.z, v.w, h23, l23);
                *(uint2*)(smem + nsA + (rA[it] * LDS + qa * 4) * 2) = make_uint2(h01, h23);
                *(uint2*)(smem + nsA + 10240 + (rA[it] * LDS + qa * 4) * 2) = make_uint2(l01, l23);
            }
            *(uint4*)(smem + nsB + (nb * LDS + qb * 8) * 2) = rbh;
            *(uint4*)(smem + nsB + 5120 + (nb * LDS + qb * 8) * 2) = rbl;
        }
    }

    int colbase = warp_n * WN + ((lane & 3) << 1);
    int rbase = row0 + warp_m * 64 + (lane >> 2);
#pragma unroll
    for (int mt = 0; mt < 4; mt++) {
        int r0g = rbase + mt * 16;
#pragma unroll
        for (int nt = 0; nt < NT8; nt++) {
            int col = colbase + nt * 8;
            if (col >= CC) continue;
            float bx = bias[col], by = bias[col + 1];
            if (r0g < NN)
                *(float2*)(out + (size_t)r0g * CC + col) =
                    make_float2(c[mt][nt][0] + bx, c[mt][nt][1] + by);
            if (r0g + 8 < NN)
                *(float2*)(out + (size_t)(r0g + 8) * CC + col) =
                    make_float2(c[mt][nt][2] + bx, c[mt][nt][3] + by);
        }
    }
}

// ---------------- launch ----------------
extern "C" void kernel_launch(void* const* d_in, const int* in_sizes, int n_in,
                              void* d_out, int out_size) {
    const float* feat = (const float*)d_in[0];
    const int*   src  = (const int*)d_in[1];
    const int*   dst  = (const int*)d_in[2];
    const float* W1   = (const float*)d_in[3];
    const float* g1   = (const float*)d_in[5];
    const float* be1  = (const float*)d_in[6];
    const float* W2   = (const float*)d_in[7];
    const float* g2   = (const float*)d_in[9];
    const float* be2  = (const float*)d_in[10];
    const float* W3   = (const float*)d_in[11];
    const float* b3   = (const float*)d_in[12];
    float* out = (float*)d_out;

    float *p_z1, *p_z2, *p_z3, *p_z4, *p_y1, *p_y2, *p_stats;
    __nv_bfloat16 *p_w1h, *p_w1l, *p_w2h, *p_w2l, *p_w3h, *p_w3l;
    cudaGetSymbolAddress((void**)&p_z1, g_z1);
    cudaGetSymbolAddress((void**)&p_z2, g_z2);
    cudaGetSymbolAddress((void**)&p_z3, g_z3);
    cudaGetSymbolAddress((void**)&p_z4, g_z4);
    cudaGetSymbolAddress((void**)&p_y1, g_y1);
    cudaGetSymbolAddress((void**)&p_y2, g_y2);
    cudaGetSymbolAddress((void**)&p_stats, g_stats);
    cudaGetSymbolAddress((void**)&p_w1h, g_w1h);
    cudaGetSymbolAddress((void**)&p_w1l, g_w1l);
    cudaGetSymbolAddress((void**)&p_w2h, g_w2h);
    cudaGetSymbolAddress((void**)&p_w2l, g_w2l);
    cudaGetSymbolAddress((void**)&p_w3h, g_w3h);
    cudaGetSymbolAddress((void**)&p_w3l, g_w3l);

    const int SM1 = 61440;
    const int SM2 = 124928;
    const int SM3 = 63488;
    cudaFuncSetAttribute((const void*)k_mma1,
                         cudaFuncAttributeMaxDynamicSharedMemorySize, SM1);
    cudaFuncSetAttribute((const void*)k_mma2,
                         cudaFuncAttributeMaxDynamicSharedMemorySize, SM2);
    cudaFuncSetAttribute((const void*)k_mma3,
                         cudaFuncAttributeMaxDynamicSharedMemorySize, SM3);

    // prep + CSR
    k_prep<<<(NN + 255) / 256, 256>>>(W1, W2, W3);
    k_count<<<(EE + 255) / 256, 256>>>(dst);
    k_scan1<<<NB_SCAN, 1024>>>();
    k_scan3<<<NB_SCAN, 1024>>>();
    k_fill<<<(EE + 255) / 256, 256>>>(src, dst);

    // propagation
    int gblocks = (NN * 32 + 255) / 256;
    k_gather<1><<<gblocks, 256>>>(feat, p_z1);
    k_gather<0><<<gblocks, 256>>>(p_z1, p_z2);
    k_gather<0><<<gblocks, 256>>>(p_z2, p_z3);
    k_gather<0><<<gblocks, 256>>>(p_z3, p_z4);

    int mgrid = (NN + 127) / 128;
    k_mma1<<<mgrid, 512, SM1>>>(p_z1, p_z2, p_z3, p_z4, feat,
                                p_w1h, p_w1l, p_y1, p_stats);
    k_mma2<<<mgrid, 512, SM2>>>(p_y1, p_w2h, p_w2l,
                                p_stats, g1, be1, p_y2, p_stats + 2 * HH);
    k_mma3<<<mgrid, 256, SM3>>>(p_y2, p_w3h, p_w3l,
                                p_stats + 2 * HH, g2, be2, b3, out);
}